// round 1
// baseline (speedup 1.0000x reference)
#include <cuda_runtime.h>
#include <math.h>

// ---------------------------------------------------------------------------
// DCRNN: 2-layer DCGRU, B=16, N=512, HID=64, K=2, T_in=12, T_out=12
// Internal layout: all per-node tensors stored (N, B, F) row-major,
// i.e. row index m = n*16 + b. Then a diffusion hop is a plain GEMM:
//   Y(512, 16F) = W(512,512) @ X(512, 16F)
// ---------------------------------------------------------------------------

#define NN   512
#define BB   16
#define HID  64
#define NB   (NN*BB)          // 8192
#define F0   65               // layer0 dconv input features (1 + HID)
#define F1   128              // layer1 dconv input features (2*HID)
#define C0   (BB*F0)          // 1040
#define C1   (BB*F1)          // 2048
#define TIN  12
#define TOUT 12

// ---------------- device scratch (no allocations allowed) ------------------
__device__ float g_Wf[NN*NN];
__device__ float g_Wb[NN*NN];
__device__ float g_cs[NN];
__device__ float g_h0[NB*HID];
__device__ float g_h1[NB*HID];
__device__ float g_di[NB];
__device__ float g_X  [NN*C1];
__device__ float g_Xf1[NN*C1];
__device__ float g_Xf2[NN*C1];
__device__ float g_Xb1[NN*C1];
__device__ float g_Xb2[NN*C1];
__device__ float g_r[NB*HID];
__device__ float g_z[NB*HID];
__device__ float g_n[NB*HID];

// ---------------- normalization of A -> Wf, Wb -----------------------------
__global__ void rownorm_k(const float* __restrict__ A, float* __restrict__ Wf) {
    int i = blockIdx.x;
    __shared__ float red[256];
    float s = 0.f;
    for (int j = threadIdx.x; j < NN; j += 256) s += A[i*NN + j];
    red[threadIdx.x] = s; __syncthreads();
    for (int off = 128; off; off >>= 1) {
        if (threadIdx.x < off) red[threadIdx.x] += red[threadIdx.x + off];
        __syncthreads();
    }
    float d = red[0] + 1e-6f;
    for (int j = threadIdx.x; j < NN; j += 256) Wf[i*NN + j] = A[i*NN + j] / d;
}

__global__ void colsum_k(const float* __restrict__ A, float* __restrict__ cs) {
    int c = blockIdx.x * blockDim.x + threadIdx.x;
    if (c < NN) {
        float s = 0.f;
        for (int r = 0; r < NN; r++) s += A[r*NN + c];
        cs[c] = s;
    }
}

__global__ void fill_wb_k(const float* __restrict__ A, const float* __restrict__ cs,
                          float* __restrict__ Wb) {
    int i = blockIdx.x;
    float d = cs[i] + 1e-6f;
    for (int j = threadIdx.x; j < NN; j += 256) Wb[i*NN + j] = A[j*NN + i] / d;
}

__global__ void zero2_k(float* a, float* b, int n) {
    int i = blockIdx.x * blockDim.x + threadIdx.x;
    if (i < n) { a[i] = 0.f; b[i] = 0.f; }
}

// ---------------- hop GEMM: two independent 512x512 @ 512xC ----------------
// z=0: Y0 = W0 @ X0 ; z=1: Y1 = W1 @ X1
__global__ void hop_gemm(const float* __restrict__ W0, const float* __restrict__ X0,
                         float* __restrict__ Y0,
                         const float* __restrict__ W1, const float* __restrict__ X1,
                         float* __restrict__ Y1, int C)
{
    const float* W = blockIdx.z ? W1 : W0;
    const float* X = blockIdx.z ? X1 : X0;
    float*       Y = blockIdx.z ? Y1 : Y0;
    const int m0 = blockIdx.y * 64;
    const int c0 = blockIdx.x * 64;
    const int tid = threadIdx.x;
    const int tx = tid & 15, ty = tid >> 4;

    __shared__ float As[16][64];
    __shared__ float Bs[16][64];

    float acc[4][4];
    #pragma unroll
    for (int i = 0; i < 4; i++)
        #pragma unroll
        for (int j = 0; j < 4; j++) acc[i][j] = 0.f;

    for (int k0 = 0; k0 < NN; k0 += 16) {
        // W tile 64x16 -> As[k][m]
        {
            int m  = tid >> 2;
            int k4 = (tid & 3) * 4;
            const float4 w = *reinterpret_cast<const float4*>(&W[(m0+m)*NN + k0 + k4]);
            As[k4+0][m] = w.x; As[k4+1][m] = w.y; As[k4+2][m] = w.z; As[k4+3][m] = w.w;
        }
        // X tile 16x64 -> Bs[k][c]
        {
            int k  = tid >> 4;
            int c4 = (tid & 15) * 4;
            int c  = c0 + c4;
            float4 v;
            if (c + 3 < C) {
                v = *reinterpret_cast<const float4*>(&X[(k0+k)*C + c]);
            } else {
                v.x = (c+0 < C) ? X[(k0+k)*C + c+0] : 0.f;
                v.y = (c+1 < C) ? X[(k0+k)*C + c+1] : 0.f;
                v.z = (c+2 < C) ? X[(k0+k)*C + c+2] : 0.f;
                v.w = (c+3 < C) ? X[(k0+k)*C + c+3] : 0.f;
            }
            Bs[k][c4+0] = v.x; Bs[k][c4+1] = v.y; Bs[k][c4+2] = v.z; Bs[k][c4+3] = v.w;
        }
        __syncthreads();
        #pragma unroll
        for (int k = 0; k < 16; k++) {
            float a[4], b[4];
            #pragma unroll
            for (int i = 0; i < 4; i++) a[i] = As[k][ty + 16*i];
            #pragma unroll
            for (int j = 0; j < 4; j++) b[j] = Bs[k][tx + 16*j];
            #pragma unroll
            for (int i = 0; i < 4; i++)
                #pragma unroll
                for (int j = 0; j < 4; j++) acc[i][j] += a[i] * b[j];
        }
        __syncthreads();
    }
    #pragma unroll
    for (int i = 0; i < 4; i++) {
        int m = m0 + ty + 16*i;
        #pragma unroll
        for (int j = 0; j < 4; j++) {
            int c = c0 + tx + 16*j;
            if (c < C) Y[m*C + c] = acc[i][j];
        }
    }
}

// ---------------- gate GEMM: (8192,5F)@(5F,64)+b, then activation ----------
// Virtual concat: accumulate 5 slices. z=0 -> (Wa,ba,Ya), z=1 -> (Wb,bb,Yb).
// act: 0 = sigmoid, 1 = tanh
__global__ void gate_gemm(const float* __restrict__ X0, const float* __restrict__ X1,
                          const float* __restrict__ X2, const float* __restrict__ X3,
                          const float* __restrict__ X4, int F,
                          const float* __restrict__ Wa, const float* __restrict__ ba,
                          float* __restrict__ Ya,
                          const float* __restrict__ Wb, const float* __restrict__ bb,
                          float* __restrict__ Yb, int act)
{
    const float* Wl = blockIdx.z ? Wb : Wa;
    const float* bl = blockIdx.z ? bb : ba;
    float*       Y  = blockIdx.z ? Yb : Ya;
    const int m0 = blockIdx.x * 64;
    const int tid = threadIdx.x;
    const int tx = tid & 15, ty = tid >> 4;
    const float* Xs[5] = {X0, X1, X2, X3, X4};

    __shared__ float As[16][64];
    __shared__ float Bs[16][64];

    float acc[4][4];
    #pragma unroll
    for (int i = 0; i < 4; i++)
        #pragma unroll
        for (int j = 0; j < 4; j++) acc[i][j] = 0.f;

    for (int s = 0; s < 5; s++) {
        const float* X = Xs[s];
        for (int k0 = 0; k0 < F; k0 += 16) {
            for (int i = tid; i < 64*16; i += 256) {
                int m = i >> 4, k = i & 15;
                As[k][m] = (k0 + k < F) ? X[(m0+m)*F + k0 + k] : 0.f;
            }
            for (int i = tid; i < 16*64; i += 256) {
                int k = i >> 6, c = i & 63;
                Bs[k][c] = (k0 + k < F) ? Wl[(s*F + k0 + k)*HID + c] : 0.f;
            }
            __syncthreads();
            #pragma unroll
            for (int k = 0; k < 16; k++) {
                float a[4], b[4];
                #pragma unroll
                for (int i = 0; i < 4; i++) a[i] = As[k][ty + 16*i];
                #pragma unroll
                for (int j = 0; j < 4; j++) b[j] = Bs[k][tx + 16*j];
                #pragma unroll
                for (int i = 0; i < 4; i++)
                    #pragma unroll
                    for (int j = 0; j < 4; j++) acc[i][j] += a[i] * b[j];
            }
            __syncthreads();
        }
    }
    #pragma unroll
    for (int i = 0; i < 4; i++) {
        int m = m0 + ty + 16*i;
        #pragma unroll
        for (int j = 0; j < 4; j++) {
            int c = tx + 16*j;
            float v = acc[i][j] + bl[c];
            v = act ? tanhf(v) : 1.f / (1.f + expf(-v));
            Y[m*HID + c] = v;
        }
    }
}

// ---------------- packing / small kernels ----------------------------------
__global__ void pack_l0(const float* __restrict__ di, const float* __restrict__ h,
                        const float* __restrict__ r, float* __restrict__ X)
{
    int idx = blockIdx.x * blockDim.x + threadIdx.x;
    if (idx >= NB * F0) return;
    int m = idx / F0, f = idx - m * F0;
    float v;
    if (f == 0) v = di[m];
    else {
        int g = f - 1;
        v = h[m*HID + g];
        if (r) v *= r[m*HID + g];
    }
    X[idx] = v;
}

__global__ void pack_l1(const float* __restrict__ h0, const float* __restrict__ h1,
                        const float* __restrict__ r, float* __restrict__ X)
{
    int idx = blockIdx.x * blockDim.x + threadIdx.x;
    if (idx >= NB * F1) return;
    int m = idx >> 7, f = idx & 127;
    float v;
    if (f < 64) v = h0[m*HID + f];
    else {
        int g = f - 64;
        v = h1[m*HID + g];
        if (r) v *= r[m*HID + g];
    }
    X[idx] = v;
}

__global__ void copy_xt(const float* __restrict__ x, int t, float* __restrict__ di)
{
    int idx = blockIdx.x * blockDim.x + threadIdx.x;
    if (idx >= NB) return;
    int b = idx >> 9, n = idx & 511;
    di[n*BB + b] = x[b*(TIN*NN) + t*NN + n];
}

__global__ void update_h(float* __restrict__ h, const float* __restrict__ z,
                         const float* __restrict__ nn)
{
    int i = blockIdx.x * blockDim.x + threadIdx.x;
    if (i < NB*HID) {
        float zz = z[i];
        h[i] = (1.f - zz) * h[i] + zz * nn[i];
    }
}

__global__ void proj_k(const float* __restrict__ h1, const float* __restrict__ Wp,
                       const float* __restrict__ bp, float* __restrict__ out,
                       float* __restrict__ di, int t)
{
    int m = blockIdx.x * blockDim.x + threadIdx.x;
    if (m >= NB) return;
    float s = bp[0];
    #pragma unroll
    for (int f = 0; f < HID; f++) s += h1[m*HID + f] * Wp[f];
    int n = m >> 4, b = m & 15;
    out[b*(TOUT*NN) + t*NN + n] = s;
    di[m] = s;
}

// ---------------- host driver ----------------------------------------------
extern "C" void kernel_launch(void* const* d_in, const int* in_sizes, int n_in,
                              void* d_out, int out_size)
{
    const float* x   = (const float*)d_in[0];
    const float* A   = (const float*)d_in[1];
    const float* Wr0 = (const float*)d_in[2];
    const float* br0 = (const float*)d_in[3];
    const float* Wz0 = (const float*)d_in[4];
    const float* bz0 = (const float*)d_in[5];
    const float* Wn0 = (const float*)d_in[6];
    const float* bn0 = (const float*)d_in[7];
    const float* Wr1 = (const float*)d_in[8];
    const float* br1 = (const float*)d_in[9];
    const float* Wz1 = (const float*)d_in[10];
    const float* bz1 = (const float*)d_in[11];
    const float* Wn1 = (const float*)d_in[12];
    const float* bn1 = (const float*)d_in[13];
    const float* Wp  = (const float*)d_in[14];
    const float* bp  = (const float*)d_in[15];
    float* out = (float*)d_out;

    float *Wf, *Wb, *cs, *h0, *h1, *di, *X, *Xf1, *Xf2, *Xb1, *Xb2, *r, *z, *nb;
    cudaGetSymbolAddress((void**)&Wf,  g_Wf);
    cudaGetSymbolAddress((void**)&Wb,  g_Wb);
    cudaGetSymbolAddress((void**)&cs,  g_cs);
    cudaGetSymbolAddress((void**)&h0,  g_h0);
    cudaGetSymbolAddress((void**)&h1,  g_h1);
    cudaGetSymbolAddress((void**)&di,  g_di);
    cudaGetSymbolAddress((void**)&X,   g_X);
    cudaGetSymbolAddress((void**)&Xf1, g_Xf1);
    cudaGetSymbolAddress((void**)&Xf2, g_Xf2);
    cudaGetSymbolAddress((void**)&Xb1, g_Xb1);
    cudaGetSymbolAddress((void**)&Xb2, g_Xb2);
    cudaGetSymbolAddress((void**)&r,   g_r);
    cudaGetSymbolAddress((void**)&z,   g_z);
    cudaGetSymbolAddress((void**)&nb,  g_n);

    rownorm_k<<<NN, 256>>>(A, Wf);
    colsum_k<<<2, 256>>>(A, cs);
    fill_wb_k<<<NN, 256>>>(A, cs, Wb);
    zero2_k<<<(NB*HID + 255)/256, 256>>>(h0, h1, NB*HID);

    auto cell = [&](int layer, const float* Wr, const float* brr, const float* Wz,
                    const float* bzz, const float* Wn, const float* bnn) {
        int F = layer ? F1 : F0;
        int C = BB * F;
        dim3 ghop((C + 63)/64, NN/64, 2);
        int packN = NB * F;
        int packG = (packN + 255)/256;

        // xh = [xl | h]
        if (layer == 0) pack_l0<<<packG, 256>>>(di, h0, nullptr, X);
        else            pack_l1<<<packG, 256>>>(h0, h1, nullptr, X);
        hop_gemm<<<ghop, 256>>>(Wf, X,   Xf1, Wb, X,   Xb1, C);
        hop_gemm<<<ghop, 256>>>(Wf, Xf1, Xf2, Wb, Xb1, Xb2, C);
        gate_gemm<<<dim3(NB/64, 1, 2), 256>>>(X, Xf1, Xf2, Xb1, Xb2, F,
                                              Wr, brr, r, Wz, bzz, z, 0);
        // xn = [xl | r*h]
        if (layer == 0) pack_l0<<<packG, 256>>>(di, h0, r, X);
        else            pack_l1<<<packG, 256>>>(h0, h1, r, X);
        hop_gemm<<<ghop, 256>>>(Wf, X,   Xf1, Wb, X,   Xb1, C);
        hop_gemm<<<ghop, 256>>>(Wf, Xf1, Xf2, Wb, Xb1, Xb2, C);
        gate_gemm<<<dim3(NB/64, 1, 1), 256>>>(X, Xf1, Xf2, Xb1, Xb2, F,
                                              Wn, bnn, nb, nullptr, nullptr, nullptr, 1);
        update_h<<<(NB*HID + 255)/256, 256>>>(layer ? h1 : h0, z, nb);
    };

    // encoder
    for (int t = 0; t < TIN; t++) {
        copy_xt<<<NB/256, 256>>>(x, t, di);
        cell(0, Wr0, br0, Wz0, bz0, Wn0, bn0);
        cell(1, Wr1, br1, Wz1, bz1, Wn1, bn1);
    }
    // decoder (autoregressive: di <- previous y)
    copy_xt<<<NB/256, 256>>>(x, TIN - 1, di);
    for (int t = 0; t < TOUT; t++) {
        cell(0, Wr0, br0, Wz0, bz0, Wn0, bn0);
        cell(1, Wr1, br1, Wz1, bz1, Wn1, bn1);
        proj_k<<<NB/256, 256>>>(h1, Wp, bp, out, di, t);
    }
}

// round 2
// speedup vs baseline: 1.3743x; 1.3743x over previous
#include <cuda_runtime.h>
#include <math.h>

// ---------------------------------------------------------------------------
// DCRNN 2-layer DCGRU. B=16, N=512, HID=64, K=2, T_in=12, T_out=12.
// Layout: per-node matrices (N, B*F) row-major; reshape to (N*B, F) is free.
// Hops are GEMMs Y(.,C) = G(1024,512) @ X(512,C), G = [Wf ; Wb] stacked.
// Inner loops use packed fp32 FMA (fma.rn.f32x2) for 2x fp32 throughput.
// ---------------------------------------------------------------------------

#define NN   512
#define BB   16
#define HID  64
#define NB   (NN*BB)          // 8192
#define F0   65
#define F1   128
#define C0   (BB*F0)          // 1040
#define C1   (BB*F1)          // 2048
#define CH   (BB*HID)         // 1024 (half chain)
#define TIN  12
#define TOUT 12

// ---------------- device scratch -------------------------------------------
__device__ float g_G  [2*NN*NN];      // [Wf ; Wb] stacked (1024 x 512)
__device__ float g_cs [NN];
__device__ float g_h0 [NB*HID];
__device__ float g_h1 [NB*HID];
__device__ float g_di [NB];
__device__ float g_S0 [NN*C1];        // xh / xn input  (512 x C)
__device__ float g_S1 [2*NN*C1];      // hop1 out stacked (1024 x C)
__device__ float g_S2 [2*NN*C1];      // hop2 out stacked
__device__ float g_T0 [NN*CH];        // r*h1 half input (512 x 1024)
__device__ float g_T1 [2*NN*CH];
__device__ float g_T2 [2*NN*CH];
__device__ float g_r  [NB*HID];
__device__ float g_z  [NB*HID];

// ---------------- f32x2 helpers --------------------------------------------
__device__ __forceinline__ unsigned long long pk2(float v) {
    unsigned long long r; unsigned int u = __float_as_uint(v);
    asm("mov.b64 %0, {%1, %1};" : "=l"(r) : "r"(u));
    return r;
}
__device__ __forceinline__ unsigned long long pk(float x, float y) {
    unsigned long long r;
    asm("mov.b64 %0, {%1, %2};" : "=l"(r) : "r"(__float_as_uint(x)), "r"(__float_as_uint(y)));
    return r;
}
#define FFMA2(d, a, b) asm("fma.rn.f32x2 %0, %1, %2, %3;" : "=l"(d) : "l"(a), "l"(b), "l"(d))

union UPair { unsigned long long u; float2 f; };

// ---------------- A -> G normalization -------------------------------------
__global__ void rownorm_k(const float* __restrict__ A, float* __restrict__ G) {
    int i = blockIdx.x;
    __shared__ float red[256];
    float s = 0.f;
    for (int j = threadIdx.x; j < NN; j += 256) s += A[i*NN + j];
    red[threadIdx.x] = s; __syncthreads();
    for (int off = 128; off; off >>= 1) {
        if (threadIdx.x < off) red[threadIdx.x] += red[threadIdx.x + off];
        __syncthreads();
    }
    float d = red[0] + 1e-6f;
    for (int j = threadIdx.x; j < NN; j += 256) G[i*NN + j] = A[i*NN + j] / d;
}
__global__ void colsum_k(const float* __restrict__ A, float* __restrict__ cs) {
    int c = blockIdx.x * blockDim.x + threadIdx.x;
    if (c < NN) {
        float s = 0.f;
        for (int r = 0; r < NN; r++) s += A[r*NN + c];
        cs[c] = s;
    }
}
__global__ void fill_wb_k(const float* __restrict__ A, const float* __restrict__ cs,
                          float* __restrict__ G) {
    int i = blockIdx.x;
    float d = cs[i] + 1e-6f;
    for (int j = threadIdx.x; j < NN; j += 256) G[(NN+i)*NN + j] = A[j*NN + i] / d;
}
__global__ void zero2_k(float* a, float* b, int n) {
    int i = blockIdx.x * blockDim.x + threadIdx.x;
    if (i < n) { a[i] = 0.f; b[i] = 0.f; }
}

// ---------------- hop GEMM: Y(m0..) = G @ X, tile 64x128, FFMA2 ------------
// rows m0 < 512 read Xtop, rows >= 512 read Xbot (block-diagonal second hop)
__global__ __launch_bounds__(128, 4)
void hop_gemm(const float* __restrict__ G, const float* __restrict__ Xtop,
              const float* __restrict__ Xbot, float* __restrict__ Y, int C)
{
    const int c0 = blockIdx.x * 128;
    const int m0 = blockIdx.y * 64;
    const float* __restrict__ X = (m0 < NN) ? Xtop : Xbot;
    const int tid = threadIdx.x;
    const int tx = tid & 15, ty = tid >> 4;

    __shared__ float As[16][64];
    __shared__ float Bs[16][128];

    unsigned long long acc[8][4];
    #pragma unroll
    for (int i = 0; i < 8; i++)
        #pragma unroll
        for (int j = 0; j < 4; j++) acc[i][j] = 0ull;

    const int arow = tid >> 1;
    const int ak   = (tid & 1) * 8;
    const int bk   = tid >> 3;
    const int bc   = (tid & 7) * 16;

    for (int k0 = 0; k0 < NN; k0 += 16) {
        float4 w0 = *reinterpret_cast<const float4*>(&G[(m0+arow)*NN + k0 + ak]);
        float4 w1 = *reinterpret_cast<const float4*>(&G[(m0+arow)*NN + k0 + ak + 4]);
        As[ak+0][arow] = w0.x; As[ak+1][arow] = w0.y;
        As[ak+2][arow] = w0.z; As[ak+3][arow] = w0.w;
        As[ak+4][arow] = w1.x; As[ak+5][arow] = w1.y;
        As[ak+6][arow] = w1.z; As[ak+7][arow] = w1.w;
        #pragma unroll
        for (int u = 0; u < 4; u++) {
            int c = c0 + bc + u*4;
            float4 v = make_float4(0.f, 0.f, 0.f, 0.f);
            if (c < C) v = *reinterpret_cast<const float4*>(&X[(k0+bk)*C + c]);
            *reinterpret_cast<float4*>(&Bs[bk][bc + u*4]) = v;
        }
        __syncthreads();
        #pragma unroll
        for (int kk = 0; kk < 16; kk++) {
            float4 a0 = *reinterpret_cast<const float4*>(&As[kk][ty*8]);
            float4 a1 = *reinterpret_cast<const float4*>(&As[kk][ty*8 + 4]);
            float4 b0 = *reinterpret_cast<const float4*>(&Bs[kk][tx*8]);
            float4 b1 = *reinterpret_cast<const float4*>(&Bs[kk][tx*8 + 4]);
            unsigned long long ap[8] = {pk2(a0.x), pk2(a0.y), pk2(a0.z), pk2(a0.w),
                                        pk2(a1.x), pk2(a1.y), pk2(a1.z), pk2(a1.w)};
            unsigned long long bp[4] = {pk(b0.x,b0.y), pk(b0.z,b0.w),
                                        pk(b1.x,b1.y), pk(b1.z,b1.w)};
            #pragma unroll
            for (int i = 0; i < 8; i++)
                #pragma unroll
                for (int j = 0; j < 4; j++) FFMA2(acc[i][j], ap[i], bp[j]);
        }
        __syncthreads();
    }
    if (c0 + tx*8 < C) {
        #pragma unroll
        for (int i = 0; i < 8; i++) {
            int m = m0 + ty*8 + i;
            UPair p0, p1, p2, p3;
            p0.u = acc[i][0]; p1.u = acc[i][1]; p2.u = acc[i][2]; p3.u = acc[i][3];
            float4 o0 = make_float4(p0.f.x, p0.f.y, p1.f.x, p1.f.y);
            float4 o1 = make_float4(p2.f.x, p2.f.y, p3.f.x, p3.f.y);
            *reinterpret_cast<float4*>(&Y[m*C + c0 + tx*8])     = o0;
            *reinterpret_cast<float4*>(&Y[m*C + c0 + tx*8 + 4]) = o1;
        }
    }
}

// ---------------- gate GEMM: (8192, 5F)@(5F,64)+b with activation ----------
// Virtual concat of 5 slices. Features f < split come from Xf (stride F),
// f >= split come from Xh (stride 64, offset f-64).
// mode 0: blockIdx.z selects (W1,b1,Y1)/(W2,b2,Y2), sigmoid
// mode 1: n-gate, fused h update: h = (1-z)*h + z*tanh(v)
struct GateArgs {
    const float *f0, *f1, *f2, *f3, *f4;
    const float *h0, *h1, *h2, *h3, *h4;
    int F, split;
    const float *W1, *b1; float *Y1;
    const float *W2, *b2; float *Y2;
    const float *zg; float *h;
    int mode;
};

__global__ __launch_bounds__(128, 4)
void gate_gemm(GateArgs a)
{
    const float* Xf[5] = {a.f0, a.f1, a.f2, a.f3, a.f4};
    const float* Xh[5] = {a.h0, a.h1, a.h2, a.h3, a.h4};
    const float* Wl = (a.mode == 0 && blockIdx.z) ? a.W2 : a.W1;
    const float* bl = (a.mode == 0 && blockIdx.z) ? a.b2 : a.b1;
    float*       Yl = (a.mode == 0 && blockIdx.z) ? a.Y2 : a.Y1;
    const int m0 = blockIdx.x * 64;
    const int tid = threadIdx.x;
    const int tx = tid & 15, ty = tid >> 4;
    const int F = a.F, split = a.split;

    __shared__ float As[16][64];
    __shared__ float Bs[16][64];

    unsigned long long acc[8][2];
    #pragma unroll
    for (int i = 0; i < 8; i++) { acc[i][0] = 0ull; acc[i][1] = 0ull; }

    const int arow = tid >> 1;
    const int ak   = (tid & 1) * 8;
    const int bk   = tid >> 3;
    const int bc   = (tid & 7) * 8;

    for (int s = 0; s < 5; s++) {
        const float* __restrict__ Xs = Xf[s];
        const float* __restrict__ Hs = Xh[s];
        for (int k0 = 0; k0 < F; k0 += 16) {
            #pragma unroll
            for (int u = 0; u < 8; u++) {
                int f = k0 + ak + u;
                float v = 0.f;
                if (f < F) {
                    if (f < split) v = Xs[(m0+arow)*F + f];
                    else           v = Hs[(m0+arow)*HID + (f - HID)];
                }
                As[ak+u][arow] = v;
            }
            {
                int f = k0 + bk;
                float4 v0 = make_float4(0.f,0.f,0.f,0.f), v1 = v0;
                if (f < F) {
                    v0 = *reinterpret_cast<const float4*>(&Wl[(s*F+f)*HID + bc]);
                    v1 = *reinterpret_cast<const float4*>(&Wl[(s*F+f)*HID + bc + 4]);
                }
                *reinterpret_cast<float4*>(&Bs[bk][bc])     = v0;
                *reinterpret_cast<float4*>(&Bs[bk][bc + 4]) = v1;
            }
            __syncthreads();
            #pragma unroll
            for (int kk = 0; kk < 16; kk++) {
                float4 a0 = *reinterpret_cast<const float4*>(&As[kk][ty*8]);
                float4 a1 = *reinterpret_cast<const float4*>(&As[kk][ty*8 + 4]);
                float4 b0 = *reinterpret_cast<const float4*>(&Bs[kk][tx*4]);
                unsigned long long ap[8] = {pk2(a0.x), pk2(a0.y), pk2(a0.z), pk2(a0.w),
                                            pk2(a1.x), pk2(a1.y), pk2(a1.z), pk2(a1.w)};
                unsigned long long bp[2] = {pk(b0.x,b0.y), pk(b0.z,b0.w)};
                #pragma unroll
                for (int i = 0; i < 8; i++) {
                    FFMA2(acc[i][0], ap[i], bp[0]);
                    FFMA2(acc[i][1], ap[i], bp[1]);
                }
            }
            __syncthreads();
        }
    }

    const int c = tx * 4;
    float bias[4] = {bl[c], bl[c+1], bl[c+2], bl[c+3]};
    #pragma unroll
    for (int i = 0; i < 8; i++) {
        int m = m0 + ty*8 + i;
        UPair p0, p1; p0.u = acc[i][0]; p1.u = acc[i][1];
        float v[4] = {p0.f.x + bias[0], p0.f.y + bias[1],
                      p1.f.x + bias[2], p1.f.y + bias[3]};
        if (a.mode == 0) {
            float4 o;
            o.x = 1.f / (1.f + expf(-v[0]));
            o.y = 1.f / (1.f + expf(-v[1]));
            o.z = 1.f / (1.f + expf(-v[2]));
            o.w = 1.f / (1.f + expf(-v[3]));
            *reinterpret_cast<float4*>(&Yl[m*HID + c]) = o;
        } else {
            float4 zz = *reinterpret_cast<const float4*>(&a.zg[m*HID + c]);
            float4 hh = *reinterpret_cast<float4*>(&a.h[m*HID + c]);
            float4 o;
            o.x = (1.f - zz.x) * hh.x + zz.x * tanhf(v[0]);
            o.y = (1.f - zz.y) * hh.y + zz.y * tanhf(v[1]);
            o.z = (1.f - zz.z) * hh.z + zz.z * tanhf(v[2]);
            o.w = (1.f - zz.w) * hh.w + zz.w * tanhf(v[3]);
            *reinterpret_cast<float4*>(&a.h[m*HID + c]) = o;
        }
    }
}

// ---------------- packing / small kernels ----------------------------------
__global__ void pack_l0(const float* __restrict__ di, const float* __restrict__ h,
                        const float* __restrict__ r, float* __restrict__ X)
{
    int idx = blockIdx.x * blockDim.x + threadIdx.x;
    if (idx >= NB * F0) return;
    int m = idx / F0, f = idx - m * F0;
    float v;
    if (f == 0) v = di[m];
    else {
        int g = f - 1;
        v = h[m*HID + g];
        if (r) v *= r[m*HID + g];
    }
    X[idx] = v;
}
__global__ void pack_l1(const float* __restrict__ h0, const float* __restrict__ h1,
                        float* __restrict__ X)
{
    int idx = blockIdx.x * blockDim.x + threadIdx.x;
    if (idx >= NB * F1) return;
    int m = idx >> 7, f = idx & 127;
    X[idx] = (f < HID) ? h0[m*HID + f] : h1[m*HID + (f - HID)];
}
__global__ void mul_rh(const float* __restrict__ r, const float* __restrict__ h,
                       float* __restrict__ o)
{
    int i = blockIdx.x * blockDim.x + threadIdx.x;
    if (i < NB*HID) o[i] = r[i] * h[i];
}
__global__ void copy_xt(const float* __restrict__ x, int t, float* __restrict__ di)
{
    int idx = blockIdx.x * blockDim.x + threadIdx.x;
    if (idx >= NB) return;
    int b = idx >> 9, n = idx & 511;
    di[n*BB + b] = x[b*(TIN*NN) + t*NN + n];
}
__global__ void proj_k(const float* __restrict__ h1, const float* __restrict__ Wp,
                       const float* __restrict__ bp, float* __restrict__ out,
                       float* __restrict__ di, int t)
{
    int m = blockIdx.x * blockDim.x + threadIdx.x;
    if (m >= NB) return;
    float s = bp[0];
    #pragma unroll
    for (int f = 0; f < HID; f++) s += h1[m*HID + f] * Wp[f];
    int n = m >> 4, b = m & 15;
    out[b*(TOUT*NN) + t*NN + n] = s;
    di[m] = s;
}

// ---------------- host driver ----------------------------------------------
extern "C" void kernel_launch(void* const* d_in, const int* in_sizes, int n_in,
                              void* d_out, int out_size)
{
    const float* x   = (const float*)d_in[0];
    const float* A   = (const float*)d_in[1];
    const float* Wr0 = (const float*)d_in[2];
    const float* br0 = (const float*)d_in[3];
    const float* Wz0 = (const float*)d_in[4];
    const float* bz0 = (const float*)d_in[5];
    const float* Wn0 = (const float*)d_in[6];
    const float* bn0 = (const float*)d_in[7];
    const float* Wr1 = (const float*)d_in[8];
    const float* br1 = (const float*)d_in[9];
    const float* Wz1 = (const float*)d_in[10];
    const float* bz1 = (const float*)d_in[11];
    const float* Wn1 = (const float*)d_in[12];
    const float* bn1 = (const float*)d_in[13];
    const float* Wp  = (const float*)d_in[14];
    const float* bp  = (const float*)d_in[15];
    float* out = (float*)d_out;

    float *G, *cs, *h0, *h1, *di, *S0, *S1, *S2, *T0, *T1, *T2, *r, *z;
    cudaGetSymbolAddress((void**)&G,  g_G);
    cudaGetSymbolAddress((void**)&cs, g_cs);
    cudaGetSymbolAddress((void**)&h0, g_h0);
    cudaGetSymbolAddress((void**)&h1, g_h1);
    cudaGetSymbolAddress((void**)&di, g_di);
    cudaGetSymbolAddress((void**)&S0, g_S0);
    cudaGetSymbolAddress((void**)&S1, g_S1);
    cudaGetSymbolAddress((void**)&S2, g_S2);
    cudaGetSymbolAddress((void**)&T0, g_T0);
    cudaGetSymbolAddress((void**)&T1, g_T1);
    cudaGetSymbolAddress((void**)&T2, g_T2);
    cudaGetSymbolAddress((void**)&r,  g_r);
    cudaGetSymbolAddress((void**)&z,  g_z);

    rownorm_k<<<NN, 256>>>(A, G);
    colsum_k<<<2, 256>>>(A, cs);
    fill_wb_k<<<NN, 256>>>(A, cs, G);
    zero2_k<<<(NB*HID + 255)/256, 256>>>(h0, h1, NB*HID);

    auto gate_args = [&](const float* s0, const float* s1, const float* s2, int C,
                         const float* t0, const float* t1, const float* t2, int Ch,
                         int F, int split) {
        GateArgs ga;
        ga.f0 = s0; ga.f1 = s1; ga.f2 = s2;
        ga.f3 = s1 ? s1 + (size_t)NN*C : nullptr;
        ga.f4 = s2 ? s2 + (size_t)NN*C : nullptr;
        ga.h0 = t0; ga.h1 = t1; ga.h2 = t2;
        ga.h3 = t1 ? t1 + (size_t)NN*Ch : nullptr;
        ga.h4 = t2 ? t2 + (size_t)NN*Ch : nullptr;
        ga.F = F; ga.split = split;
        ga.W1 = nullptr; ga.b1 = nullptr; ga.Y1 = nullptr;
        ga.W2 = nullptr; ga.b2 = nullptr; ga.Y2 = nullptr;
        ga.zg = nullptr; ga.h = nullptr; ga.mode = 0;
        return ga;
    };

    auto cell0 = [&]() {
        dim3 gh((C0 + 127)/128, 16);
        int packG = (NB*F0 + 255)/256;
        // xh chain
        pack_l0<<<packG, 256>>>(di, h0, nullptr, S0);
        hop_gemm<<<gh, 128>>>(G, S0, S0, S1, C0);
        hop_gemm<<<gh, 128>>>(G, S1, S1 + (size_t)NN*C0, S2, C0);
        // r,z gates
        GateArgs ga = gate_args(S0, S1, S2, C0, nullptr, nullptr, nullptr, 0, F0, F0);
        ga.W1 = Wr0; ga.b1 = br0; ga.Y1 = r;
        ga.W2 = Wz0; ga.b2 = bz0; ga.Y2 = z;
        ga.mode = 0;
        gate_gemm<<<dim3(NB/64, 1, 2), 128>>>(ga);
        // n chain (full recompute, C0 small)
        pack_l0<<<packG, 256>>>(di, h0, r, S0);
        hop_gemm<<<gh, 128>>>(G, S0, S0, S1, C0);
        hop_gemm<<<gh, 128>>>(G, S1, S1 + (size_t)NN*C0, S2, C0);
        GateArgs gn = gate_args(S0, S1, S2, C0, nullptr, nullptr, nullptr, 0, F0, F0);
        gn.W1 = Wn0; gn.b1 = bn0; gn.zg = z; gn.h = h0; gn.mode = 1;
        gate_gemm<<<dim3(NB/64, 1, 1), 128>>>(gn);
    };

    auto cell1 = [&]() {
        dim3 gh(C1/128, 16), ghh(CH/128, 16);
        // xh chain
        pack_l1<<<(NB*F1)/256, 256>>>(h0, h1, S0);
        hop_gemm<<<gh, 128>>>(G, S0, S0, S1, C1);
        hop_gemm<<<gh, 128>>>(G, S1, S1 + (size_t)NN*C1, S2, C1);
        GateArgs ga = gate_args(S0, S1, S2, C1, nullptr, nullptr, nullptr, 0, F1, F1);
        ga.W1 = Wr1; ga.b1 = br1; ga.Y1 = r;
        ga.W2 = Wz1; ga.b2 = bz1; ga.Y2 = z;
        ga.mode = 0;
        gate_gemm<<<dim3(NB/64, 1, 2), 128>>>(ga);
        // n chain: only r*h1 half needs hops; h0 half reused from xh chain
        mul_rh<<<(NB*HID)/256, 256>>>(r, h1, T0);
        hop_gemm<<<ghh, 128>>>(G, T0, T0, T1, CH);
        hop_gemm<<<ghh, 128>>>(G, T1, T1 + (size_t)NN*CH, T2, CH);
        GateArgs gn = gate_args(S0, S1, S2, C1, T0, T1, T2, CH, F1, HID);
        gn.W1 = Wn1; gn.b1 = bn1; gn.zg = z; gn.h = h1; gn.mode = 1;
        gate_gemm<<<dim3(NB/64, 1, 1), 128>>>(gn);
    };

    for (int t = 0; t < TIN; t++) {
        copy_xt<<<NB/256, 256>>>(x, t, di);
        cell0();
        cell1();
    }
    copy_xt<<<NB/256, 256>>>(x, TIN - 1, di);
    for (int t = 0; t < TOUT; t++) {
        cell0();
        cell1();
        proj_k<<<NB/256, 256>>>(h1, Wp, bp, out, di, t);
    }
}

// round 3
// speedup vs baseline: 1.5438x; 1.1233x over previous
#include <cuda_runtime.h>
#include <cuda_bf16.h>
#include <math.h>

// ---------------------------------------------------------------------------
// DCRNN 2-layer DCGRU. B=16, N=512, HID=64, K=2, T_in=12, T_out=12.
// Hop GEMMs Y(1024,C) = G(1024,512)@X run on tensor cores (mma.sync bf16)
// with two-term bf16 splitting (hi/lo) for fp32-grade accuracy:
//   Y ~= Ghi·Xhi + Glo·Xhi + Ghi·Xlo
// Gate GEMMs remain FFMA2 SIMT (tensorize next round).
// ---------------------------------------------------------------------------

#define NN   512
#define BB   16
#define HID  64
#define NB   (NN*BB)          // 8192
#define F0   65
#define F1   128
#define C0   (BB*F0)          // 1040
#define C1   (BB*F1)          // 2048
#define CH   (BB*HID)         // 1024
#define TIN  12
#define TOUT 12
#define KC   32               // k-chunk for hop mma
#define AP   40               // smem row pitch (elements) = KC + 8

typedef __nv_bfloat16 bf16;

// ---------------- device scratch -------------------------------------------
__device__ float g_G [2*NN*NN];
__device__ bf16  g_Gh[2*NN*NN];
__device__ bf16  g_Gl[2*NN*NN];
__device__ float g_cs[NN];
__device__ float g_h0[NB*HID];
__device__ float g_h1[NB*HID];
__device__ float g_di[NB];
__device__ float g_S0 [NN*C1];
__device__ bf16  g_S0h[NN*C1];
__device__ bf16  g_S0l[NN*C1];
__device__ float g_S1 [2*NN*C1];
__device__ bf16  g_S1h[2*NN*C1];
__device__ bf16  g_S1l[2*NN*C1];
__device__ float g_S2 [2*NN*C1];
__device__ float g_T0 [NN*CH];
__device__ bf16  g_T0h[NN*CH];
__device__ bf16  g_T0l[NN*CH];
__device__ float g_T1 [2*NN*CH];
__device__ bf16  g_T1h[2*NN*CH];
__device__ bf16  g_T1l[2*NN*CH];
__device__ float g_T2 [2*NN*CH];
__device__ float g_r [NB*HID];
__device__ float g_z [NB*HID];

// ---------------- f32x2 helpers (gate GEMM) --------------------------------
__device__ __forceinline__ unsigned long long pk2(float v) {
    unsigned long long r; unsigned int u = __float_as_uint(v);
    asm("mov.b64 %0, {%1, %1};" : "=l"(r) : "r"(u));
    return r;
}
__device__ __forceinline__ unsigned long long pk(float x, float y) {
    unsigned long long r;
    asm("mov.b64 %0, {%1, %2};" : "=l"(r) : "r"(__float_as_uint(x)), "r"(__float_as_uint(y)));
    return r;
}
#define FFMA2(d, a, b) asm("fma.rn.f32x2 %0, %1, %2, %3;" : "=l"(d) : "l"(a), "l"(b), "l"(d))
union UPair { unsigned long long u; float2 f; };

// ---------------- A -> G normalization -------------------------------------
__global__ void rownorm_k(const float* __restrict__ A, float* __restrict__ G) {
    int i = blockIdx.x;
    __shared__ float red[256];
    float s = 0.f;
    for (int j = threadIdx.x; j < NN; j += 256) s += A[i*NN + j];
    red[threadIdx.x] = s; __syncthreads();
    for (int off = 128; off; off >>= 1) {
        if (threadIdx.x < off) red[threadIdx.x] += red[threadIdx.x + off];
        __syncthreads();
    }
    float d = red[0] + 1e-6f;
    for (int j = threadIdx.x; j < NN; j += 256) G[i*NN + j] = A[i*NN + j] / d;
}
__global__ void colsum_k(const float* __restrict__ A, float* __restrict__ cs) {
    int c = blockIdx.x * blockDim.x + threadIdx.x;
    if (c < NN) {
        float s = 0.f;
        for (int r = 0; r < NN; r++) s += A[r*NN + c];
        cs[c] = s;
    }
}
__global__ void fill_wb_k(const float* __restrict__ A, const float* __restrict__ cs,
                          float* __restrict__ G) {
    int i = blockIdx.x;
    float d = cs[i] + 1e-6f;
    for (int j = threadIdx.x; j < NN; j += 256) G[(NN+i)*NN + j] = A[j*NN + i] / d;
}
__global__ void split_G_k(const float* __restrict__ G, bf16* __restrict__ Gh,
                          bf16* __restrict__ Gl) {
    int i = blockIdx.x * blockDim.x + threadIdx.x;
    if (i < 2*NN*NN) {
        float v = G[i];
        bf16 h = __float2bfloat16(v);
        Gh[i] = h;
        Gl[i] = __float2bfloat16(v - __bfloat162float(h));
    }
}
__global__ void zero2_k(float* a, float* b, int n) {
    int i = blockIdx.x * blockDim.x + threadIdx.x;
    if (i < n) { a[i] = 0.f; b[i] = 0.f; }
}

// ---------------- hop GEMM on tensor cores ---------------------------------
// Y(m0..m0+128, c0..c0+128) = G(row-major) @ X ; X selected top/bottom by m0.
// Split-bf16: acc += Ghi*Xhi + Glo*Xhi + Ghi*Xlo.
#define MMA_BF16(d, a, b0v, b1v)                                              \
    asm("mma.sync.aligned.m16n8k16.row.col.f32.bf16.bf16.f32 "                \
        "{%0,%1,%2,%3}, {%4,%5,%6,%7}, {%8,%9}, {%0,%1,%2,%3};"               \
        : "+f"(d[0]), "+f"(d[1]), "+f"(d[2]), "+f"(d[3])                      \
        : "r"(a[0]), "r"(a[1]), "r"(a[2]), "r"(a[3]), "r"(b0v), "r"(b1v))

__device__ __forceinline__ void split_store2(bf16* Yh, bf16* Yl, size_t off, float2 v) {
    bf16 h0 = __float2bfloat16(v.x);
    bf16 h1 = __float2bfloat16(v.y);
    bf16 l0 = __float2bfloat16(v.x - __bfloat162float(h0));
    bf16 l1 = __float2bfloat16(v.y - __bfloat162float(h1));
    __nv_bfloat162 hh; hh.x = h0; hh.y = h1;
    __nv_bfloat162 ll; ll.x = l0; ll.y = l1;
    *reinterpret_cast<__nv_bfloat162*>(&Yh[off]) = hh;
    *reinterpret_cast<__nv_bfloat162*>(&Yl[off]) = ll;
}

__global__ __launch_bounds__(256)
void hop_mma(const bf16* __restrict__ Gh, const bf16* __restrict__ Gl,
             const bf16* __restrict__ Xth, const bf16* __restrict__ Xtl,
             const bf16* __restrict__ Xbh, const bf16* __restrict__ Xbl,
             float* __restrict__ Y, bf16* __restrict__ Yh, bf16* __restrict__ Yl,
             int C, int write_split)
{
    const int m0 = blockIdx.y * 128;
    const int c0 = blockIdx.x * 128;
    const bf16* __restrict__ Xh = (m0 < NN) ? Xth : Xbh;
    const bf16* __restrict__ Xl = (m0 < NN) ? Xtl : Xbl;

    __shared__ bf16 Ash[128][AP];
    __shared__ bf16 Asl[128][AP];
    __shared__ bf16 Bsh[128][AP];
    __shared__ bf16 Bsl[128][AP];

    const int tid  = threadIdx.x;
    const int wid  = tid >> 5, lane = tid & 31;
    const int g    = lane >> 2, t4 = lane & 3;
    const int wm   = (wid >> 2) * 64;   // 0 or 64
    const int wn   = (wid & 3) * 32;    // 0,32,64,96

    float acc[4][4][4];
    #pragma unroll
    for (int mi = 0; mi < 4; mi++)
        #pragma unroll
        for (int ni = 0; ni < 4; ni++)
            #pragma unroll
            for (int q = 0; q < 4; q++) acc[mi][ni][q] = 0.f;

    for (int k0 = 0; k0 < NN; k0 += KC) {
        // --- A tiles: 128 rows x KC, vectorized ---
        {
            int r = tid >> 1;
            int half = tid & 1;                 // 16 bf16 halves
            const uint4* sah = reinterpret_cast<const uint4*>(Gh + (size_t)(m0+r)*NN + k0 + half*16);
            const uint4* sal = reinterpret_cast<const uint4*>(Gl + (size_t)(m0+r)*NN + k0 + half*16);
            uint4 h0v = sah[0], h1v = sah[1];
            uint4 l0v = sal[0], l1v = sal[1];
            *reinterpret_cast<uint4*>(&Ash[r][half*16])     = h0v;
            *reinterpret_cast<uint4*>(&Ash[r][half*16 + 8]) = h1v;
            *reinterpret_cast<uint4*>(&Asl[r][half*16])     = l0v;
            *reinterpret_cast<uint4*>(&Asl[r][half*16 + 8]) = l1v;
        }
        // --- B tiles: X[k0..k0+KC][c0..c0+128] transposed into Bs[c][k] ---
        #pragma unroll
        for (int i = 0; i < 16; i++) {
            int e = i*256 + tid;
            int k = e >> 7, c = e & 127;
            int gc = c0 + c;
            bf16 vh = __float2bfloat16(0.f), vl = vh;
            if (gc < C) {
                size_t off = (size_t)(k0+k)*C + gc;
                vh = Xh[off]; vl = Xl[off];
            }
            Bsh[c][k] = vh; Bsl[c][k] = vl;
        }
        __syncthreads();

        #pragma unroll
        for (int kk = 0; kk < KC; kk += 16) {
            unsigned ah[4][4], al[4][4];
            #pragma unroll
            for (int mi = 0; mi < 4; mi++) {
                int mr = wm + mi*16;
                ah[mi][0] = *reinterpret_cast<const unsigned*>(&Ash[mr+g  ][kk + t4*2]);
                ah[mi][1] = *reinterpret_cast<const unsigned*>(&Ash[mr+g+8][kk + t4*2]);
                ah[mi][2] = *reinterpret_cast<const unsigned*>(&Ash[mr+g  ][kk + 8 + t4*2]);
                ah[mi][3] = *reinterpret_cast<const unsigned*>(&Ash[mr+g+8][kk + 8 + t4*2]);
                al[mi][0] = *reinterpret_cast<const unsigned*>(&Asl[mr+g  ][kk + t4*2]);
                al[mi][1] = *reinterpret_cast<const unsigned*>(&Asl[mr+g+8][kk + t4*2]);
                al[mi][2] = *reinterpret_cast<const unsigned*>(&Asl[mr+g  ][kk + 8 + t4*2]);
                al[mi][3] = *reinterpret_cast<const unsigned*>(&Asl[mr+g+8][kk + 8 + t4*2]);
            }
            #pragma unroll
            for (int ni = 0; ni < 4; ni++) {
                int nc = wn + ni*8;
                unsigned bh0 = *reinterpret_cast<const unsigned*>(&Bsh[nc+g][kk + t4*2]);
                unsigned bh1 = *reinterpret_cast<const unsigned*>(&Bsh[nc+g][kk + 8 + t4*2]);
                unsigned bl0 = *reinterpret_cast<const unsigned*>(&Bsl[nc+g][kk + t4*2]);
                unsigned bl1 = *reinterpret_cast<const unsigned*>(&Bsl[nc+g][kk + 8 + t4*2]);
                #pragma unroll
                for (int mi = 0; mi < 4; mi++) {
                    MMA_BF16(acc[mi][ni], ah[mi], bh0, bh1);
                    MMA_BF16(acc[mi][ni], al[mi], bh0, bh1);
                    MMA_BF16(acc[mi][ni], ah[mi], bl0, bl1);
                }
            }
        }
        __syncthreads();
    }

    // --- epilogue ---
    #pragma unroll
    for (int mi = 0; mi < 4; mi++) {
        #pragma unroll
        for (int ni = 0; ni < 4; ni++) {
            int ncol = c0 + wn + ni*8 + t4*2;
            if (ncol < C) {
                int m1 = m0 + wm + mi*16 + g;
                int m2 = m1 + 8;
                float2 v01; v01.x = acc[mi][ni][0]; v01.y = acc[mi][ni][1];
                float2 v23; v23.x = acc[mi][ni][2]; v23.y = acc[mi][ni][3];
                size_t o1 = (size_t)m1*C + ncol;
                size_t o2 = (size_t)m2*C + ncol;
                *reinterpret_cast<float2*>(&Y[o1]) = v01;
                *reinterpret_cast<float2*>(&Y[o2]) = v23;
                if (write_split) {
                    split_store2(Yh, Yl, o1, v01);
                    split_store2(Yh, Yl, o2, v23);
                }
            }
        }
    }
}

// ---------------- gate GEMM (FFMA2, unchanged from R2) ---------------------
struct GateArgs {
    const float *f0, *f1, *f2, *f3, *f4;
    const float *h0, *h1, *h2, *h3, *h4;
    int F, split;
    const float *W1, *b1; float *Y1;
    const float *W2, *b2; float *Y2;
    const float *zg; float *h;
    int mode;
};

__global__ __launch_bounds__(128, 4)
void gate_gemm(GateArgs a)
{
    const float* Xf[5] = {a.f0, a.f1, a.f2, a.f3, a.f4};
    const float* Xh[5] = {a.h0, a.h1, a.h2, a.h3, a.h4};
    const float* Wl = (a.mode == 0 && blockIdx.z) ? a.W2 : a.W1;
    const float* bl = (a.mode == 0 && blockIdx.z) ? a.b2 : a.b1;
    float*       Yl = (a.mode == 0 && blockIdx.z) ? a.Y2 : a.Y1;
    const int m0 = blockIdx.x * 64;
    const int tid = threadIdx.x;
    const int tx = tid & 15, ty = tid >> 4;
    const int F = a.F, split = a.split;

    __shared__ float As[16][64];
    __shared__ float Bs[16][64];

    unsigned long long acc[8][2];
    #pragma unroll
    for (int i = 0; i < 8; i++) { acc[i][0] = 0ull; acc[i][1] = 0ull; }

    const int arow = tid >> 1;
    const int ak   = (tid & 1) * 8;
    const int bk   = tid >> 3;
    const int bc   = (tid & 7) * 8;

    for (int s = 0; s < 5; s++) {
        const float* __restrict__ Xs = Xf[s];
        const float* __restrict__ Hs = Xh[s];
        for (int k0 = 0; k0 < F; k0 += 16) {
            #pragma unroll
            for (int u = 0; u < 8; u++) {
                int f = k0 + ak + u;
                float v = 0.f;
                if (f < F) {
                    if (f < split) v = Xs[(size_t)(m0+arow)*F + f];
                    else           v = Hs[(size_t)(m0+arow)*HID + (f - HID)];
                }
                As[ak+u][arow] = v;
            }
            {
                int f = k0 + bk;
                float4 v0 = make_float4(0.f,0.f,0.f,0.f), v1 = v0;
                if (f < F) {
                    v0 = *reinterpret_cast<const float4*>(&Wl[(size_t)(s*F+f)*HID + bc]);
                    v1 = *reinterpret_cast<const float4*>(&Wl[(size_t)(s*F+f)*HID + bc + 4]);
                }
                *reinterpret_cast<float4*>(&Bs[bk][bc])     = v0;
                *reinterpret_cast<float4*>(&Bs[bk][bc + 4]) = v1;
            }
            __syncthreads();
            #pragma unroll
            for (int kk = 0; kk < 16; kk++) {
                float4 a0 = *reinterpret_cast<const float4*>(&As[kk][ty*8]);
                float4 a1 = *reinterpret_cast<const float4*>(&As[kk][ty*8 + 4]);
                float4 b0 = *reinterpret_cast<const float4*>(&Bs[kk][tx*4]);
                unsigned long long ap[8] = {pk2(a0.x), pk2(a0.y), pk2(a0.z), pk2(a0.w),
                                            pk2(a1.x), pk2(a1.y), pk2(a1.z), pk2(a1.w)};
                unsigned long long bp[2] = {pk(b0.x,b0.y), pk(b0.z,b0.w)};
                #pragma unroll
                for (int i = 0; i < 8; i++) {
                    FFMA2(acc[i][0], ap[i], bp[0]);
                    FFMA2(acc[i][1], ap[i], bp[1]);
                }
            }
            __syncthreads();
        }
    }

    const int c = tx * 4;
    float bias[4] = {bl[c], bl[c+1], bl[c+2], bl[c+3]};
    #pragma unroll
    for (int i = 0; i < 8; i++) {
        int m = m0 + ty*8 + i;
        UPair p0, p1; p0.u = acc[i][0]; p1.u = acc[i][1];
        float v[4] = {p0.f.x + bias[0], p0.f.y + bias[1],
                      p1.f.x + bias[2], p1.f.y + bias[3]};
        if (a.mode == 0) {
            float4 o;
            o.x = 1.f / (1.f + expf(-v[0]));
            o.y = 1.f / (1.f + expf(-v[1]));
            o.z = 1.f / (1.f + expf(-v[2]));
            o.w = 1.f / (1.f + expf(-v[3]));
            *reinterpret_cast<float4*>(&Yl[(size_t)m*HID + c]) = o;
        } else {
            float4 zz = *reinterpret_cast<const float4*>(&a.zg[(size_t)m*HID + c]);
            float4 hh = *reinterpret_cast<float4*>(&a.h[(size_t)m*HID + c]);
            float4 o;
            o.x = (1.f - zz.x) * hh.x + zz.x * tanhf(v[0]);
            o.y = (1.f - zz.y) * hh.y + zz.y * tanhf(v[1]);
            o.z = (1.f - zz.z) * hh.z + zz.z * tanhf(v[2]);
            o.w = (1.f - zz.w) * hh.w + zz.w * tanhf(v[3]);
            *reinterpret_cast<float4*>(&a.h[(size_t)m*HID + c]) = o;
        }
    }
}

// ---------------- packing / small kernels ----------------------------------
__device__ __forceinline__ void emit_split(float v, float* X, bf16* Xh, bf16* Xl, int idx) {
    X[idx] = v;
    bf16 h = __float2bfloat16(v);
    Xh[idx] = h;
    Xl[idx] = __float2bfloat16(v - __bfloat162float(h));
}

__global__ void pack_l0(const float* __restrict__ di, const float* __restrict__ h,
                        const float* __restrict__ r, float* __restrict__ X,
                        bf16* __restrict__ Xh, bf16* __restrict__ Xl)
{
    int idx = blockIdx.x * blockDim.x + threadIdx.x;
    if (idx >= NB * F0) return;
    int m = idx / F0, f = idx - m * F0;
    float v;
    if (f == 0) v = di[m];
    else {
        int g = f - 1;
        v = h[m*HID + g];
        if (r) v *= r[m*HID + g];
    }
    emit_split(v, X, Xh, Xl, idx);
}
__global__ void pack_l1(const float* __restrict__ h0, const float* __restrict__ h1,
                        float* __restrict__ X, bf16* __restrict__ Xh, bf16* __restrict__ Xl)
{
    int idx = blockIdx.x * blockDim.x + threadIdx.x;
    if (idx >= NB * F1) return;
    int m = idx >> 7, f = idx & 127;
    float v = (f < HID) ? h0[m*HID + f] : h1[m*HID + (f - HID)];
    emit_split(v, X, Xh, Xl, idx);
}
__global__ void mul_rh(const float* __restrict__ r, const float* __restrict__ h,
                       float* __restrict__ o, bf16* __restrict__ oh, bf16* __restrict__ ol)
{
    int i = blockIdx.x * blockDim.x + threadIdx.x;
    if (i < NB*HID) emit_split(r[i] * h[i], o, oh, ol, i);
}
__global__ void copy_xt(const float* __restrict__ x, int t, float* __restrict__ di)
{
    int idx = blockIdx.x * blockDim.x + threadIdx.x;
    if (idx >= NB) return;
    int b = idx >> 9, n = idx & 511;
    di[n*BB + b] = x[b*(TIN*NN) + t*NN + n];
}
__global__ void proj_k(const float* __restrict__ h1, const float* __restrict__ Wp,
                       const float* __restrict__ bp, float* __restrict__ out,
                       float* __restrict__ di, int t)
{
    int m = blockIdx.x * blockDim.x + threadIdx.x;
    if (m >= NB) return;
    float s = bp[0];
    #pragma unroll
    for (int f = 0; f < HID; f++) s += h1[m*HID + f] * Wp[f];
    int n = m >> 4, b = m & 15;
    out[b*(TOUT*NN) + t*NN + n] = s;
    di[m] = s;
}

// ---------------- host driver ----------------------------------------------
extern "C" void kernel_launch(void* const* d_in, const int* in_sizes, int n_in,
                              void* d_out, int out_size)
{
    const float* x   = (const float*)d_in[0];
    const float* A   = (const float*)d_in[1];
    const float* Wr0 = (const float*)d_in[2];
    const float* br0 = (const float*)d_in[3];
    const float* Wz0 = (const float*)d_in[4];
    const float* bz0 = (const float*)d_in[5];
    const float* Wn0 = (const float*)d_in[6];
    const float* bn0 = (const float*)d_in[7];
    const float* Wr1 = (const float*)d_in[8];
    const float* br1 = (const float*)d_in[9];
    const float* Wz1 = (const float*)d_in[10];
    const float* bz1 = (const float*)d_in[11];
    const float* Wn1 = (const float*)d_in[12];
    const float* bn1 = (const float*)d_in[13];
    const float* Wp  = (const float*)d_in[14];
    const float* bp  = (const float*)d_in[15];
    float* out = (float*)d_out;

    float *G, *cs, *h0, *h1, *di, *S0, *S1, *S2, *T0, *T1, *T2, *r, *z;
    bf16 *Gh, *Gl, *S0h, *S0l, *S1h, *S1l, *T0h, *T0l, *T1h, *T1l;
    cudaGetSymbolAddress((void**)&G,   g_G);
    cudaGetSymbolAddress((void**)&Gh,  g_Gh);
    cudaGetSymbolAddress((void**)&Gl,  g_Gl);
    cudaGetSymbolAddress((void**)&cs,  g_cs);
    cudaGetSymbolAddress((void**)&h0,  g_h0);
    cudaGetSymbolAddress((void**)&h1,  g_h1);
    cudaGetSymbolAddress((void**)&di,  g_di);
    cudaGetSymbolAddress((void**)&S0,  g_S0);
    cudaGetSymbolAddress((void**)&S0h, g_S0h);
    cudaGetSymbolAddress((void**)&S0l, g_S0l);
    cudaGetSymbolAddress((void**)&S1,  g_S1);
    cudaGetSymbolAddress((void**)&S1h, g_S1h);
    cudaGetSymbolAddress((void**)&S1l, g_S1l);
    cudaGetSymbolAddress((void**)&S2,  g_S2);
    cudaGetSymbolAddress((void**)&T0,  g_T0);
    cudaGetSymbolAddress((void**)&T0h, g_T0h);
    cudaGetSymbolAddress((void**)&T0l, g_T0l);
    cudaGetSymbolAddress((void**)&T1,  g_T1);
    cudaGetSymbolAddress((void**)&T1h, g_T1h);
    cudaGetSymbolAddress((void**)&T1l, g_T1l);
    cudaGetSymbolAddress((void**)&T2,  g_T2);
    cudaGetSymbolAddress((void**)&r,   g_r);
    cudaGetSymbolAddress((void**)&z,   g_z);

    rownorm_k<<<NN, 256>>>(A, G);
    colsum_k<<<2, 256>>>(A, cs);
    fill_wb_k<<<NN, 256>>>(A, cs, G);
    split_G_k<<<(2*NN*NN + 255)/256, 256>>>(G, Gh, Gl);
    zero2_k<<<(NB*HID + 255)/256, 256>>>(h0, h1, NB*HID);

    auto gate_args = [&](const float* s0, const float* s1, const float* s2, int C,
                         const float* t0, const float* t1, const float* t2, int Ch,
                         int F, int split) {
        GateArgs ga;
        ga.f0 = s0; ga.f1 = s1; ga.f2 = s2;
        ga.f3 = s1 ? s1 + (size_t)NN*C : nullptr;
        ga.f4 = s2 ? s2 + (size_t)NN*C : nullptr;
        ga.h0 = t0; ga.h1 = t1; ga.h2 = t2;
        ga.h3 = t1 ? t1 + (size_t)NN*Ch : nullptr;
        ga.h4 = t2 ? t2 + (size_t)NN*Ch : nullptr;
        ga.F = F; ga.split = split;
        ga.W1 = nullptr; ga.b1 = nullptr; ga.Y1 = nullptr;
        ga.W2 = nullptr; ga.b2 = nullptr; ga.Y2 = nullptr;
        ga.zg = nullptr; ga.h = nullptr; ga.mode = 0;
        return ga;
    };

    auto cell0 = [&]() {
        dim3 gh((C0 + 127)/128, 8);
        int packG = (NB*F0 + 255)/256;
        // xh chain
        pack_l0<<<packG, 256>>>(di, h0, nullptr, S0, S0h, S0l);
        hop_mma<<<gh, 256>>>(Gh, Gl, S0h, S0l, S0h, S0l, S1, S1h, S1l, C0, 1);
        hop_mma<<<gh, 256>>>(Gh, Gl, S1h, S1l, S1h + (size_t)NN*C0, S1l + (size_t)NN*C0,
                             S2, nullptr, nullptr, C0, 0);
        GateArgs ga = gate_args(S0, S1, S2, C0, nullptr, nullptr, nullptr, 0, F0, F0);
        ga.W1 = Wr0; ga.b1 = br0; ga.Y1 = r;
        ga.W2 = Wz0; ga.b2 = bz0; ga.Y2 = z;
        ga.mode = 0;
        gate_gemm<<<dim3(NB/64, 1, 2), 128>>>(ga);
        // n chain
        pack_l0<<<packG, 256>>>(di, h0, r, S0, S0h, S0l);
        hop_mma<<<gh, 256>>>(Gh, Gl, S0h, S0l, S0h, S0l, S1, S1h, S1l, C0, 1);
        hop_mma<<<gh, 256>>>(Gh, Gl, S1h, S1l, S1h + (size_t)NN*C0, S1l + (size_t)NN*C0,
                             S2, nullptr, nullptr, C0, 0);
        GateArgs gn = gate_args(S0, S1, S2, C0, nullptr, nullptr, nullptr, 0, F0, F0);
        gn.W1 = Wn0; gn.b1 = bn0; gn.zg = z; gn.h = h0; gn.mode = 1;
        gate_gemm<<<dim3(NB/64, 1, 1), 128>>>(gn);
    };

    auto cell1 = [&]() {
        dim3 gh(C1/128, 8), ghh(CH/128, 8);
        // xh chain
        pack_l1<<<(NB*F1)/256, 256>>>(h0, h1, S0, S0h, S0l);
        hop_mma<<<gh, 256>>>(Gh, Gl, S0h, S0l, S0h, S0l, S1, S1h, S1l, C1, 1);
        hop_mma<<<gh, 256>>>(Gh, Gl, S1h, S1l, S1h + (size_t)NN*C1, S1l + (size_t)NN*C1,
                             S2, nullptr, nullptr, C1, 0);
        GateArgs ga = gate_args(S0, S1, S2, C1, nullptr, nullptr, nullptr, 0, F1, F1);
        ga.W1 = Wr1; ga.b1 = br1; ga.Y1 = r;
        ga.W2 = Wz1; ga.b2 = bz1; ga.Y2 = z;
        ga.mode = 0;
        gate_gemm<<<dim3(NB/64, 1, 2), 128>>>(ga);
        // n chain: only r*h1 half needs hops
        mul_rh<<<(NB*HID)/256, 256>>>(r, h1, T0, T0h, T0l);
        hop_mma<<<ghh, 256>>>(Gh, Gl, T0h, T0l, T0h, T0l, T1, T1h, T1l, CH, 1);
        hop_mma<<<ghh, 256>>>(Gh, Gl, T1h, T1l, T1h + (size_t)NN*CH, T1l + (size_t)NN*CH,
                              T2, nullptr, nullptr, CH, 0);
        GateArgs gn = gate_args(S0, S1, S2, C1, T0, T1, T2, CH, F1, HID);
        gn.W1 = Wn1; gn.b1 = bn1; gn.zg = z; gn.h = h1; gn.mode = 1;
        gate_gemm<<<dim3(NB/64, 1, 1), 128>>>(gn);
    };

    for (int t = 0; t < TIN; t++) {
        copy_xt<<<NB/256, 256>>>(x, t, di);
        cell0();
        cell1();
    }
    copy_xt<<<NB/256, 256>>>(x, TIN - 1, di);
    for (int t = 0; t < TOUT; t++) {
        cell0();
        cell1();
        proj_k<<<NB/256, 256>>>(h1, Wp, bp, out, di, t);
    }
}

// round 4
// speedup vs baseline: 2.7401x; 1.7749x over previous
#include <cuda_runtime.h>
#include <cuda_bf16.h>
#include <math.h>

// ---------------------------------------------------------------------------
// DCRNN 2-layer DCGRU. B=16, N=512, HID=64, K=2, T_in=12, T_out=12.
// All GEMMs (hops AND gates) on tensor cores, mma.sync bf16 with two-term
// split (hi/lo):  A·B ~= Ah·Bh + Al·Bh + Ah·Bl   (fp32-grade accuracy).
// cp.async 2-stage pipelines + ldmatrix fragments.
// Layer-0 feature dim padded 65 -> 80 so every tile is full (no predicates).
// ---------------------------------------------------------------------------

#define NN   512
#define BB   16
#define HID  64
#define NB   (NN*BB)          // 8192
#define F0P  80               // padded layer0 features (1 + 64 + 15 pad)
#define F1   128
#define C0P  (BB*F0P)         // 1280
#define C1   (BB*F1)          // 2048
#define CH   (BB*HID)         // 1024
#define TIN  12
#define TOUT 12

#define KC   32               // hop k-chunk
#define APP  40               // hop A smem pitch
#define BPP  136              // hop B smem pitch
#define GAP  24               // gate A smem pitch
#define GBP  72               // gate B smem pitch

#define KP0  (5*F0P)          // 400 padded gate K, layer0
#define KP1  (5*F1)           // 640

typedef __nv_bfloat16 bf16;

// ---------------- device scratch -------------------------------------------
__device__ float g_G [2*NN*NN];
__device__ bf16  g_Gh[2*NN*NN];
__device__ bf16  g_Gl[2*NN*NN];
__device__ float g_cs[NN];
__device__ float g_h0[NB*HID];
__device__ float g_h1[NB*HID];
__device__ float g_di[NB];
__device__ bf16  g_S0h[NN*C1];
__device__ bf16  g_S0l[NN*C1];
__device__ bf16  g_S1h[2*NN*C1];
__device__ bf16  g_S1l[2*NN*C1];
__device__ bf16  g_S2h[2*NN*C1];
__device__ bf16  g_S2l[2*NN*C1];
__device__ bf16  g_T0h[NN*CH];
__device__ bf16  g_T0l[NN*CH];
__device__ bf16  g_T1h[2*NN*CH];
__device__ bf16  g_T1l[2*NN*CH];
__device__ bf16  g_T2h[2*NN*CH];
__device__ bf16  g_T2l[2*NN*CH];
__device__ float g_r [NB*HID];
__device__ float g_z [NB*HID];
// padded split gate weights: [W0r | W0z | W0n | W1r | W1z | W1n]
#define OW0R 0
#define OW0Z (KP0*HID)
#define OW0N (2*KP0*HID)
#define OW1R (3*KP0*HID)
#define OW1Z (3*KP0*HID + KP1*HID)
#define OW1N (3*KP0*HID + 2*KP1*HID)
#define WTOT (3*KP0*HID + 3*KP1*HID)
__device__ bf16  g_Wsh[WTOT];
__device__ bf16  g_Wsl[WTOT];

// ---------------- PTX helpers ----------------------------------------------
__device__ __forceinline__ void cp16(void* dst, const void* src) {
    unsigned d = (unsigned)__cvta_generic_to_shared(dst);
    asm volatile("cp.async.ca.shared.global [%0], [%1], 16;\n" :: "r"(d), "l"(src));
}
#define CP_COMMIT() asm volatile("cp.async.commit_group;\n")
#define CP_WAIT(n)  asm volatile("cp.async.wait_group %0;\n" :: "n"(n))

__device__ __forceinline__ void ldsm4(unsigned* r, const void* p) {
    unsigned a = (unsigned)__cvta_generic_to_shared(p);
    asm volatile("ldmatrix.sync.aligned.m8n8.x4.shared.b16 {%0,%1,%2,%3}, [%4];"
                 : "=r"(r[0]), "=r"(r[1]), "=r"(r[2]), "=r"(r[3]) : "r"(a));
}
__device__ __forceinline__ void ldsm4t(unsigned* r, const void* p) {
    unsigned a = (unsigned)__cvta_generic_to_shared(p);
    asm volatile("ldmatrix.sync.aligned.m8n8.x4.trans.shared.b16 {%0,%1,%2,%3}, [%4];"
                 : "=r"(r[0]), "=r"(r[1]), "=r"(r[2]), "=r"(r[3]) : "r"(a));
}
#define MMA_BF16(d, a, b0v, b1v)                                              \
    asm("mma.sync.aligned.m16n8k16.row.col.f32.bf16.bf16.f32 "                \
        "{%0,%1,%2,%3}, {%4,%5,%6,%7}, {%8,%9}, {%0,%1,%2,%3};"               \
        : "+f"(d[0]), "+f"(d[1]), "+f"(d[2]), "+f"(d[3])                      \
        : "r"(a[0]), "r"(a[1]), "r"(a[2]), "r"(a[3]), "r"(b0v), "r"(b1v))

__device__ __forceinline__ void split_store2(bf16* Yh, bf16* Yl, size_t off, float vx, float vy) {
    bf16 h0 = __float2bfloat16(vx);
    bf16 h1 = __float2bfloat16(vy);
    bf16 l0 = __float2bfloat16(vx - __bfloat162float(h0));
    bf16 l1 = __float2bfloat16(vy - __bfloat162float(h1));
    __nv_bfloat162 hh; hh.x = h0; hh.y = h1;
    __nv_bfloat162 ll; ll.x = l0; ll.y = l1;
    *reinterpret_cast<__nv_bfloat162*>(&Yh[off]) = hh;
    *reinterpret_cast<__nv_bfloat162*>(&Yl[off]) = ll;
}

// ---------------- A -> G normalization -------------------------------------
__global__ void rownorm_k(const float* __restrict__ A, float* __restrict__ G) {
    int i = blockIdx.x;
    __shared__ float red[256];
    float s = 0.f;
    for (int j = threadIdx.x; j < NN; j += 256) s += A[i*NN + j];
    red[threadIdx.x] = s; __syncthreads();
    for (int off = 128; off; off >>= 1) {
        if (threadIdx.x < off) red[threadIdx.x] += red[threadIdx.x + off];
        __syncthreads();
    }
    float d = red[0] + 1e-6f;
    for (int j = threadIdx.x; j < NN; j += 256) G[i*NN + j] = A[i*NN + j] / d;
}
__global__ void colsum_k(const float* __restrict__ A, float* __restrict__ cs) {
    int c = blockIdx.x * blockDim.x + threadIdx.x;
    if (c < NN) {
        float s = 0.f;
        for (int r = 0; r < NN; r++) s += A[r*NN + c];
        cs[c] = s;
    }
}
__global__ void fill_wb_k(const float* __restrict__ A, const float* __restrict__ cs,
                          float* __restrict__ G) {
    int i = blockIdx.x;
    float d = cs[i] + 1e-6f;
    for (int j = threadIdx.x; j < NN; j += 256) G[(NN+i)*NN + j] = A[j*NN + i] / d;
}
__global__ void split_G_k(const float* __restrict__ G, bf16* __restrict__ Gh,
                          bf16* __restrict__ Gl) {
    int i = blockIdx.x * blockDim.x + threadIdx.x;
    if (i < 2*NN*NN) {
        float v = G[i];
        bf16 h = __float2bfloat16(v);
        Gh[i] = h;
        Gl[i] = __float2bfloat16(v - __bfloat162float(h));
    }
}
// pad+split one gate weight matrix (5F x 64) into (5*Fp x 64)
__global__ void split_W_k(const float* __restrict__ W, int F, int Fp,
                          bf16* __restrict__ Wh, bf16* __restrict__ Wl) {
    int i = blockIdx.x * blockDim.x + threadIdx.x;
    if (i >= 5*Fp*HID) return;
    int row = i >> 6, c = i & 63;
    int s = row / Fp, f = row - s*Fp;
    float v = (f < F) ? W[(size_t)(s*F + f)*HID + c] : 0.f;
    bf16 h = __float2bfloat16(v);
    Wh[i] = h;
    Wl[i] = __float2bfloat16(v - __bfloat162float(h));
}
__global__ void zero2_k(float* a, float* b, int n) {
    int i = blockIdx.x * blockDim.x + threadIdx.x;
    if (i < n) { a[i] = 0.f; b[i] = 0.f; }
}

// ---------------- hop GEMM: pipelined mma ----------------------------------
// Y(m0..+128, c0..+128) = G @ X ; X selected top/bottom by m0. C % 128 == 0.
__global__ __launch_bounds__(256)
void hop_mma(const bf16* __restrict__ Gh, const bf16* __restrict__ Gl,
             const bf16* __restrict__ Xth, const bf16* __restrict__ Xtl,
             const bf16* __restrict__ Xbh, const bf16* __restrict__ Xbl,
             bf16* __restrict__ Yh, bf16* __restrict__ Yl, int C)
{
    const int m0 = blockIdx.y * 128;
    const int c0 = blockIdx.x * 128;
    const bf16* __restrict__ Xh = (m0 < NN) ? Xth : Xbh;
    const bf16* __restrict__ Xl = (m0 < NN) ? Xtl : Xbl;

    __shared__ bf16 Ash[2][128][APP];
    __shared__ bf16 Asl[2][128][APP];
    __shared__ bf16 Bsh[2][KC][BPP];
    __shared__ bf16 Bsl[2][KC][BPP];

    const int tid = threadIdx.x;
    const int wid = tid >> 5, lane = tid & 31;
    const int wm = (wid >> 2) * 64, wn = (wid & 3) * 32;
    const int g = lane >> 2, t4 = lane & 3;

    const int ar = tid >> 1;
    const int aj = (tid & 1) * 16;
    const int bk = tid >> 3;
    const int bj = (tid & 7) * 8;

    float acc[4][4][4];
    #pragma unroll
    for (int mi = 0; mi < 4; mi++)
        #pragma unroll
        for (int ni = 0; ni < 4; ni++)
            #pragma unroll
            for (int q = 0; q < 4; q++) acc[mi][ni][q] = 0.f;

    auto load_stage = [&](int buf, int k0) {
        const bf16* a1 = Gh + (size_t)(m0+ar)*NN + k0 + aj;
        const bf16* a2 = Gl + (size_t)(m0+ar)*NN + k0 + aj;
        cp16(&Ash[buf][ar][aj],     a1);
        cp16(&Ash[buf][ar][aj+8],   a1+8);
        cp16(&Asl[buf][ar][aj],     a2);
        cp16(&Asl[buf][ar][aj+8],   a2+8);
        const bf16* b1 = Xh + (size_t)(k0+bk)*C + c0 + bj;
        const bf16* b2 = Xl + (size_t)(k0+bk)*C + c0 + bj;
        cp16(&Bsh[buf][bk][bj],     b1);
        cp16(&Bsh[buf][bk][bj+64],  b1+64);
        cp16(&Bsl[buf][bk][bj],     b2);
        cp16(&Bsl[buf][bk][bj+64],  b2+64);
    };

    load_stage(0, 0);
    CP_COMMIT();

    const int NIT = NN / KC;   // 16
    for (int it = 0; it < NIT; it++) {
        int buf = it & 1;
        if (it + 1 < NIT) { load_stage(buf ^ 1, (it+1)*KC); CP_COMMIT(); CP_WAIT(1); }
        else              { CP_WAIT(0); }
        __syncthreads();

        #pragma unroll
        for (int kk = 0; kk < KC; kk += 16) {
            const int arow = lane & 15;
            const int acol = kk + ((lane >> 4) << 3);
            unsigned ah[4][4], al[4][4];
            #pragma unroll
            for (int mi = 0; mi < 4; mi++) {
                ldsm4(ah[mi], &Ash[buf][wm + mi*16 + arow][acol]);
                ldsm4(al[mi], &Asl[buf][wm + mi*16 + arow][acol]);
            }
            const int brow = kk + (lane & 15);
            #pragma unroll
            for (int np = 0; np < 2; np++) {
                const int bcol = wn + np*16 + ((lane >> 4) << 3);
                unsigned bh[4], blo[4];
                ldsm4t(bh,  &Bsh[buf][brow][bcol]);
                ldsm4t(blo, &Bsl[buf][brow][bcol]);
                #pragma unroll
                for (int h2 = 0; h2 < 2; h2++) {
                    int ni = np*2 + h2;
                    #pragma unroll
                    for (int mi = 0; mi < 4; mi++) {
                        MMA_BF16(acc[mi][ni], ah[mi], bh[h2*2],  bh[h2*2+1]);
                        MMA_BF16(acc[mi][ni], al[mi], bh[h2*2],  bh[h2*2+1]);
                        MMA_BF16(acc[mi][ni], ah[mi], blo[h2*2], blo[h2*2+1]);
                    }
                }
            }
        }
        __syncthreads();
    }

    #pragma unroll
    for (int mi = 0; mi < 4; mi++) {
        #pragma unroll
        for (int ni = 0; ni < 4; ni++) {
            int ncol = c0 + wn + ni*8 + t4*2;
            int m1 = m0 + wm + mi*16 + g;
            size_t o1 = (size_t)m1*C + ncol;
            size_t o2 = (size_t)(m1+8)*C + ncol;
            split_store2(Yh, Yl, o1, acc[mi][ni][0], acc[mi][ni][1]);
            split_store2(Yh, Yl, o2, acc[mi][ni][2], acc[mi][ni][3]);
        }
    }
}

// ---------------- gate GEMM: (8192, 5Fp)@(5Fp,64), mma, fused epilogue -----
struct GateArgs {
    const bf16 *fh[5], *fl[5];    // f-part slices, row stride Fp
    const bf16 *hh[5], *hl[5];    // h-part slices, row stride 64 (f >= split)
    int Fp, split;
    const bf16 *W1h, *W1l; const float* b1; float* Y1;
    const bf16 *W2h, *W2l; const float* b2; float* Y2;
    const float* zg; float* h;
    int mode;                     // 0: sigmoid -> Y ; 1: tanh + h update
};

__global__ __launch_bounds__(128)
void gate_mma(GateArgs a)
{
    const bf16* Wh = (a.mode == 0 && blockIdx.z) ? a.W2h : a.W1h;
    const bf16* Wl = (a.mode == 0 && blockIdx.z) ? a.W2l : a.W1l;
    const float* bl = (a.mode == 0 && blockIdx.z) ? a.b2 : a.b1;
    float* Yl = (a.mode == 0 && blockIdx.z) ? a.Y2 : a.Y1;

    const int m0 = blockIdx.x * 128;
    const int tid = threadIdx.x;
    const int wid = tid >> 5, lane = tid & 31;
    const int g = lane >> 2, t4 = lane & 3;
    const int Fp = a.Fp, split = a.split;
    const int CPS = Fp >> 4;           // 16-chunks per slice

    __shared__ bf16 Ash[2][128][GAP];
    __shared__ bf16 Asl[2][128][GAP];
    __shared__ bf16 Bsh[2][16][GBP];
    __shared__ bf16 Bsl[2][16][GBP];

    float acc[2][8][4];
    #pragma unroll
    for (int mi = 0; mi < 2; mi++)
        #pragma unroll
        for (int ni = 0; ni < 8; ni++)
            #pragma unroll
            for (int q = 0; q < 4; q++) acc[mi][ni][q] = 0.f;

    const int bkr = tid >> 3;          // 0..15
    const int bjc = (tid & 7) * 8;

    auto load_stage = [&](int buf, int kidx) {
        // A: row = tid, two 8-chunks
        int s  = kidx / CPS;
        int fb = (kidx - s*CPS) * 16;
        #pragma unroll
        for (int j = 0; j < 2; j++) {
            int f0 = fb + j*8;
            const bf16 *sh, *sl;
            if (f0 < split) { sh = a.fh[s] + (size_t)(m0+tid)*Fp + f0;
                              sl = a.fl[s] + (size_t)(m0+tid)*Fp + f0; }
            else            { sh = a.hh[s] + (size_t)(m0+tid)*HID + (f0 - HID);
                              sl = a.hl[s] + (size_t)(m0+tid)*HID + (f0 - HID); }
            cp16(&Ash[buf][tid][j*8], sh);
            cp16(&Asl[buf][tid][j*8], sl);
        }
        // B: padded W is dense (5*Fp, 64): row = global k
        int gk = kidx*16 + bkr;
        cp16(&Bsh[buf][bkr][bjc], Wh + (size_t)gk*HID + bjc);
        cp16(&Bsl[buf][bkr][bjc], Wl + (size_t)gk*HID + bjc);
    };

    load_stage(0, 0);
    CP_COMMIT();

    const int NIT = 5 * CPS;
    for (int it = 0; it < NIT; it++) {
        int buf = it & 1;
        if (it + 1 < NIT) { load_stage(buf ^ 1, it+1); CP_COMMIT(); CP_WAIT(1); }
        else              { CP_WAIT(0); }
        __syncthreads();

        const int arow = lane & 15;
        const int acol = (lane >> 4) << 3;
        unsigned ah[2][4], al[2][4];
        #pragma unroll
        for (int mi = 0; mi < 2; mi++) {
            ldsm4(ah[mi], &Ash[buf][wid*32 + mi*16 + arow][acol]);
            ldsm4(al[mi], &Asl[buf][wid*32 + mi*16 + arow][acol]);
        }
        const int brow = lane & 15;
        #pragma unroll
        for (int np = 0; np < 4; np++) {
            const int bcol = np*16 + ((lane >> 4) << 3);
            unsigned bh[4], blo[4];
            ldsm4t(bh,  &Bsh[buf][brow][bcol]);
            ldsm4t(blo, &Bsl[buf][brow][bcol]);
            #pragma unroll
            for (int h2 = 0; h2 < 2; h2++) {
                int ni = np*2 + h2;
                #pragma unroll
                for (int mi = 0; mi < 2; mi++) {
                    MMA_BF16(acc[mi][ni], ah[mi], bh[h2*2],  bh[h2*2+1]);
                    MMA_BF16(acc[mi][ni], al[mi], bh[h2*2],  bh[h2*2+1]);
                    MMA_BF16(acc[mi][ni], ah[mi], blo[h2*2], blo[h2*2+1]);
                }
            }
        }
        __syncthreads();
    }

    #pragma unroll
    for (int mi = 0; mi < 2; mi++) {
        #pragma unroll
        for (int ni = 0; ni < 8; ni++) {
            int n = ni*8 + t4*2;
            float b0 = bl[n], b1v = bl[n+1];
            #pragma unroll
            for (int half = 0; half < 2; half++) {
                int m = m0 + wid*32 + mi*16 + g + half*8;
                float vx = acc[mi][ni][half*2]   + b0;
                float vy = acc[mi][ni][half*2+1] + b1v;
                size_t off = (size_t)m*HID + n;
                if (a.mode == 0) {
                    float2 o;
                    o.x = 1.f / (1.f + expf(-vx));
                    o.y = 1.f / (1.f + expf(-vy));
                    *reinterpret_cast<float2*>(&Yl[off]) = o;
                } else {
                    float2 zz = *reinterpret_cast<const float2*>(&a.zg[off]);
                    float2 hh = *reinterpret_cast<float2*>(&a.h[off]);
                    float2 o;
                    o.x = (1.f - zz.x) * hh.x + zz.x * tanhf(vx);
                    o.y = (1.f - zz.y) * hh.y + zz.y * tanhf(vy);
                    *reinterpret_cast<float2*>(&a.h[off]) = o;
                }
            }
        }
    }
}

// ---------------- packing / small kernels ----------------------------------
__device__ __forceinline__ void emit_split(float v, bf16* Xh, bf16* Xl, int idx) {
    bf16 h = __float2bfloat16(v);
    Xh[idx] = h;
    Xl[idx] = __float2bfloat16(v - __bfloat162float(h));
}
__global__ void pack_l0(const float* __restrict__ di, const float* __restrict__ h,
                        const float* __restrict__ r, bf16* __restrict__ Xh,
                        bf16* __restrict__ Xl)
{
    int idx = blockIdx.x * blockDim.x + threadIdx.x;
    if (idx >= NB * F0P) return;
    int m = idx / F0P, f = idx - m * F0P;
    float v = 0.f;
    if (f == 0) v = di[m];
    else if (f <= HID) {
        int g = f - 1;
        v = h[m*HID + g];
        if (r) v *= r[m*HID + g];
    }
    emit_split(v, Xh, Xl, idx);
}
__global__ void pack_l1(const float* __restrict__ h0, const float* __restrict__ h1,
                        bf16* __restrict__ Xh, bf16* __restrict__ Xl)
{
    int idx = blockIdx.x * blockDim.x + threadIdx.x;
    if (idx >= NB * F1) return;
    int m = idx >> 7, f = idx & 127;
    float v = (f < HID) ? h0[m*HID + f] : h1[m*HID + (f - HID)];
    emit_split(v, Xh, Xl, idx);
}
__global__ void mul_rh(const float* __restrict__ r, const float* __restrict__ h,
                       bf16* __restrict__ oh, bf16* __restrict__ ol)
{
    int i = blockIdx.x * blockDim.x + threadIdx.x;
    if (i < NB*HID) emit_split(r[i] * h[i], oh, ol, i);
}
__global__ void copy_xt(const float* __restrict__ x, int t, float* __restrict__ di)
{
    int idx = blockIdx.x * blockDim.x + threadIdx.x;
    if (idx >= NB) return;
    int b = idx >> 9, n = idx & 511;
    di[n*BB + b] = x[b*(TIN*NN) + t*NN + n];
}
__global__ void proj_k(const float* __restrict__ h1, const float* __restrict__ Wp,
                       const float* __restrict__ bp, float* __restrict__ out,
                       float* __restrict__ di, int t)
{
    int m = blockIdx.x * blockDim.x + threadIdx.x;
    if (m >= NB) return;
    float s = bp[0];
    #pragma unroll
    for (int f = 0; f < HID; f++) s += h1[m*HID + f] * Wp[f];
    int n = m >> 4, b = m & 15;
    out[b*(TOUT*NN) + t*NN + n] = s;
    di[m] = s;
}

// ---------------- host driver ----------------------------------------------
extern "C" void kernel_launch(void* const* d_in, const int* in_sizes, int n_in,
                              void* d_out, int out_size)
{
    const float* x   = (const float*)d_in[0];
    const float* A   = (const float*)d_in[1];
    const float* Wr0 = (const float*)d_in[2];
    const float* br0 = (const float*)d_in[3];
    const float* Wz0 = (const float*)d_in[4];
    const float* bz0 = (const float*)d_in[5];
    const float* Wn0 = (const float*)d_in[6];
    const float* bn0 = (const float*)d_in[7];
    const float* Wr1 = (const float*)d_in[8];
    const float* br1 = (const float*)d_in[9];
    const float* Wz1 = (const float*)d_in[10];
    const float* bz1 = (const float*)d_in[11];
    const float* Wn1 = (const float*)d_in[12];
    const float* bn1 = (const float*)d_in[13];
    const float* Wp  = (const float*)d_in[14];
    const float* bp  = (const float*)d_in[15];
    float* out = (float*)d_out;

    float *G, *cs, *h0, *h1, *di, *r, *z;
    bf16 *Gh, *Gl, *S0h, *S0l, *S1h, *S1l, *S2h, *S2l;
    bf16 *T0h, *T0l, *T1h, *T1l, *T2h, *T2l, *Wsh, *Wsl;
    cudaGetSymbolAddress((void**)&G,   g_G);
    cudaGetSymbolAddress((void**)&Gh,  g_Gh);
    cudaGetSymbolAddress((void**)&Gl,  g_Gl);
    cudaGetSymbolAddress((void**)&cs,  g_cs);
    cudaGetSymbolAddress((void**)&h0,  g_h0);
    cudaGetSymbolAddress((void**)&h1,  g_h1);
    cudaGetSymbolAddress((void**)&di,  g_di);
    cudaGetSymbolAddress((void**)&S0h, g_S0h);
    cudaGetSymbolAddress((void**)&S0l, g_S0l);
    cudaGetSymbolAddress((void**)&S1h, g_S1h);
    cudaGetSymbolAddress((void**)&S1l, g_S1l);
    cudaGetSymbolAddress((void**)&S2h, g_S2h);
    cudaGetSymbolAddress((void**)&S2l, g_S2l);
    cudaGetSymbolAddress((void**)&T0h, g_T0h);
    cudaGetSymbolAddress((void**)&T0l, g_T0l);
    cudaGetSymbolAddress((void**)&T1h, g_T1h);
    cudaGetSymbolAddress((void**)&T1l, g_T1l);
    cudaGetSymbolAddress((void**)&T2h, g_T2h);
    cudaGetSymbolAddress((void**)&T2l, g_T2l);
    cudaGetSymbolAddress((void**)&r,   g_r);
    cudaGetSymbolAddress((void**)&z,   g_z);
    cudaGetSymbolAddress((void**)&Wsh, g_Wsh);
    cudaGetSymbolAddress((void**)&Wsl, g_Wsl);

    rownorm_k<<<NN, 256>>>(A, G);
    colsum_k<<<2, 256>>>(A, cs);
    fill_wb_k<<<NN, 256>>>(A, cs, G);
    split_G_k<<<(2*NN*NN + 255)/256, 256>>>(G, Gh, Gl);
    int g0 = (KP0*HID + 255)/256, g1 = (KP1*HID + 255)/256;
    split_W_k<<<g0, 256>>>(Wr0, 65, F0P, Wsh + OW0R, Wsl + OW0R);
    split_W_k<<<g0, 256>>>(Wz0, 65, F0P, Wsh + OW0Z, Wsl + OW0Z);
    split_W_k<<<g0, 256>>>(Wn0, 65, F0P, Wsh + OW0N, Wsl + OW0N);
    split_W_k<<<g1, 256>>>(Wr1, F1, F1,  Wsh + OW1R, Wsl + OW1R);
    split_W_k<<<g1, 256>>>(Wz1, F1, F1,  Wsh + OW1Z, Wsl + OW1Z);
    split_W_k<<<g1, 256>>>(Wn1, F1, F1,  Wsh + OW1N, Wsl + OW1N);
    zero2_k<<<(NB*HID + 255)/256, 256>>>(h0, h1, NB*HID);

    auto make_ga = [&](bf16* s0h, bf16* s0l, bf16* s1hh, bf16* s1ll,
                       bf16* s2hh, bf16* s2ll, int C,
                       bf16* t0hh, bf16* t0ll, bf16* t1hh, bf16* t1ll,
                       bf16* t2hh, bf16* t2ll, int Ch, int Fp, int split) {
        GateArgs ga;
        ga.fh[0] = s0h; ga.fl[0] = s0l;
        ga.fh[1] = s1hh; ga.fl[1] = s1ll;
        ga.fh[2] = s2hh; ga.fl[2] = s2ll;
        ga.fh[3] = s1hh + (size_t)NN*C; ga.fl[3] = s1ll + (size_t)NN*C;
        ga.fh[4] = s2hh + (size_t)NN*C; ga.fl[4] = s2ll + (size_t)NN*C;
        bf16 *th0 = t0hh ? t0hh : s0h, *tl0 = t0ll ? t0ll : s0l;
        ga.hh[0] = th0; ga.hl[0] = tl0;
        ga.hh[1] = t1hh ? t1hh : s1hh; ga.hl[1] = t1ll ? t1ll : s1ll;
        ga.hh[2] = t2hh ? t2hh : s2hh; ga.hl[2] = t2ll ? t2ll : s2ll;
        ga.hh[3] = t1hh ? t1hh + (size_t)NN*Ch : ga.fh[3];
        ga.hl[3] = t1ll ? t1ll + (size_t)NN*Ch : ga.fl[3];
        ga.hh[4] = t2hh ? t2hh + (size_t)NN*Ch : ga.fh[4];
        ga.hl[4] = t2ll ? t2ll + (size_t)NN*Ch : ga.fl[4];
        ga.Fp = Fp; ga.split = split;
        ga.W1h = nullptr; ga.W1l = nullptr; ga.b1 = nullptr; ga.Y1 = nullptr;
        ga.W2h = nullptr; ga.W2l = nullptr; ga.b2 = nullptr; ga.Y2 = nullptr;
        ga.zg = nullptr; ga.h = nullptr; ga.mode = 0;
        return ga;
    };

    auto cell0 = [&]() {
        dim3 gh(C0P/128, 8);
        int packG = (NB*F0P + 255)/256;
        // xh chain
        pack_l0<<<packG, 256>>>(di, h0, nullptr, S0h, S0l);
        hop_mma<<<gh, 256>>>(Gh, Gl, S0h, S0l, S0h, S0l, S1h, S1l, C0P);
        hop_mma<<<gh, 256>>>(Gh, Gl, S1h, S1l, S1h + (size_t)NN*C0P, S1l + (size_t)NN*C0P,
                             S2h, S2l, C0P);
        GateArgs ga = make_ga(S0h, S0l, S1h, S1l, S2h, S2l, C0P,
                              nullptr, nullptr, nullptr, nullptr, nullptr, nullptr,
                              0, F0P, F0P);
        ga.W1h = Wsh + OW0R; ga.W1l = Wsl + OW0R; ga.b1 = br0; ga.Y1 = r;
        ga.W2h = Wsh + OW0Z; ga.W2l = Wsl + OW0Z; ga.b2 = bz0; ga.Y2 = z;
        ga.mode = 0;
        gate_mma<<<dim3(NB/128, 1, 2), 128>>>(ga);
        // n chain
        pack_l0<<<packG, 256>>>(di, h0, r, S0h, S0l);
        hop_mma<<<gh, 256>>>(Gh, Gl, S0h, S0l, S0h, S0l, S1h, S1l, C0P);
        hop_mma<<<gh, 256>>>(Gh, Gl, S1h, S1l, S1h + (size_t)NN*C0P, S1l + (size_t)NN*C0P,
                             S2h, S2l, C0P);
        GateArgs gn = make_ga(S0h, S0l, S1h, S1l, S2h, S2l, C0P,
                              nullptr, nullptr, nullptr, nullptr, nullptr, nullptr,
                              0, F0P, F0P);
        gn.W1h = Wsh + OW0N; gn.W1l = Wsl + OW0N; gn.b1 = bn0;
        gn.zg = z; gn.h = h0; gn.mode = 1;
        gate_mma<<<dim3(NB/128, 1, 1), 128>>>(gn);
    };

    auto cell1 = [&]() {
        dim3 gh(C1/128, 8), ghh(CH/128, 8);
        // xh chain
        pack_l1<<<(NB*F1)/256, 256>>>(h0, h1, S0h, S0l);
        hop_mma<<<gh, 256>>>(Gh, Gl, S0h, S0l, S0h, S0l, S1h, S1l, C1);
        hop_mma<<<gh, 256>>>(Gh, Gl, S1h, S1l, S1h + (size_t)NN*C1, S1l + (size_t)NN*C1,
                             S2h, S2l, C1);
        GateArgs ga = make_ga(S0h, S0l, S1h, S1l, S2h, S2l, C1,
                              nullptr, nullptr, nullptr, nullptr, nullptr, nullptr,
                              0, F1, F1);
        ga.W1h = Wsh + OW1R; ga.W1l = Wsl + OW1R; ga.b1 = br1; ga.Y1 = r;
        ga.W2h = Wsh + OW1Z; ga.W2l = Wsl + OW1Z; ga.b2 = bz1; ga.Y2 = z;
        ga.mode = 0;
        gate_mma<<<dim3(NB/128, 1, 2), 128>>>(ga);
        // n chain: only r*h1 half needs hops; h0 half reused from xh chain
        mul_rh<<<(NB*HID)/256, 256>>>(r, h1, T0h, T0l);
        hop_mma<<<ghh, 256>>>(Gh, Gl, T0h, T0l, T0h, T0l, T1h, T1l, CH);
        hop_mma<<<ghh, 256>>>(Gh, Gl, T1h, T1l, T1h + (size_t)NN*CH, T1l + (size_t)NN*CH,
                              T2h, T2l, CH);
        GateArgs gn = make_ga(S0h, S0l, S1h, S1l, S2h, S2l, C1,
                              T0h, T0l, T1h, T1l, T2h, T2l, CH, F1, HID);
        gn.W1h = Wsh + OW1N; gn.W1l = Wsl + OW1N; gn.b1 = bn1;
        gn.zg = z; gn.h = h1; gn.mode = 1;
        gate_mma<<<dim3(NB/128, 1, 1), 128>>>(gn);
    };

    for (int t = 0; t < TIN; t++) {
        copy_xt<<<NB/256, 256>>>(x, t, di);
        cell0();
        cell1();
    }
    copy_xt<<<NB/256, 256>>>(x, TIN - 1, di);
    for (int t = 0; t < TOUT; t++) {
        cell0();
        cell1();
        proj_k<<<NB/256, 256>>>(h1, Wp, bp, out, di, t);
    }
}

// round 5
// speedup vs baseline: 2.9564x; 1.0789x over previous
#include <cuda_runtime.h>
#include <cuda_bf16.h>
#include <math.h>

// ---------------------------------------------------------------------------
// DCRNN 2-layer DCGRU. B=16, N=512, HID=64, K=2, T_in=12, T_out=12.
// All GEMMs on tensor cores (mma.sync bf16, two-term hi/lo split).
// Layer-0 feature order [h(64) | di | pad] so n-chain hops only r*h (cols
// shared with xh chain via linearity). Gate epilogues write split h directly
// into next chain buffers — no pack kernels.
// ---------------------------------------------------------------------------

#define NN   512
#define BB   16
#define HID  64
#define NB   (NN*BB)          // 8192
#define F0P  80               // padded layer0 features: [h(64) | di | pad(15)]
#define F1   128
#define C0P  (BB*F0P)         // 1280
#define C1   (BB*F1)          // 2048
#define CH   (BB*HID)         // 1024
#define TIN  12
#define TOUT 12

#define KC   32
#define APP  40               // hop A smem pitch
#define BPP  72               // hop B smem pitch (64+8)
#define GAP  24               // gate A smem pitch
#define GBP  72               // gate B smem pitch

#define KP0  (5*F0P)          // 400
#define KP1  (5*F1)           // 640

typedef __nv_bfloat16 bf16;

// ---------------- device scratch -------------------------------------------
__device__ float g_G [2*NN*NN];
__device__ bf16  g_Gh[2*NN*NN];
__device__ bf16  g_Gl[2*NN*NN];
__device__ float g_cs[NN];
__device__ float g_h0[NB*HID];
__device__ float g_h1[NB*HID];
__device__ float g_di[NB];
__device__ bf16  g_SAh[NN*C0P];      // layer0 chain input [h|di|pad]
__device__ bf16  g_SAl[NN*C0P];
__device__ bf16  g_SBh[NN*C1];       // layer1 chain input [h0|h1]
__device__ bf16  g_SBl[NN*C1];
__device__ bf16  g_S1h[2*NN*C1];
__device__ bf16  g_S1l[2*NN*C1];
__device__ bf16  g_S2h[2*NN*C1];
__device__ bf16  g_S2l[2*NN*C1];
__device__ bf16  g_T0h[NN*CH];
__device__ bf16  g_T0l[NN*CH];
__device__ bf16  g_T1h[2*NN*CH];
__device__ bf16  g_T1l[2*NN*CH];
__device__ bf16  g_T2h[2*NN*CH];
__device__ bf16  g_T2l[2*NN*CH];
__device__ float g_r [NB*HID];
__device__ float g_z [NB*HID];
#define OW0R 0
#define OW0Z (KP0*HID)
#define OW0N (2*KP0*HID)
#define OW1R (3*KP0*HID)
#define OW1Z (3*KP0*HID + KP1*HID)
#define OW1N (3*KP0*HID + 2*KP1*HID)
#define WTOT (3*KP0*HID + 3*KP1*HID)
__device__ bf16  g_Wsh[WTOT];
__device__ bf16  g_Wsl[WTOT];

// ---------------- PTX helpers ----------------------------------------------
__device__ __forceinline__ void cp16(void* dst, const void* src) {
    unsigned d = (unsigned)__cvta_generic_to_shared(dst);
    asm volatile("cp.async.ca.shared.global [%0], [%1], 16;\n" :: "r"(d), "l"(src));
}
#define CP_COMMIT() asm volatile("cp.async.commit_group;\n")
#define CP_WAIT(n)  asm volatile("cp.async.wait_group %0;\n" :: "n"(n))

__device__ __forceinline__ void ldsm4(unsigned* r, const void* p) {
    unsigned a = (unsigned)__cvta_generic_to_shared(p);
    asm volatile("ldmatrix.sync.aligned.m8n8.x4.shared.b16 {%0,%1,%2,%3}, [%4];"
                 : "=r"(r[0]), "=r"(r[1]), "=r"(r[2]), "=r"(r[3]) : "r"(a));
}
__device__ __forceinline__ void ldsm4t(unsigned* r, const void* p) {
    unsigned a = (unsigned)__cvta_generic_to_shared(p);
    asm volatile("ldmatrix.sync.aligned.m8n8.x4.trans.shared.b16 {%0,%1,%2,%3}, [%4];"
                 : "=r"(r[0]), "=r"(r[1]), "=r"(r[2]), "=r"(r[3]) : "r"(a));
}
#define MMA_BF16(d, a, b0v, b1v)                                              \
    asm("mma.sync.aligned.m16n8k16.row.col.f32.bf16.bf16.f32 "                \
        "{%0,%1,%2,%3}, {%4,%5,%6,%7}, {%8,%9}, {%0,%1,%2,%3};"               \
        : "+f"(d[0]), "+f"(d[1]), "+f"(d[2]), "+f"(d[3])                      \
        : "r"(a[0]), "r"(a[1]), "r"(a[2]), "r"(a[3]), "r"(b0v), "r"(b1v))

__device__ __forceinline__ void split_store2(bf16* Yh, bf16* Yl, size_t off, float vx, float vy) {
    bf16 h0 = __float2bfloat16(vx);
    bf16 h1 = __float2bfloat16(vy);
    bf16 l0 = __float2bfloat16(vx - __bfloat162float(h0));
    bf16 l1 = __float2bfloat16(vy - __bfloat162float(h1));
    __nv_bfloat162 hh; hh.x = h0; hh.y = h1;
    __nv_bfloat162 ll; ll.x = l0; ll.y = l1;
    *reinterpret_cast<__nv_bfloat162*>(&Yh[off]) = hh;
    *reinterpret_cast<__nv_bfloat162*>(&Yl[off]) = ll;
}
__device__ __forceinline__ void emit_split(float v, bf16* Xh, bf16* Xl, size_t idx) {
    bf16 h = __float2bfloat16(v);
    Xh[idx] = h;
    Xl[idx] = __float2bfloat16(v - __bfloat162float(h));
}

// ---------------- A -> G normalization -------------------------------------
__global__ void rownorm_k(const float* __restrict__ A, float* __restrict__ G) {
    int i = blockIdx.x;
    __shared__ float red[256];
    float s = 0.f;
    for (int j = threadIdx.x; j < NN; j += 256) s += A[i*NN + j];
    red[threadIdx.x] = s; __syncthreads();
    for (int off = 128; off; off >>= 1) {
        if (threadIdx.x < off) red[threadIdx.x] += red[threadIdx.x + off];
        __syncthreads();
    }
    float d = red[0] + 1e-6f;
    for (int j = threadIdx.x; j < NN; j += 256) G[i*NN + j] = A[i*NN + j] / d;
}
__global__ void colsum_k(const float* __restrict__ A, float* __restrict__ cs) {
    int c = blockIdx.x * blockDim.x + threadIdx.x;
    if (c < NN) {
        float s = 0.f;
        for (int r = 0; r < NN; r++) s += A[r*NN + c];
        cs[c] = s;
    }
}
__global__ void fill_wb_k(const float* __restrict__ A, const float* __restrict__ cs,
                          float* __restrict__ G) {
    int i = blockIdx.x;
    float d = cs[i] + 1e-6f;
    for (int j = threadIdx.x; j < NN; j += 256) G[(NN+i)*NN + j] = A[j*NN + i] / d;
}
__global__ void split_G_k(const float* __restrict__ G, bf16* __restrict__ Gh,
                          bf16* __restrict__ Gl) {
    int i = blockIdx.x * blockDim.x + threadIdx.x;
    if (i < 2*NN*NN) {
        float v = G[i];
        bf16 h = __float2bfloat16(v);
        Gh[i] = h;
        Gl[i] = __float2bfloat16(v - __bfloat162float(h));
    }
}
// layer0 weights: orig (5*65,64) with per-slice order [x, h(64)]
// -> padded (5*80,64) with order [h(64), x, pad(15)]
__global__ void split_W0_k(const float* __restrict__ W, bf16* __restrict__ Wh,
                           bf16* __restrict__ Wl) {
    int i = blockIdx.x * blockDim.x + threadIdx.x;
    if (i >= KP0*HID) return;
    int row = i >> 6, c = i & 63;
    int s = row / F0P, f = row - s*F0P;
    float v = 0.f;
    if (f < 64)       v = W[(size_t)(s*65 + f + 1)*HID + c];
    else if (f == 64) v = W[(size_t)(s*65)*HID + c];
    bf16 h = __float2bfloat16(v);
    Wh[i] = h;
    Wl[i] = __float2bfloat16(v - __bfloat162float(h));
}
// layer1 weights: dense (5*128,64), identity order
__global__ void split_W1_k(const float* __restrict__ W, bf16* __restrict__ Wh,
                           bf16* __restrict__ Wl) {
    int i = blockIdx.x * blockDim.x + threadIdx.x;
    if (i >= KP1*HID) return;
    float v = W[i];
    bf16 h = __float2bfloat16(v);
    Wh[i] = h;
    Wl[i] = __float2bfloat16(v - __bfloat162float(h));
}
__global__ void zero2_k(float* a, float* b, int n) {
    int i = blockIdx.x * blockDim.x + threadIdx.x;
    if (i < n) { a[i] = 0.f; b[i] = 0.f; }
}
__global__ void zero_bb_k(bf16* a, bf16* b, int n) {
    int i = blockIdx.x * blockDim.x + threadIdx.x;
    if (i < n) { a[i] = __float2bfloat16(0.f); b[i] = __float2bfloat16(0.f); }
}

// ---------------- hop GEMM: 128x64 tile, 256 thr, 2 CTAs/SM ----------------
__global__ __launch_bounds__(256, 2)
void hop_mma(const bf16* __restrict__ Gh, const bf16* __restrict__ Gl,
             const bf16* __restrict__ Xth, const bf16* __restrict__ Xtl,
             const bf16* __restrict__ Xbh, const bf16* __restrict__ Xbl,
             bf16* __restrict__ Yh, bf16* __restrict__ Yl, int C)
{
    const int m0 = blockIdx.y * 128;
    const int c0 = blockIdx.x * 64;
    const bf16* __restrict__ Xh = (m0 < NN) ? Xth : Xbh;
    const bf16* __restrict__ Xl = (m0 < NN) ? Xtl : Xbl;

    __shared__ bf16 Ash[2][128][APP];
    __shared__ bf16 Asl[2][128][APP];
    __shared__ bf16 Bsh[2][KC][BPP];
    __shared__ bf16 Bsl[2][KC][BPP];

    const int tid = threadIdx.x;
    const int wid = tid >> 5, lane = tid & 31;
    const int wm = (wid >> 1) * 32;    // 0,32,64,96
    const int wn = (wid & 1) * 32;     // 0,32
    const int g = lane >> 2, t4 = lane & 3;

    const int ar = tid >> 1, aj = (tid & 1) * 16;
    const int bk = tid >> 3, bj = (tid & 7) * 8;

    float acc[2][4][4];
    #pragma unroll
    for (int mi = 0; mi < 2; mi++)
        #pragma unroll
        for (int ni = 0; ni < 4; ni++)
            #pragma unroll
            for (int q = 0; q < 4; q++) acc[mi][ni][q] = 0.f;

    auto load_stage = [&](int buf, int k0) {
        const bf16* a1 = Gh + (size_t)(m0+ar)*NN + k0 + aj;
        const bf16* a2 = Gl + (size_t)(m0+ar)*NN + k0 + aj;
        cp16(&Ash[buf][ar][aj],   a1);
        cp16(&Ash[buf][ar][aj+8], a1+8);
        cp16(&Asl[buf][ar][aj],   a2);
        cp16(&Asl[buf][ar][aj+8], a2+8);
        const bf16* b1 = Xh + (size_t)(k0+bk)*C + c0 + bj;
        const bf16* b2 = Xl + (size_t)(k0+bk)*C + c0 + bj;
        cp16(&Bsh[buf][bk][bj], b1);
        cp16(&Bsl[buf][bk][bj], b2);
    };

    load_stage(0, 0);
    CP_COMMIT();

    const int NIT = NN / KC;
    for (int it = 0; it < NIT; it++) {
        int buf = it & 1;
        if (it + 1 < NIT) { load_stage(buf ^ 1, (it+1)*KC); CP_COMMIT(); CP_WAIT(1); }
        else              { CP_WAIT(0); }
        __syncthreads();

        #pragma unroll
        for (int kk = 0; kk < KC; kk += 16) {
            const int arow = lane & 15;
            const int acol = kk + ((lane >> 4) << 3);
            unsigned ah[2][4], al[2][4];
            #pragma unroll
            for (int mi = 0; mi < 2; mi++) {
                ldsm4(ah[mi], &Ash[buf][wm + mi*16 + arow][acol]);
                ldsm4(al[mi], &Asl[buf][wm + mi*16 + arow][acol]);
            }
            const int brow = kk + (lane & 15);
            #pragma unroll
            for (int np = 0; np < 2; np++) {
                const int bcol = wn + np*16 + ((lane >> 4) << 3);
                unsigned bh[4], blo[4];
                ldsm4t(bh,  &Bsh[buf][brow][bcol]);
                ldsm4t(blo, &Bsl[buf][brow][bcol]);
                #pragma unroll
                for (int h2 = 0; h2 < 2; h2++) {
                    int ni = np*2 + h2;
                    #pragma unroll
                    for (int mi = 0; mi < 2; mi++) {
                        MMA_BF16(acc[mi][ni], ah[mi], bh[h2*2],  bh[h2*2+1]);
                        MMA_BF16(acc[mi][ni], al[mi], bh[h2*2],  bh[h2*2+1]);
                        MMA_BF16(acc[mi][ni], ah[mi], blo[h2*2], blo[h2*2+1]);
                    }
                }
            }
        }
        __syncthreads();
    }

    #pragma unroll
    for (int mi = 0; mi < 2; mi++) {
        #pragma unroll
        for (int ni = 0; ni < 4; ni++) {
            int ncol = c0 + wn + ni*8 + t4*2;
            int m1 = m0 + wm + mi*16 + g;
            size_t o1 = (size_t)m1*C + ncol;
            size_t o2 = (size_t)(m1+8)*C + ncol;
            split_store2(Yh, Yl, o1, acc[mi][ni][0], acc[mi][ni][1]);
            split_store2(Yh, Yl, o2, acc[mi][ni][2], acc[mi][ni][3]);
        }
    }
}

// ---------------- gate GEMM with generalized two-source slices -------------
struct GateArgs {
    const bf16 *Ah[5], *Al[5];        // features f < split
    const bf16 *Bh[5], *Bl[5];        // features f >= split (index f-split)
    int strideA, strideB, split, Fp;
    const bf16 *W1h, *W1l; const float* b1; float* Y1;
    const bf16 *W2h, *W2l; const float* b2; float* Y2;
    const float* zg; float* h;
    bf16 *e1h, *e1l; int e1s, e1o;    // optional split dests (mode1)
    bf16 *e2h, *e2l; int e2s, e2o;
    int mode;                          // 0 sigmoid->Y ; 1 tanh + h update
};

__global__ __launch_bounds__(128, 4)
void gate_mma(GateArgs a)
{
    const bf16* Wh = (a.mode == 0 && blockIdx.z) ? a.W2h : a.W1h;
    const bf16* Wl = (a.mode == 0 && blockIdx.z) ? a.W2l : a.W1l;
    const float* bl = (a.mode == 0 && blockIdx.z) ? a.b2 : a.b1;
    float* Yl = (a.mode == 0 && blockIdx.z) ? a.Y2 : a.Y1;

    const int m0 = blockIdx.x * 128;
    const int tid = threadIdx.x;
    const int wid = tid >> 5, lane = tid & 31;
    const int g = lane >> 2, t4 = lane & 3;
    const int CPS = a.Fp >> 4;

    __shared__ bf16 Ash[2][128][GAP];
    __shared__ bf16 Asl[2][128][GAP];
    __shared__ bf16 Bsh[2][16][GBP];
    __shared__ bf16 Bsl[2][16][GBP];

    float acc[2][8][4];
    #pragma unroll
    for (int mi = 0; mi < 2; mi++)
        #pragma unroll
        for (int ni = 0; ni < 8; ni++)
            #pragma unroll
            for (int q = 0; q < 4; q++) acc[mi][ni][q] = 0.f;

    const int bkr = tid >> 3, bjc = (tid & 7) * 8;

    auto load_stage = [&](int buf, int kidx) {
        int s  = kidx / CPS;
        int fb = (kidx - s*CPS) * 16;
        #pragma unroll
        for (int j = 0; j < 2; j++) {
            int f0 = fb + j*8;
            const bf16 *sh, *sl;
            if (f0 < a.split) { sh = a.Ah[s] + (size_t)(m0+tid)*a.strideA + f0;
                                sl = a.Al[s] + (size_t)(m0+tid)*a.strideA + f0; }
            else              { sh = a.Bh[s] + (size_t)(m0+tid)*a.strideB + (f0 - a.split);
                                sl = a.Bl[s] + (size_t)(m0+tid)*a.strideB + (f0 - a.split); }
            cp16(&Ash[buf][tid][j*8], sh);
            cp16(&Asl[buf][tid][j*8], sl);
        }
        int gk = kidx*16 + bkr;
        cp16(&Bsh[buf][bkr][bjc], Wh + (size_t)gk*HID + bjc);
        cp16(&Bsl[buf][bkr][bjc], Wl + (size_t)gk*HID + bjc);
    };

    load_stage(0, 0);
    CP_COMMIT();

    const int NIT = 5 * CPS;
    for (int it = 0; it < NIT; it++) {
        int buf = it & 1;
        if (it + 1 < NIT) { load_stage(buf ^ 1, it+1); CP_COMMIT(); CP_WAIT(1); }
        else              { CP_WAIT(0); }
        __syncthreads();

        const int arow = lane & 15;
        const int acol = (lane >> 4) << 3;
        unsigned ah[2][4], al[2][4];
        #pragma unroll
        for (int mi = 0; mi < 2; mi++) {
            ldsm4(ah[mi], &Ash[buf][wid*32 + mi*16 + arow][acol]);
            ldsm4(al[mi], &Asl[buf][wid*32 + mi*16 + arow][acol]);
        }
        const int brow = lane & 15;
        #pragma unroll
        for (int np = 0; np < 4; np++) {
            const int bcol = np*16 + ((lane >> 4) << 3);
            unsigned bh[4], blo[4];
            ldsm4t(bh,  &Bsh[buf][brow][bcol]);
            ldsm4t(blo, &Bsl[buf][brow][bcol]);
            #pragma unroll
            for (int h2 = 0; h2 < 2; h2++) {
                int ni = np*2 + h2;
                #pragma unroll
                for (int mi = 0; mi < 2; mi++) {
                    MMA_BF16(acc[mi][ni], ah[mi], bh[h2*2],  bh[h2*2+1]);
                    MMA_BF16(acc[mi][ni], al[mi], bh[h2*2],  bh[h2*2+1]);
                    MMA_BF16(acc[mi][ni], ah[mi], blo[h2*2], blo[h2*2+1]);
                }
            }
        }
        __syncthreads();
    }

    #pragma unroll
    for (int mi = 0; mi < 2; mi++) {
        #pragma unroll
        for (int ni = 0; ni < 8; ni++) {
            int n = ni*8 + t4*2;
            float b0 = bl[n], b1v = bl[n+1];
            #pragma unroll
            for (int half = 0; half < 2; half++) {
                int m = m0 + wid*32 + mi*16 + g + half*8;
                float vx = acc[mi][ni][half*2]   + b0;
                float vy = acc[mi][ni][half*2+1] + b1v;
                size_t off = (size_t)m*HID + n;
                if (a.mode == 0) {
                    float2 o;
                    o.x = 1.f / (1.f + expf(-vx));
                    o.y = 1.f / (1.f + expf(-vy));
                    *reinterpret_cast<float2*>(&Yl[off]) = o;
                } else {
                    float2 zz = *reinterpret_cast<const float2*>(&a.zg[off]);
                    float2 hh = *reinterpret_cast<float2*>(&a.h[off]);
                    float2 o;
                    o.x = (1.f - zz.x) * hh.x + zz.x * tanhf(vx);
                    o.y = (1.f - zz.y) * hh.y + zz.y * tanhf(vy);
                    *reinterpret_cast<float2*>(&a.h[off]) = o;
                    if (a.e1h) split_store2(a.e1h, a.e1l, (size_t)m*a.e1s + a.e1o + n, o.x, o.y);
                    if (a.e2h) split_store2(a.e2h, a.e2l, (size_t)m*a.e2s + a.e2o + n, o.x, o.y);
                }
            }
        }
    }
}

// ---------------- small kernels --------------------------------------------
__global__ void mul_rh(const float* __restrict__ r, const float* __restrict__ h,
                       bf16* __restrict__ oh, bf16* __restrict__ ol)
{
    int i = blockIdx.x * blockDim.x + threadIdx.x;
    if (i < NB*HID) emit_split(r[i] * h[i], oh, ol, i);
}
__global__ void copy_xt(const float* __restrict__ x, int t, float* __restrict__ di,
                        bf16* __restrict__ SAh, bf16* __restrict__ SAl)
{
    int idx = blockIdx.x * blockDim.x + threadIdx.x;
    if (idx >= NB) return;
    int b = idx >> 9, n = idx & 511;
    float v = x[b*(TIN*NN) + t*NN + n];
    int m = n*BB + b;
    di[m] = v;
    emit_split(v, SAh, SAl, (size_t)m*F0P + 64);
}
__global__ void proj_k(const float* __restrict__ h1, const float* __restrict__ Wp,
                       const float* __restrict__ bp, float* __restrict__ out,
                       float* __restrict__ di, bf16* __restrict__ SAh,
                       bf16* __restrict__ SAl, int t)
{
    int m = blockIdx.x * blockDim.x + threadIdx.x;
    if (m >= NB) return;
    float s = bp[0];
    #pragma unroll
    for (int f = 0; f < HID; f++) s += h1[m*HID + f] * Wp[f];
    int n = m >> 4, b = m & 15;
    out[b*(TOUT*NN) + t*NN + n] = s;
    di[m] = s;
    emit_split(s, SAh, SAl, (size_t)m*F0P + 64);
}

// ---------------- host driver ----------------------------------------------
extern "C" void kernel_launch(void* const* d_in, const int* in_sizes, int n_in,
                              void* d_out, int out_size)
{
    const float* x   = (const float*)d_in[0];
    const float* A   = (const float*)d_in[1];
    const float* Wr0 = (const float*)d_in[2];
    const float* br0 = (const float*)d_in[3];
    const float* Wz0 = (const float*)d_in[4];
    const float* bz0 = (const float*)d_in[5];
    const float* Wn0 = (const float*)d_in[6];
    const float* bn0 = (const float*)d_in[7];
    const float* Wr1 = (const float*)d_in[8];
    const float* br1 = (const float*)d_in[9];
    const float* Wz1 = (const float*)d_in[10];
    const float* bz1 = (const float*)d_in[11];
    const float* Wn1 = (const float*)d_in[12];
    const float* bn1 = (const float*)d_in[13];
    const float* Wp  = (const float*)d_in[14];
    const float* bp  = (const float*)d_in[15];
    float* out = (float*)d_out;

    float *G, *cs, *h0, *h1, *di, *r, *z;
    bf16 *Gh, *Gl, *SAh, *SAl, *SBh, *SBl, *S1h, *S1l, *S2h, *S2l;
    bf16 *T0h, *T0l, *T1h, *T1l, *T2h, *T2l, *Wsh, *Wsl;
    cudaGetSymbolAddress((void**)&G,   g_G);
    cudaGetSymbolAddress((void**)&Gh,  g_Gh);
    cudaGetSymbolAddress((void**)&Gl,  g_Gl);
    cudaGetSymbolAddress((void**)&cs,  g_cs);
    cudaGetSymbolAddress((void**)&h0,  g_h0);
    cudaGetSymbolAddress((void**)&h1,  g_h1);
    cudaGetSymbolAddress((void**)&di,  g_di);
    cudaGetSymbolAddress((void**)&SAh, g_SAh);
    cudaGetSymbolAddress((void**)&SAl, g_SAl);
    cudaGetSymbolAddress((void**)&SBh, g_SBh);
    cudaGetSymbolAddress((void**)&SBl, g_SBl);
    cudaGetSymbolAddress((void**)&S1h, g_S1h);
    cudaGetSymbolAddress((void**)&S1l, g_S1l);
    cudaGetSymbolAddress((void**)&S2h, g_S2h);
    cudaGetSymbolAddress((void**)&S2l, g_S2l);
    cudaGetSymbolAddress((void**)&T0h, g_T0h);
    cudaGetSymbolAddress((void**)&T0l, g_T0l);
    cudaGetSymbolAddress((void**)&T1h, g_T1h);
    cudaGetSymbolAddress((void**)&T1l, g_T1l);
    cudaGetSymbolAddress((void**)&T2h, g_T2h);
    cudaGetSymbolAddress((void**)&T2l, g_T2l);
    cudaGetSymbolAddress((void**)&r,   g_r);
    cudaGetSymbolAddress((void**)&z,   g_z);
    cudaGetSymbolAddress((void**)&Wsh, g_Wsh);
    cudaGetSymbolAddress((void**)&Wsl, g_Wsl);

    rownorm_k<<<NN, 256>>>(A, G);
    colsum_k<<<2, 256>>>(A, cs);
    fill_wb_k<<<NN, 256>>>(A, cs, G);
    split_G_k<<<(2*NN*NN + 255)/256, 256>>>(G, Gh, Gl);
    int g0 = (KP0*HID + 255)/256, g1 = (KP1*HID + 255)/256;
    split_W0_k<<<g0, 256>>>(Wr0, Wsh + OW0R, Wsl + OW0R);
    split_W0_k<<<g0, 256>>>(Wz0, Wsh + OW0Z, Wsl + OW0Z);
    split_W0_k<<<g0, 256>>>(Wn0, Wsh + OW0N, Wsl + OW0N);
    split_W1_k<<<g1, 256>>>(Wr1, Wsh + OW1R, Wsl + OW1R);
    split_W1_k<<<g1, 256>>>(Wz1, Wsh + OW1Z, Wsl + OW1Z);
    split_W1_k<<<g1, 256>>>(Wn1, Wsh + OW1N, Wsl + OW1N);
    zero2_k<<<(NB*HID + 255)/256, 256>>>(h0, h1, NB*HID);
    zero_bb_k<<<(NN*C0P + 255)/256, 256>>>(SAh, SAl, NN*C0P);
    zero_bb_k<<<(NN*C1 + 255)/256, 256>>>(SBh, SBl, NN*C1);

    auto cell0 = [&]() {
        dim3 ghS(C0P/64, 8), ghT(CH/64, 8);
        // xh chain over [h0 | di | pad]
        hop_mma<<<ghS, 256>>>(Gh, Gl, SAh, SAl, SAh, SAl, S1h, S1l, C0P);
        hop_mma<<<ghS, 256>>>(Gh, Gl, S1h, S1l, S1h + (size_t)NN*C0P, S1l + (size_t)NN*C0P,
                              S2h, S2l, C0P);
        // r, z gates: all features from S chain (stride 80)
        GateArgs ga = {};
        ga.Ah[0]=SAh; ga.Al[0]=SAl;
        ga.Ah[1]=S1h; ga.Al[1]=S1l;
        ga.Ah[2]=S2h; ga.Al[2]=S2l;
        ga.Ah[3]=S1h+(size_t)NN*C0P; ga.Al[3]=S1l+(size_t)NN*C0P;
        ga.Ah[4]=S2h+(size_t)NN*C0P; ga.Al[4]=S2l+(size_t)NN*C0P;
        for (int s=0;s<5;s++){ ga.Bh[s]=ga.Ah[s]; ga.Bl[s]=ga.Al[s]; }
        ga.strideA = F0P; ga.strideB = F0P; ga.split = F0P; ga.Fp = F0P;
        ga.W1h = Wsh+OW0R; ga.W1l = Wsl+OW0R; ga.b1 = br0; ga.Y1 = r;
        ga.W2h = Wsh+OW0Z; ga.W2l = Wsl+OW0Z; ga.b2 = bz0; ga.Y2 = z;
        ga.mode = 0;
        gate_mma<<<dim3(NB/128, 1, 2), 128>>>(ga);
        // n chain: hop only r*h0 (di/pad cols reused from S chain)
        mul_rh<<<(NB*HID)/256, 256>>>(r, h0, T0h, T0l);
        hop_mma<<<ghT, 256>>>(Gh, Gl, T0h, T0l, T0h, T0l, T1h, T1l, CH);
        hop_mma<<<ghT, 256>>>(Gh, Gl, T1h, T1l, T1h + (size_t)NN*CH, T1l + (size_t)NN*CH,
                              T2h, T2l, CH);
        GateArgs gn = {};
        gn.Ah[0]=T0h; gn.Al[0]=T0l;
        gn.Ah[1]=T1h; gn.Al[1]=T1l;
        gn.Ah[2]=T2h; gn.Al[2]=T2l;
        gn.Ah[3]=T1h+(size_t)NN*CH; gn.Al[3]=T1l+(size_t)NN*CH;
        gn.Ah[4]=T2h+(size_t)NN*CH; gn.Al[4]=T2l+(size_t)NN*CH;
        gn.Bh[0]=SAh+64; gn.Bl[0]=SAl+64;
        gn.Bh[1]=S1h+64; gn.Bl[1]=S1l+64;
        gn.Bh[2]=S2h+64; gn.Bl[2]=S2l+64;
        gn.Bh[3]=S1h+(size_t)NN*C0P+64; gn.Bl[3]=S1l+(size_t)NN*C0P+64;
        gn.Bh[4]=S2h+(size_t)NN*C0P+64; gn.Bl[4]=S2l+(size_t)NN*C0P+64;
        gn.strideA = HID; gn.strideB = F0P; gn.split = HID; gn.Fp = F0P;
        gn.W1h = Wsh+OW0N; gn.W1l = Wsl+OW0N; gn.b1 = bn0;
        gn.zg = z; gn.h = h0;
        gn.e1h = SAh; gn.e1l = SAl; gn.e1s = F0P; gn.e1o = 0;
        gn.e2h = SBh; gn.e2l = SBl; gn.e2s = F1;  gn.e2o = 0;
        gn.mode = 1;
        gate_mma<<<dim3(NB/128, 1, 1), 128>>>(gn);
    };

    auto cell1 = [&]() {
        dim3 ghS(C1/64, 8), ghT(CH/64, 8);
        hop_mma<<<ghS, 256>>>(Gh, Gl, SBh, SBl, SBh, SBl, S1h, S1l, C1);
        hop_mma<<<ghS, 256>>>(Gh, Gl, S1h, S1l, S1h + (size_t)NN*C1, S1l + (size_t)NN*C1,
                              S2h, S2l, C1);
        GateArgs ga = {};
        ga.Ah[0]=SBh; ga.Al[0]=SBl;
        ga.Ah[1]=S1h; ga.Al[1]=S1l;
        ga.Ah[2]=S2h; ga.Al[2]=S2l;
        ga.Ah[3]=S1h+(size_t)NN*C1; ga.Al[3]=S1l+(size_t)NN*C1;
        ga.Ah[4]=S2h+(size_t)NN*C1; ga.Al[4]=S2l+(size_t)NN*C1;
        for (int s=0;s<5;s++){ ga.Bh[s]=ga.Ah[s]; ga.Bl[s]=ga.Al[s]; }
        ga.strideA = F1; ga.strideB = F1; ga.split = F1; ga.Fp = F1;
        ga.W1h = Wsh+OW1R; ga.W1l = Wsl+OW1R; ga.b1 = br1; ga.Y1 = r;
        ga.W2h = Wsh+OW1Z; ga.W2l = Wsl+OW1Z; ga.b2 = bz1; ga.Y2 = z;
        ga.mode = 0;
        gate_mma<<<dim3(NB/128, 1, 2), 128>>>(ga);
        // n chain: only r*h1 half hops; h0 half reused from S chain
        mul_rh<<<(NB*HID)/256, 256>>>(r, h1, T0h, T0l);
        hop_mma<<<ghT, 256>>>(Gh, Gl, T0h, T0l, T0h, T0l, T1h, T1l, CH);
        hop_mma<<<ghT, 256>>>(Gh, Gl, T1h, T1l, T1h + (size_t)NN*CH, T1l + (size_t)NN*CH,
                              T2h, T2l, CH);
        GateArgs gn = {};
        gn.Ah[0]=SBh; gn.Al[0]=SBl;
        gn.Ah[1]=S1h; gn.Al[1]=S1l;
        gn.Ah[2]=S2h; gn.Al[2]=S2l;
        gn.Ah[3]=S1h+(size_t)NN*C1; gn.Al[3]=S1l+(size_t)NN*C1;
        gn.Ah[4]=S2h+(size_t)NN*C1; gn.Al[4]=S2l+(size_t)NN*C1;
        gn.Bh[0]=T0h; gn.Bl[0]=T0l;
        gn.Bh[1]=T1h; gn.Bl[1]=T1l;
        gn.Bh[2]=T2h; gn.Bl[2]=T2l;
        gn.Bh[3]=T1h+(size_t)NN*CH; gn.Bl[3]=T1l+(size_t)NN*CH;
        gn.Bh[4]=T2h+(size_t)NN*CH; gn.Bl[4]=T2l+(size_t)NN*CH;
        gn.strideA = F1; gn.strideB = HID; gn.split = HID; gn.Fp = F1;
        gn.W1h = Wsh+OW1N; gn.W1l = Wsl+OW1N; gn.b1 = bn1;
        gn.zg = z; gn.h = h1;
        gn.e1h = SBh; gn.e1l = SBl; gn.e1s = F1; gn.e1o = HID;
        gn.mode = 1;
        gate_mma<<<dim3(NB/128, 1, 1), 128>>>(gn);
    };

    for (int t = 0; t < TIN; t++) {
        copy_xt<<<NB/256, 256>>>(x, t, di, SAh, SAl);
        cell0();
        cell1();
    }
    copy_xt<<<NB/256, 256>>>(x, TIN - 1, di, SAh, SAl);
    for (int t = 0; t < TOUT; t++) {
        cell0();
        cell1();
        proj_k<<<NB/256, 256>>>(h1, Wp, bp, out, di, SAh, SAl, t);
    }
}

// round 6
// speedup vs baseline: 3.1220x; 1.0560x over previous
#include <cuda_runtime.h>
#include <cuda_bf16.h>
#include <math.h>

// ---------------------------------------------------------------------------
// DCRNN 2-layer DCGRU. B=16, N=512, HID=64, K=2, T_in=12, T_out=12.
// Critical-path minimized: G4 = [Wf; Wb; Wf^2; Wb^2] precomputed once so each
// diffusion chain is ONE stacked GEMM Y(2048,C) = G4 @ X on tensor cores
// (mma.sync bf16, two-term hi/lo split). mul_rh fused into r-gate epilogue.
// 9 dependent launches per timestep.
// ---------------------------------------------------------------------------

#define NN   512
#define BB   16
#define HID  64
#define NB   (NN*BB)          // 8192
#define F0P  80               // layer0 features: [h(64) | di | pad(15)]
#define F1   128
#define C0P  (BB*F0P)         // 1280
#define C1   (BB*F1)          // 2048
#define CH   (BB*HID)         // 1024
#define TIN  12
#define TOUT 12

#define KC   32
#define APP  40               // hop A smem pitch
#define BPP  72               // hop B smem pitch
#define GAP  24               // gate A smem pitch
#define GBP  72               // gate B smem pitch

#define KP0  (5*F0P)          // 400
#define KP1  (5*F1)           // 640

typedef __nv_bfloat16 bf16;

// ---------------- device scratch -------------------------------------------
__device__ float g_G [4*NN*NN];      // rows: [Wf; Wb; Wf^2; Wb^2] (2048 x 512)
__device__ bf16  g_Gh[4*NN*NN];
__device__ bf16  g_Gl[4*NN*NN];
__device__ float g_cs[NN];
__device__ float g_h0[NB*HID];
__device__ float g_h1[NB*HID];
__device__ float g_di[NB];
__device__ bf16  g_SAh[NN*C0P];      // layer0 chain input [h0|di|pad]
__device__ bf16  g_SAl[NN*C0P];
__device__ bf16  g_SBh[NN*C1];       // layer1 chain input [h0|h1]
__device__ bf16  g_SBl[NN*C1];
__device__ bf16  g_S12h[4*NN*C1];    // stacked hop outputs (4 blocks)
__device__ bf16  g_S12l[4*NN*C1];
__device__ bf16  g_T0h[NN*CH];       // r*h
__device__ bf16  g_T0l[NN*CH];
__device__ bf16  g_T12h[4*NN*CH];
__device__ bf16  g_T12l[4*NN*CH];
__device__ float g_r [NB*HID];
__device__ float g_z [NB*HID];
#define OW0R 0
#define OW0Z (KP0*HID)
#define OW0N (2*KP0*HID)
#define OW1R (3*KP0*HID)
#define OW1Z (3*KP0*HID + KP1*HID)
#define OW1N (3*KP0*HID + 2*KP1*HID)
#define WTOT (3*KP0*HID + 3*KP1*HID)
__device__ bf16  g_Wsh[WTOT];
__device__ bf16  g_Wsl[WTOT];

// ---------------- PTX helpers ----------------------------------------------
__device__ __forceinline__ void cp16(void* dst, const void* src) {
    unsigned d = (unsigned)__cvta_generic_to_shared(dst);
    asm volatile("cp.async.ca.shared.global [%0], [%1], 16;\n" :: "r"(d), "l"(src));
}
#define CP_COMMIT() asm volatile("cp.async.commit_group;\n")
#define CP_WAIT(n)  asm volatile("cp.async.wait_group %0;\n" :: "n"(n))

__device__ __forceinline__ void ldsm4(unsigned* r, const void* p) {
    unsigned a = (unsigned)__cvta_generic_to_shared(p);
    asm volatile("ldmatrix.sync.aligned.m8n8.x4.shared.b16 {%0,%1,%2,%3}, [%4];"
                 : "=r"(r[0]), "=r"(r[1]), "=r"(r[2]), "=r"(r[3]) : "r"(a));
}
__device__ __forceinline__ void ldsm4t(unsigned* r, const void* p) {
    unsigned a = (unsigned)__cvta_generic_to_shared(p);
    asm volatile("ldmatrix.sync.aligned.m8n8.x4.trans.shared.b16 {%0,%1,%2,%3}, [%4];"
                 : "=r"(r[0]), "=r"(r[1]), "=r"(r[2]), "=r"(r[3]) : "r"(a));
}
#define MMA_BF16(d, a, b0v, b1v)                                              \
    asm("mma.sync.aligned.m16n8k16.row.col.f32.bf16.bf16.f32 "                \
        "{%0,%1,%2,%3}, {%4,%5,%6,%7}, {%8,%9}, {%0,%1,%2,%3};"               \
        : "+f"(d[0]), "+f"(d[1]), "+f"(d[2]), "+f"(d[3])                      \
        : "r"(a[0]), "r"(a[1]), "r"(a[2]), "r"(a[3]), "r"(b0v), "r"(b1v))

__device__ __forceinline__ void split_store2(bf16* Yh, bf16* Yl, size_t off, float vx, float vy) {
    bf16 h0 = __float2bfloat16(vx);
    bf16 h1 = __float2bfloat16(vy);
    bf16 l0 = __float2bfloat16(vx - __bfloat162float(h0));
    bf16 l1 = __float2bfloat16(vy - __bfloat162float(h1));
    __nv_bfloat162 hh; hh.x = h0; hh.y = h1;
    __nv_bfloat162 ll; ll.x = l0; ll.y = l1;
    *reinterpret_cast<__nv_bfloat162*>(&Yh[off]) = hh;
    *reinterpret_cast<__nv_bfloat162*>(&Yl[off]) = ll;
}
__device__ __forceinline__ void emit_split(float v, bf16* Xh, bf16* Xl, size_t idx) {
    bf16 h = __float2bfloat16(v);
    Xh[idx] = h;
    Xl[idx] = __float2bfloat16(v - __bfloat162float(h));
}

// ---------------- A -> G normalization + squares ---------------------------
__global__ void rownorm_k(const float* __restrict__ A, float* __restrict__ G) {
    int i = blockIdx.x;
    __shared__ float red[256];
    float s = 0.f;
    for (int j = threadIdx.x; j < NN; j += 256) s += A[i*NN + j];
    red[threadIdx.x] = s; __syncthreads();
    for (int off = 128; off; off >>= 1) {
        if (threadIdx.x < off) red[threadIdx.x] += red[threadIdx.x + off];
        __syncthreads();
    }
    float d = red[0] + 1e-6f;
    for (int j = threadIdx.x; j < NN; j += 256) G[i*NN + j] = A[i*NN + j] / d;
}
__global__ void colsum_k(const float* __restrict__ A, float* __restrict__ cs) {
    int c = blockIdx.x * blockDim.x + threadIdx.x;
    if (c < NN) {
        float s = 0.f;
        for (int r = 0; r < NN; r++) s += A[r*NN + c];
        cs[c] = s;
    }
}
__global__ void fill_wb_k(const float* __restrict__ A, const float* __restrict__ cs,
                          float* __restrict__ G) {
    int i = blockIdx.x;
    float d = cs[i] + 1e-6f;
    for (int j = threadIdx.x; j < NN; j += 256) G[(NN+i)*NN + j] = A[j*NN + i] / d;
}
// Out_block(2+z) = G_block(z)^2  (fp32, 64x64 tiles)
__global__ void square_k(const float* __restrict__ G, float* __restrict__ Out) {
    const float* Am = G + (size_t)blockIdx.z*NN*NN;
    float* Cm = Out + (size_t)(2 + blockIdx.z)*NN*NN;
    const int m0 = blockIdx.y * 64, n0 = blockIdx.x * 64;
    const int tid = threadIdx.x;
    const int tx = tid & 15, ty = tid >> 4;
    __shared__ float As[16][64];
    __shared__ float Bs[16][64];
    float acc[4][4];
    #pragma unroll
    for (int i = 0; i < 4; i++)
        #pragma unroll
        for (int j = 0; j < 4; j++) acc[i][j] = 0.f;
    for (int k0 = 0; k0 < NN; k0 += 16) {
        {
            int m = tid >> 2, k4 = (tid & 3) * 4;
            float4 w = *reinterpret_cast<const float4*>(&Am[(size_t)(m0+m)*NN + k0 + k4]);
            As[k4+0][m] = w.x; As[k4+1][m] = w.y; As[k4+2][m] = w.z; As[k4+3][m] = w.w;
        }
        {
            int k = tid >> 4, c4 = (tid & 15) * 4;
            float4 v = *reinterpret_cast<const float4*>(&Am[(size_t)(k0+k)*NN + n0 + c4]);
            *reinterpret_cast<float4*>(&Bs[k][c4]) = v;
        }
        __syncthreads();
        #pragma unroll
        for (int k = 0; k < 16; k++) {
            float a[4], b[4];
            #pragma unroll
            for (int i = 0; i < 4; i++) a[i] = As[k][ty + 16*i];
            #pragma unroll
            for (int j = 0; j < 4; j++) b[j] = Bs[k][tx + 16*j];
            #pragma unroll
            for (int i = 0; i < 4; i++)
                #pragma unroll
                for (int j = 0; j < 4; j++) acc[i][j] += a[i] * b[j];
        }
        __syncthreads();
    }
    #pragma unroll
    for (int i = 0; i < 4; i++)
        #pragma unroll
        for (int j = 0; j < 4; j++)
            Cm[(size_t)(m0 + ty + 16*i)*NN + n0 + tx + 16*j] = acc[i][j];
}
__global__ void split_G_k(const float* __restrict__ G, bf16* __restrict__ Gh,
                          bf16* __restrict__ Gl) {
    int i = blockIdx.x * blockDim.x + threadIdx.x;
    if (i < 4*NN*NN) {
        float v = G[i];
        bf16 h = __float2bfloat16(v);
        Gh[i] = h;
        Gl[i] = __float2bfloat16(v - __bfloat162float(h));
    }
}
__global__ void split_W0_k(const float* __restrict__ W, bf16* __restrict__ Wh,
                           bf16* __restrict__ Wl) {
    int i = blockIdx.x * blockDim.x + threadIdx.x;
    if (i >= KP0*HID) return;
    int row = i >> 6, c = i & 63;
    int s = row / F0P, f = row - s*F0P;
    float v = 0.f;
    if (f < 64)       v = W[(size_t)(s*65 + f + 1)*HID + c];
    else if (f == 64) v = W[(size_t)(s*65)*HID + c];
    bf16 h = __float2bfloat16(v);
    Wh[i] = h;
    Wl[i] = __float2bfloat16(v - __bfloat162float(h));
}
__global__ void split_W1_k(const float* __restrict__ W, bf16* __restrict__ Wh,
                           bf16* __restrict__ Wl) {
    int i = blockIdx.x * blockDim.x + threadIdx.x;
    if (i >= KP1*HID) return;
    float v = W[i];
    bf16 h = __float2bfloat16(v);
    Wh[i] = h;
    Wl[i] = __float2bfloat16(v - __bfloat162float(h));
}
__global__ void zero2_k(float* a, float* b, int n) {
    int i = blockIdx.x * blockDim.x + threadIdx.x;
    if (i < n) { a[i] = 0.f; b[i] = 0.f; }
}
__global__ void zero_bb_k(bf16* a, bf16* b, int n) {
    int i = blockIdx.x * blockDim.x + threadIdx.x;
    if (i < n) { a[i] = __float2bfloat16(0.f); b[i] = __float2bfloat16(0.f); }
}

// ---------------- stacked hop GEMM: Y(2048,C) = G4 @ X ---------------------
__global__ __launch_bounds__(256, 2)
void hop4_mma(const bf16* __restrict__ Gh, const bf16* __restrict__ Gl,
              const bf16* __restrict__ Xh, const bf16* __restrict__ Xl,
              bf16* __restrict__ Yh, bf16* __restrict__ Yl, int C)
{
    const int m0 = blockIdx.y * 128;   // 0..1920
    const int c0 = blockIdx.x * 64;

    __shared__ bf16 Ash[2][128][APP];
    __shared__ bf16 Asl[2][128][APP];
    __shared__ bf16 Bsh[2][KC][BPP];
    __shared__ bf16 Bsl[2][KC][BPP];

    const int tid = threadIdx.x;
    const int wid = tid >> 5, lane = tid & 31;
    const int wm = (wid >> 1) * 32;
    const int wn = (wid & 1) * 32;
    const int g = lane >> 2, t4 = lane & 3;

    const int ar = tid >> 1, aj = (tid & 1) * 16;
    const int bk = tid >> 3, bj = (tid & 7) * 8;

    float acc[2][4][4];
    #pragma unroll
    for (int mi = 0; mi < 2; mi++)
        #pragma unroll
        for (int ni = 0; ni < 4; ni++)
            #pragma unroll
            for (int q = 0; q < 4; q++) acc[mi][ni][q] = 0.f;

    auto load_stage = [&](int buf, int k0) {
        const bf16* a1 = Gh + (size_t)(m0+ar)*NN + k0 + aj;
        const bf16* a2 = Gl + (size_t)(m0+ar)*NN + k0 + aj;
        cp16(&Ash[buf][ar][aj],   a1);
        cp16(&Ash[buf][ar][aj+8], a1+8);
        cp16(&Asl[buf][ar][aj],   a2);
        cp16(&Asl[buf][ar][aj+8], a2+8);
        const bf16* b1 = Xh + (size_t)(k0+bk)*C + c0 + bj;
        const bf16* b2 = Xl + (size_t)(k0+bk)*C + c0 + bj;
        cp16(&Bsh[buf][bk][bj], b1);
        cp16(&Bsl[buf][bk][bj], b2);
    };

    load_stage(0, 0);
    CP_COMMIT();

    const int NIT = NN / KC;
    for (int it = 0; it < NIT; it++) {
        int buf = it & 1;
        if (it + 1 < NIT) { load_stage(buf ^ 1, (it+1)*KC); CP_COMMIT(); CP_WAIT(1); }
        else              { CP_WAIT(0); }
        __syncthreads();

        #pragma unroll
        for (int kk = 0; kk < KC; kk += 16) {
            const int arow = lane & 15;
            const int acol = kk + ((lane >> 4) << 3);
            unsigned ah[2][4], al[2][4];
            #pragma unroll
            for (int mi = 0; mi < 2; mi++) {
                ldsm4(ah[mi], &Ash[buf][wm + mi*16 + arow][acol]);
                ldsm4(al[mi], &Asl[buf][wm + mi*16 + arow][acol]);
            }
            const int brow = kk + (lane & 15);
            #pragma unroll
            for (int np = 0; np < 2; np++) {
                const int bcol = wn + np*16 + ((lane >> 4) << 3);
                unsigned bh[4], blo[4];
                ldsm4t(bh,  &Bsh[buf][brow][bcol]);
                ldsm4t(blo, &Bsl[buf][brow][bcol]);
                #pragma unroll
                for (int h2 = 0; h2 < 2; h2++) {
                    int ni = np*2 + h2;
                    #pragma unroll
                    for (int mi = 0; mi < 2; mi++) {
                        MMA_BF16(acc[mi][ni], ah[mi], bh[h2*2],  bh[h2*2+1]);
                        MMA_BF16(acc[mi][ni], al[mi], bh[h2*2],  bh[h2*2+1]);
                        MMA_BF16(acc[mi][ni], ah[mi], blo[h2*2], blo[h2*2+1]);
                    }
                }
            }
        }
        __syncthreads();
    }

    #pragma unroll
    for (int mi = 0; mi < 2; mi++) {
        #pragma unroll
        for (int ni = 0; ni < 4; ni++) {
            int ncol = c0 + wn + ni*8 + t4*2;
            int m1 = m0 + wm + mi*16 + g;
            size_t o1 = (size_t)m1*C + ncol;
            size_t o2 = (size_t)(m1+8)*C + ncol;
            split_store2(Yh, Yl, o1, acc[mi][ni][0], acc[mi][ni][1]);
            split_store2(Yh, Yl, o2, acc[mi][ni][2], acc[mi][ni][3]);
        }
    }
}

// ---------------- gate GEMM with generalized two-source slices -------------
struct GateArgs {
    const bf16 *Ah[5], *Al[5];
    const bf16 *Bh[5], *Bl[5];
    int strideA, strideB, split, Fp;
    const bf16 *W1h, *W1l; const float* b1; float* Y1;
    const bf16 *W2h, *W2l; const float* b2; float* Y2;
    const float* zg; float* h;
    const float* hmul; bf16 *t0h, *t0l;  // mode0/z0: also write T0 = r*hmul
    bf16 *e1h, *e1l; int e1s, e1o;       // mode1 split dests
    bf16 *e2h, *e2l; int e2s, e2o;
    int mode;
};

__global__ __launch_bounds__(128, 4)
void gate_mma(GateArgs a)
{
    const bf16* Wh = (a.mode == 0 && blockIdx.z) ? a.W2h : a.W1h;
    const bf16* Wl = (a.mode == 0 && blockIdx.z) ? a.W2l : a.W1l;
    const float* bl = (a.mode == 0 && blockIdx.z) ? a.b2 : a.b1;
    float* Yl = (a.mode == 0 && blockIdx.z) ? a.Y2 : a.Y1;

    const int m0 = blockIdx.x * 128;
    const int tid = threadIdx.x;
    const int wid = tid >> 5, lane = tid & 31;
    const int g = lane >> 2, t4 = lane & 3;
    const int CPS = a.Fp >> 4;

    __shared__ bf16 Ash[2][128][GAP];
    __shared__ bf16 Asl[2][128][GAP];
    __shared__ bf16 Bsh[2][16][GBP];
    __shared__ bf16 Bsl[2][16][GBP];

    float acc[2][8][4];
    #pragma unroll
    for (int mi = 0; mi < 2; mi++)
        #pragma unroll
        for (int ni = 0; ni < 8; ni++)
            #pragma unroll
            for (int q = 0; q < 4; q++) acc[mi][ni][q] = 0.f;

    const int bkr = tid >> 3, bjc = (tid & 7) * 8;

    auto load_stage = [&](int buf, int kidx) {
        int s  = kidx / CPS;
        int fb = (kidx - s*CPS) * 16;
        #pragma unroll
        for (int j = 0; j < 2; j++) {
            int f0 = fb + j*8;
            const bf16 *sh, *sl;
            if (f0 < a.split) { sh = a.Ah[s] + (size_t)(m0+tid)*a.strideA + f0;
                                sl = a.Al[s] + (size_t)(m0+tid)*a.strideA + f0; }
            else              { sh = a.Bh[s] + (size_t)(m0+tid)*a.strideB + (f0 - a.split);
                                sl = a.Bl[s] + (size_t)(m0+tid)*a.strideB + (f0 - a.split); }
            cp16(&Ash[buf][tid][j*8], sh);
            cp16(&Asl[buf][tid][j*8], sl);
        }
        int gk = kidx*16 + bkr;
        cp16(&Bsh[buf][bkr][bjc], Wh + (size_t)gk*HID + bjc);
        cp16(&Bsl[buf][bkr][bjc], Wl + (size_t)gk*HID + bjc);
    };

    load_stage(0, 0);
    CP_COMMIT();

    const int NIT = 5 * CPS;
    for (int it = 0; it < NIT; it++) {
        int buf = it & 1;
        if (it + 1 < NIT) { load_stage(buf ^ 1, it+1); CP_COMMIT(); CP_WAIT(1); }
        else              { CP_WAIT(0); }
        __syncthreads();

        const int arow = lane & 15;
        const int acol = (lane >> 4) << 3;
        unsigned ah[2][4], al[2][4];
        #pragma unroll
        for (int mi = 0; mi < 2; mi++) {
            ldsm4(ah[mi], &Ash[buf][wid*32 + mi*16 + arow][acol]);
            ldsm4(al[mi], &Asl[buf][wid*32 + mi*16 + arow][acol]);
        }
        const int brow = lane & 15;
        #pragma unroll
        for (int np = 0; np < 4; np++) {
            const int bcol = np*16 + ((lane >> 4) << 3);
            unsigned bh[4], blo[4];
            ldsm4t(bh,  &Bsh[buf][brow][bcol]);
            ldsm4t(blo, &Bsl[buf][brow][bcol]);
            #pragma unroll
            for (int h2 = 0; h2 < 2; h2++) {
                int ni = np*2 + h2;
                #pragma unroll
                for (int mi = 0; mi < 2; mi++) {
                    MMA_BF16(acc[mi][ni], ah[mi], bh[h2*2],  bh[h2*2+1]);
                    MMA_BF16(acc[mi][ni], al[mi], bh[h2*2],  bh[h2*2+1]);
                    MMA_BF16(acc[mi][ni], ah[mi], blo[h2*2], blo[h2*2+1]);
                }
            }
        }
        __syncthreads();
    }

    const bool write_t0 = (a.mode == 0) && (blockIdx.z == 0) && (a.t0h != nullptr);
    #pragma unroll
    for (int mi = 0; mi < 2; mi++) {
        #pragma unroll
        for (int ni = 0; ni < 8; ni++) {
            int n = ni*8 + t4*2;
            float b0 = bl[n], b1v = bl[n+1];
            #pragma unroll
            for (int half = 0; half < 2; half++) {
                int m = m0 + wid*32 + mi*16 + g + half*8;
                float vx = acc[mi][ni][half*2]   + b0;
                float vy = acc[mi][ni][half*2+1] + b1v;
                size_t off = (size_t)m*HID + n;
                if (a.mode == 0) {
                    float2 o;
                    o.x = 1.f / (1.f + expf(-vx));
                    o.y = 1.f / (1.f + expf(-vy));
                    *reinterpret_cast<float2*>(&Yl[off]) = o;
                    if (write_t0) {
                        float2 hh = *reinterpret_cast<const float2*>(&a.hmul[off]);
                        split_store2(a.t0h, a.t0l, off, o.x * hh.x, o.y * hh.y);
                    }
                } else {
                    float2 zz = *reinterpret_cast<const float2*>(&a.zg[off]);
                    float2 hh = *reinterpret_cast<float2*>(&a.h[off]);
                    float2 o;
                    o.x = (1.f - zz.x) * hh.x + zz.x * tanhf(vx);
                    o.y = (1.f - zz.y) * hh.y + zz.y * tanhf(vy);
                    *reinterpret_cast<float2*>(&a.h[off]) = o;
                    if (a.e1h) split_store2(a.e1h, a.e1l, (size_t)m*a.e1s + a.e1o + n, o.x, o.y);
                    if (a.e2h) split_store2(a.e2h, a.e2l, (size_t)m*a.e2s + a.e2o + n, o.x, o.y);
                }
            }
        }
    }
}

// ---------------- small kernels --------------------------------------------
__global__ void copy_xt(const float* __restrict__ x, int t, float* __restrict__ di,
                        bf16* __restrict__ SAh, bf16* __restrict__ SAl)
{
    int idx = blockIdx.x * blockDim.x + threadIdx.x;
    if (idx >= NB) return;
    int b = idx >> 9, n = idx & 511;
    float v = x[b*(TIN*NN) + t*NN + n];
    int m = n*BB + b;
    di[m] = v;
    emit_split(v, SAh, SAl, (size_t)m*F0P + 64);
}
__global__ void proj_k(const float* __restrict__ h1, const float* __restrict__ Wp,
                       const float* __restrict__ bp, float* __restrict__ out,
                       float* __restrict__ di, bf16* __restrict__ SAh,
                       bf16* __restrict__ SAl, int t)
{
    int m = blockIdx.x * blockDim.x + threadIdx.x;
    if (m >= NB) return;
    float s = bp[0];
    #pragma unroll
    for (int f = 0; f < HID; f++) s += h1[m*HID + f] * Wp[f];
    int n = m >> 4, b = m & 15;
    out[b*(TOUT*NN) + t*NN + n] = s;
    di[m] = s;
    emit_split(s, SAh, SAl, (size_t)m*F0P + 64);
}

// ---------------- host driver ----------------------------------------------
extern "C" void kernel_launch(void* const* d_in, const int* in_sizes, int n_in,
                              void* d_out, int out_size)
{
    const float* x   = (const float*)d_in[0];
    const float* A   = (const float*)d_in[1];
    const float* Wr0 = (const float*)d_in[2];
    const float* br0 = (const float*)d_in[3];
    const float* Wz0 = (const float*)d_in[4];
    const float* bz0 = (const float*)d_in[5];
    const float* Wn0 = (const float*)d_in[6];
    const float* bn0 = (const float*)d_in[7];
    const float* Wr1 = (const float*)d_in[8];
    const float* br1 = (const float*)d_in[9];
    const float* Wz1 = (const float*)d_in[10];
    const float* bz1 = (const float*)d_in[11];
    const float* Wn1 = (const float*)d_in[12];
    const float* bn1 = (const float*)d_in[13];
    const float* Wp  = (const float*)d_in[14];
    const float* bp  = (const float*)d_in[15];
    float* out = (float*)d_out;

    float *G, *cs, *h0, *h1, *di, *r, *z;
    bf16 *Gh, *Gl, *SAh, *SAl, *SBh, *SBl, *S12h, *S12l;
    bf16 *T0h, *T0l, *T12h, *T12l, *Wsh, *Wsl;
    cudaGetSymbolAddress((void**)&G,    g_G);
    cudaGetSymbolAddress((void**)&Gh,   g_Gh);
    cudaGetSymbolAddress((void**)&Gl,   g_Gl);
    cudaGetSymbolAddress((void**)&cs,   g_cs);
    cudaGetSymbolAddress((void**)&h0,   g_h0);
    cudaGetSymbolAddress((void**)&h1,   g_h1);
    cudaGetSymbolAddress((void**)&di,   g_di);
    cudaGetSymbolAddress((void**)&SAh,  g_SAh);
    cudaGetSymbolAddress((void**)&SAl,  g_SAl);
    cudaGetSymbolAddress((void**)&SBh,  g_SBh);
    cudaGetSymbolAddress((void**)&SBl,  g_SBl);
    cudaGetSymbolAddress((void**)&S12h, g_S12h);
    cudaGetSymbolAddress((void**)&S12l, g_S12l);
    cudaGetSymbolAddress((void**)&T0h,  g_T0h);
    cudaGetSymbolAddress((void**)&T0l,  g_T0l);
    cudaGetSymbolAddress((void**)&T12h, g_T12h);
    cudaGetSymbolAddress((void**)&T12l, g_T12l);
    cudaGetSymbolAddress((void**)&r,    g_r);
    cudaGetSymbolAddress((void**)&z,    g_z);
    cudaGetSymbolAddress((void**)&Wsh,  g_Wsh);
    cudaGetSymbolAddress((void**)&Wsl,  g_Wsl);

    rownorm_k<<<NN, 256>>>(A, G);
    colsum_k<<<2, 256>>>(A, cs);
    fill_wb_k<<<NN, 256>>>(A, cs, G);
    square_k<<<dim3(8, 8, 2), 256>>>(G, G);
    split_G_k<<<(4*NN*NN + 255)/256, 256>>>(G, Gh, Gl);
    int g0 = (KP0*HID + 255)/256, g1 = (KP1*HID + 255)/256;
    split_W0_k<<<g0, 256>>>(Wr0, Wsh + OW0R, Wsl + OW0R);
    split_W0_k<<<g0, 256>>>(Wz0, Wsh + OW0Z, Wsl + OW0Z);
    split_W0_k<<<g0, 256>>>(Wn0, Wsh + OW0N, Wsl + OW0N);
    split_W1_k<<<g1, 256>>>(Wr1, Wsh + OW1R, Wsl + OW1R);
    split_W1_k<<<g1, 256>>>(Wz1, Wsh + OW1Z, Wsl + OW1Z);
    split_W1_k<<<g1, 256>>>(Wn1, Wsh + OW1N, Wsl + OW1N);
    zero2_k<<<(NB*HID + 255)/256, 256>>>(h0, h1, NB*HID);
    zero_bb_k<<<(NN*C0P + 255)/256, 256>>>(SAh, SAl, NN*C0P);
    zero_bb_k<<<(NN*C1 + 255)/256, 256>>>(SBh, SBl, NN*C1);

    // slice block order in stacked output: blk0=Wf, blk1=Wb, blk2=Wf2, blk3=Wb2
    // gate slice order: [X, WfX, Wf2X, WbX, Wb2X] -> blocks {in,0,2,1,3}
    auto wire_S = [&](GateArgs& ga, bf16* inh, bf16* inl, bf16* sh, bf16* sl, int C) {
        ga.Ah[0]=inh;                    ga.Al[0]=inl;
        ga.Ah[1]=sh;                     ga.Al[1]=sl;
        ga.Ah[2]=sh+(size_t)2*NN*C;      ga.Al[2]=sl+(size_t)2*NN*C;
        ga.Ah[3]=sh+(size_t)NN*C;        ga.Al[3]=sl+(size_t)NN*C;
        ga.Ah[4]=sh+(size_t)3*NN*C;      ga.Al[4]=sl+(size_t)3*NN*C;
    };

    auto cell0 = [&]() {
        // one stacked hop over [h0 | di | pad]
        hop4_mma<<<dim3(C0P/64, 16), 256>>>(Gh, Gl, SAh, SAl, S12h, S12l, C0P);
        GateArgs ga = {};
        wire_S(ga, SAh, SAl, S12h, S12l, C0P);
        for (int s=0;s<5;s++){ ga.Bh[s]=ga.Ah[s]; ga.Bl[s]=ga.Al[s]; }
        ga.strideA = F0P; ga.strideB = F0P; ga.split = F0P; ga.Fp = F0P;
        ga.W1h = Wsh+OW0R; ga.W1l = Wsl+OW0R; ga.b1 = br0; ga.Y1 = r;
        ga.W2h = Wsh+OW0Z; ga.W2l = Wsl+OW0Z; ga.b2 = bz0; ga.Y2 = z;
        ga.hmul = h0; ga.t0h = T0h; ga.t0l = T0l;
        ga.mode = 0;
        gate_mma<<<dim3(NB/128, 1, 2), 128>>>(ga);
        // stacked hop over r*h0
        hop4_mma<<<dim3(CH/64, 16), 256>>>(Gh, Gl, T0h, T0l, T12h, T12l, CH);
        GateArgs gn = {};
        wire_S(gn, T0h, T0l, T12h, T12l, CH);
        gn.Bh[0]=SAh+64; gn.Bl[0]=SAl+64;
        gn.Bh[1]=S12h+64;                  gn.Bl[1]=S12l+64;
        gn.Bh[2]=S12h+(size_t)2*NN*C0P+64; gn.Bl[2]=S12l+(size_t)2*NN*C0P+64;
        gn.Bh[3]=S12h+(size_t)NN*C0P+64;   gn.Bl[3]=S12l+(size_t)NN*C0P+64;
        gn.Bh[4]=S12h+(size_t)3*NN*C0P+64; gn.Bl[4]=S12l+(size_t)3*NN*C0P+64;
        gn.strideA = HID; gn.strideB = F0P; gn.split = HID; gn.Fp = F0P;
        gn.W1h = Wsh+OW0N; gn.W1l = Wsl+OW0N; gn.b1 = bn0;
        gn.zg = z; gn.h = h0;
        gn.e1h = SAh; gn.e1l = SAl; gn.e1s = F0P; gn.e1o = 0;
        gn.e2h = SBh; gn.e2l = SBl; gn.e2s = F1;  gn.e2o = 0;
        gn.mode = 1;
        gate_mma<<<dim3(NB/128, 1, 1), 128>>>(gn);
    };

    auto cell1 = [&]() {
        hop4_mma<<<dim3(C1/64, 16), 256>>>(Gh, Gl, SBh, SBl, S12h, S12l, C1);
        GateArgs ga = {};
        wire_S(ga, SBh, SBl, S12h, S12l, C1);
        for (int s=0;s<5;s++){ ga.Bh[s]=ga.Ah[s]; ga.Bl[s]=ga.Al[s]; }
        ga.strideA = F1; ga.strideB = F1; ga.split = F1; ga.Fp = F1;
        ga.W1h = Wsh+OW1R; ga.W1l = Wsl+OW1R; ga.b1 = br1; ga.Y1 = r;
        ga.W2h = Wsh+OW1Z; ga.W2l = Wsl+OW1Z; ga.b2 = bz1; ga.Y2 = z;
        ga.hmul = h1; ga.t0h = T0h; ga.t0l = T0l;
        ga.mode = 0;
        gate_mma<<<dim3(NB/128, 1, 2), 128>>>(ga);
        hop4_mma<<<dim3(CH/64, 16), 256>>>(Gh, Gl, T0h, T0l, T12h, T12l, CH);
        GateArgs gn = {};
        // A side: h0 features from S chain (f < 64); B side: r*h1 hops (T)
        wire_S(gn, SBh, SBl, S12h, S12l, C1);
        gn.Bh[0]=T0h;                     gn.Bl[0]=T0l;
        gn.Bh[1]=T12h;                    gn.Bl[1]=T12l;
        gn.Bh[2]=T12h+(size_t)2*NN*CH;    gn.Bl[2]=T12l+(size_t)2*NN*CH;
        gn.Bh[3]=T12h+(size_t)NN*CH;      gn.Bl[3]=T12l+(size_t)NN*CH;
        gn.Bh[4]=T12h+(size_t)3*NN*CH;    gn.Bl[4]=T12l+(size_t)3*NN*CH;
        gn.strideA = F1; gn.strideB = HID; gn.split = HID; gn.Fp = F1;
        gn.W1h = Wsh+OW1N; gn.W1l = Wsl+OW1N; gn.b1 = bn1;
        gn.zg = z; gn.h = h1;
        gn.e1h = SBh; gn.e1l = SBl; gn.e1s = F1; gn.e1o = HID;
        gn.mode = 1;
        gate_mma<<<dim3(NB/128, 1, 1), 128>>>(gn);
    };

    for (int t = 0; t < TIN; t++) {
        copy_xt<<<NB/256, 256>>>(x, t, di, SAh, SAl);
        cell0();
        cell1();
    }
    copy_xt<<<NB/256, 256>>>(x, TIN - 1, di, SAh, SAl);
    for (int t = 0; t < TOUT; t++) {
        cell0();
        cell1();
        proj_k<<<NB/256, 256>>>(h1, Wp, bp, out, di, SAh, SAl, t);
    }
}

// round 7
// speedup vs baseline: 4.0044x; 1.2827x over previous
#include <cuda_runtime.h>
#include <cuda_bf16.h>
#include <math.h>

// ---------------------------------------------------------------------------
// DCRNN 2-layer DCGRU. B=16, N=512, HID=64, K=2, T_in=12, T_out=12.
// G4 = [Wf; Wb; Wf^2; Wb^2] precomputed; each diffusion chain is ONE stacked
// tensor-core GEMM (mma.sync bf16, two-term hi/lo split). 8 launches/step:
//   hop4(S) -> gate_rz -> hop4(T) -> gate_n   x 2 cells
// copy_xt / proj fused into cell-1 n-gate epilogue. Layer-0 stride 72 so the
// S-chain hop is exactly one wave (288 CTAs).
// ---------------------------------------------------------------------------

#define NN   512
#define BB   16
#define HID  64
#define NB   (NN*BB)          // 8192
#define F0S  72               // layer0 storage: [h(64) | di | pad(7)]
#define F0P  80               // layer0 gate K per slice (rows 65..79 zero wt)
#define F1   128
#define C0S  (BB*F0S)         // 1152
#define C1   (BB*F1)          // 2048
#define CH   (BB*HID)         // 1024
#define TIN  12
#define TOUT 12

#define KC   32
#define APP  40
#define BPP  72
#define GAP  24
#define GBP  72

#define KP0  (5*F0P)          // 400
#define KP1  (5*F1)           // 640

typedef __nv_bfloat16 bf16;

// ---------------- device scratch -------------------------------------------
__device__ float g_G [4*NN*NN];
__device__ bf16  g_Gh[4*NN*NN];
__device__ bf16  g_Gl[4*NN*NN];
__device__ float g_cs[NN];
__device__ float g_h0[NB*HID];
__device__ float g_h1[NB*HID];
__device__ bf16  g_SAh[NN*C1];       // layer0 chain input, stride F0S (slack)
__device__ bf16  g_SAl[NN*C1];
__device__ bf16  g_SBh[NN*C1];       // layer1 chain input [h0|h1]
__device__ bf16  g_SBl[NN*C1];
__device__ bf16  g_S12h[4*NN*C1];
__device__ bf16  g_S12l[4*NN*C1];
__device__ bf16  g_T0h[NN*CH];
__device__ bf16  g_T0l[NN*CH];
__device__ bf16  g_T12h[4*NN*CH];
__device__ bf16  g_T12l[4*NN*CH];
__device__ float g_r [NB*HID];
__device__ float g_z [NB*HID];
#define OW0R 0
#define OW0Z (KP0*HID)
#define OW0N (2*KP0*HID)
#define OW1R (3*KP0*HID)
#define OW1Z (3*KP0*HID + KP1*HID)
#define OW1N (3*KP0*HID + 2*KP1*HID)
#define WTOT (3*KP0*HID + 3*KP1*HID)
__device__ bf16  g_Wsh[WTOT];
__device__ bf16  g_Wsl[WTOT];

// ---------------- PTX helpers ----------------------------------------------
__device__ __forceinline__ void cp16(void* dst, const void* src) {
    unsigned d = (unsigned)__cvta_generic_to_shared(dst);
    asm volatile("cp.async.ca.shared.global [%0], [%1], 16;\n" :: "r"(d), "l"(src));
}
#define CP_COMMIT() asm volatile("cp.async.commit_group;\n")
#define CP_WAIT(n)  asm volatile("cp.async.wait_group %0;\n" :: "n"(n))

__device__ __forceinline__ void ldsm4(unsigned* r, const void* p) {
    unsigned a = (unsigned)__cvta_generic_to_shared(p);
    asm volatile("ldmatrix.sync.aligned.m8n8.x4.shared.b16 {%0,%1,%2,%3}, [%4];"
                 : "=r"(r[0]), "=r"(r[1]), "=r"(r[2]), "=r"(r[3]) : "r"(a));
}
__device__ __forceinline__ void ldsm4t(unsigned* r, const void* p) {
    unsigned a = (unsigned)__cvta_generic_to_shared(p);
    asm volatile("ldmatrix.sync.aligned.m8n8.x4.trans.shared.b16 {%0,%1,%2,%3}, [%4];"
                 : "=r"(r[0]), "=r"(r[1]), "=r"(r[2]), "=r"(r[3]) : "r"(a));
}
#define MMA_BF16(d, a, b0v, b1v)                                              \
    asm("mma.sync.aligned.m16n8k16.row.col.f32.bf16.bf16.f32 "                \
        "{%0,%1,%2,%3}, {%4,%5,%6,%7}, {%8,%9}, {%0,%1,%2,%3};"               \
        : "+f"(d[0]), "+f"(d[1]), "+f"(d[2]), "+f"(d[3])                      \
        : "r"(a[0]), "r"(a[1]), "r"(a[2]), "r"(a[3]), "r"(b0v), "r"(b1v))

__device__ __forceinline__ void split_store2(bf16* Yh, bf16* Yl, size_t off, float vx, float vy) {
    bf16 h0 = __float2bfloat16(vx);
    bf16 h1 = __float2bfloat16(vy);
    bf16 l0 = __float2bfloat16(vx - __bfloat162float(h0));
    bf16 l1 = __float2bfloat16(vy - __bfloat162float(h1));
    __nv_bfloat162 hh; hh.x = h0; hh.y = h1;
    __nv_bfloat162 ll; ll.x = l0; ll.y = l1;
    *reinterpret_cast<__nv_bfloat162*>(&Yh[off]) = hh;
    *reinterpret_cast<__nv_bfloat162*>(&Yl[off]) = ll;
}
__device__ __forceinline__ void emit_split(float v, bf16* Xh, bf16* Xl, size_t idx) {
    bf16 h = __float2bfloat16(v);
    Xh[idx] = h;
    Xl[idx] = __float2bfloat16(v - __bfloat162float(h));
}

// ---------------- setup kernels --------------------------------------------
__global__ void rownorm_k(const float* __restrict__ A, float* __restrict__ G) {
    int i = blockIdx.x;
    __shared__ float red[256];
    float s = 0.f;
    for (int j = threadIdx.x; j < NN; j += 256) s += A[i*NN + j];
    red[threadIdx.x] = s; __syncthreads();
    for (int off = 128; off; off >>= 1) {
        if (threadIdx.x < off) red[threadIdx.x] += red[threadIdx.x + off];
        __syncthreads();
    }
    float d = red[0] + 1e-6f;
    for (int j = threadIdx.x; j < NN; j += 256) G[i*NN + j] = A[i*NN + j] / d;
}
__global__ void colsum_k(const float* __restrict__ A, float* __restrict__ cs) {
    int c = blockIdx.x * blockDim.x + threadIdx.x;
    if (c < NN) {
        float s = 0.f;
        for (int r = 0; r < NN; r++) s += A[r*NN + c];
        cs[c] = s;
    }
}
__global__ void fill_wb_k(const float* __restrict__ A, const float* __restrict__ cs,
                          float* __restrict__ G) {
    int i = blockIdx.x;
    float d = cs[i] + 1e-6f;
    for (int j = threadIdx.x; j < NN; j += 256) G[(NN+i)*NN + j] = A[j*NN + i] / d;
}
__global__ void square_k(const float* __restrict__ G, float* __restrict__ Out) {
    const float* Am = G + (size_t)blockIdx.z*NN*NN;
    float* Cm = Out + (size_t)(2 + blockIdx.z)*NN*NN;
    const int m0 = blockIdx.y * 64, n0 = blockIdx.x * 64;
    const int tid = threadIdx.x;
    const int tx = tid & 15, ty = tid >> 4;
    __shared__ float As[16][64];
    __shared__ float Bs[16][64];
    float acc[4][4];
    #pragma unroll
    for (int i = 0; i < 4; i++)
        #pragma unroll
        for (int j = 0; j < 4; j++) acc[i][j] = 0.f;
    for (int k0 = 0; k0 < NN; k0 += 16) {
        {
            int m = tid >> 2, k4 = (tid & 3) * 4;
            float4 w = *reinterpret_cast<const float4*>(&Am[(size_t)(m0+m)*NN + k0 + k4]);
            As[k4+0][m] = w.x; As[k4+1][m] = w.y; As[k4+2][m] = w.z; As[k4+3][m] = w.w;
        }
        {
            int k = tid >> 4, c4 = (tid & 15) * 4;
            float4 v = *reinterpret_cast<const float4*>(&Am[(size_t)(k0+k)*NN + n0 + c4]);
            *reinterpret_cast<float4*>(&Bs[k][c4]) = v;
        }
        __syncthreads();
        #pragma unroll
        for (int k = 0; k < 16; k++) {
            float a[4], b[4];
            #pragma unroll
            for (int i = 0; i < 4; i++) a[i] = As[k][ty + 16*i];
            #pragma unroll
            for (int j = 0; j < 4; j++) b[j] = Bs[k][tx + 16*j];
            #pragma unroll
            for (int i = 0; i < 4; i++)
                #pragma unroll
                for (int j = 0; j < 4; j++) acc[i][j] += a[i] * b[j];
        }
        __syncthreads();
    }
    #pragma unroll
    for (int i = 0; i < 4; i++)
        #pragma unroll
        for (int j = 0; j < 4; j++)
            Cm[(size_t)(m0 + ty + 16*i)*NN + n0 + tx + 16*j] = acc[i][j];
}
__global__ void split_G_k(const float* __restrict__ G, bf16* __restrict__ Gh,
                          bf16* __restrict__ Gl) {
    int i = blockIdx.x * blockDim.x + threadIdx.x;
    if (i < 4*NN*NN) {
        float v = G[i];
        bf16 h = __float2bfloat16(v);
        Gh[i] = h;
        Gl[i] = __float2bfloat16(v - __bfloat162float(h));
    }
}
__global__ void split_W0_k(const float* __restrict__ W, bf16* __restrict__ Wh,
                           bf16* __restrict__ Wl) {
    int i = blockIdx.x * blockDim.x + threadIdx.x;
    if (i >= KP0*HID) return;
    int row = i >> 6, c = i & 63;
    int s = row / F0P, f = row - s*F0P;
    float v = 0.f;
    if (f < 64)       v = W[(size_t)(s*65 + f + 1)*HID + c];
    else if (f == 64) v = W[(size_t)(s*65)*HID + c];
    bf16 h = __float2bfloat16(v);
    Wh[i] = h;
    Wl[i] = __float2bfloat16(v - __bfloat162float(h));
}
__global__ void split_W1_k(const float* __restrict__ W, bf16* __restrict__ Wh,
                           bf16* __restrict__ Wl) {
    int i = blockIdx.x * blockDim.x + threadIdx.x;
    if (i >= KP1*HID) return;
    float v = W[i];
    bf16 h = __float2bfloat16(v);
    Wh[i] = h;
    Wl[i] = __float2bfloat16(v - __bfloat162float(h));
}
__global__ void zero2_k(float* a, float* b, int n) {
    int i = blockIdx.x * blockDim.x + threadIdx.x;
    if (i < n) { a[i] = 0.f; b[i] = 0.f; }
}
__global__ void zero_bb_k(bf16* a, bf16* b, int n) {
    int i = blockIdx.x * blockDim.x + threadIdx.x;
    if (i < n) { a[i] = __float2bfloat16(0.f); b[i] = __float2bfloat16(0.f); }
}
__global__ void copy_xt(const float* __restrict__ x, int t,
                        bf16* __restrict__ SAh, bf16* __restrict__ SAl)
{
    int idx = blockIdx.x * blockDim.x + threadIdx.x;
    if (idx >= NB) return;
    int b = idx >> 9, n = idx & 511;
    float v = x[b*(TIN*NN) + t*NN + n];
    int m = n*BB + b;
    emit_split(v, SAh, SAl, (size_t)m*F0S + 64);
}

// ---------------- stacked hop GEMM: Y(2048,C) = G4 @ X ---------------------
__global__ __launch_bounds__(256, 2)
void hop4_mma(const bf16* __restrict__ Gh, const bf16* __restrict__ Gl,
              const bf16* __restrict__ Xh, const bf16* __restrict__ Xl,
              bf16* __restrict__ Yh, bf16* __restrict__ Yl, int C)
{
    const int m0 = blockIdx.y * 128;
    const int c0 = blockIdx.x * 64;

    __shared__ bf16 Ash[2][128][APP];
    __shared__ bf16 Asl[2][128][APP];
    __shared__ bf16 Bsh[2][KC][BPP];
    __shared__ bf16 Bsl[2][KC][BPP];

    const int tid = threadIdx.x;
    const int wid = tid >> 5, lane = tid & 31;
    const int wm = (wid >> 1) * 32;
    const int wn = (wid & 1) * 32;
    const int g = lane >> 2, t4 = lane & 3;

    const int ar = tid >> 1, aj = (tid & 1) * 16;
    const int bk = tid >> 3, bj = (tid & 7) * 8;

    float acc[2][4][4];
    #pragma unroll
    for (int mi = 0; mi < 2; mi++)
        #pragma unroll
        for (int ni = 0; ni < 4; ni++)
            #pragma unroll
            for (int q = 0; q < 4; q++) acc[mi][ni][q] = 0.f;

    auto load_stage = [&](int buf, int k0) {
        const bf16* a1 = Gh + (size_t)(m0+ar)*NN + k0 + aj;
        const bf16* a2 = Gl + (size_t)(m0+ar)*NN + k0 + aj;
        cp16(&Ash[buf][ar][aj],   a1);
        cp16(&Ash[buf][ar][aj+8], a1+8);
        cp16(&Asl[buf][ar][aj],   a2);
        cp16(&Asl[buf][ar][aj+8], a2+8);
        const bf16* b1 = Xh + (size_t)(k0+bk)*C + c0 + bj;
        const bf16* b2 = Xl + (size_t)(k0+bk)*C + c0 + bj;
        cp16(&Bsh[buf][bk][bj], b1);
        cp16(&Bsl[buf][bk][bj], b2);
    };

    load_stage(0, 0);
    CP_COMMIT();

    const int NIT = NN / KC;
    for (int it = 0; it < NIT; it++) {
        int buf = it & 1;
        if (it + 1 < NIT) { load_stage(buf ^ 1, (it+1)*KC); CP_COMMIT(); CP_WAIT(1); }
        else              { CP_WAIT(0); }
        __syncthreads();

        #pragma unroll
        for (int kk = 0; kk < KC; kk += 16) {
            const int arow = lane & 15;
            const int acol = kk + ((lane >> 4) << 3);
            unsigned ah[2][4], al[2][4];
            #pragma unroll
            for (int mi = 0; mi < 2; mi++) {
                ldsm4(ah[mi], &Ash[buf][wm + mi*16 + arow][acol]);
                ldsm4(al[mi], &Asl[buf][wm + mi*16 + arow][acol]);
            }
            const int brow = kk + (lane & 15);
            #pragma unroll
            for (int np = 0; np < 2; np++) {
                const int bcol = wn + np*16 + ((lane >> 4) << 3);
                unsigned bh[4], blo[4];
                ldsm4t(bh,  &Bsh[buf][brow][bcol]);
                ldsm4t(blo, &Bsl[buf][brow][bcol]);
                #pragma unroll
                for (int h2 = 0; h2 < 2; h2++) {
                    int ni = np*2 + h2;
                    #pragma unroll
                    for (int mi = 0; mi < 2; mi++) {
                        MMA_BF16(acc[mi][ni], ah[mi], bh[h2*2],  bh[h2*2+1]);
                        MMA_BF16(acc[mi][ni], al[mi], bh[h2*2],  bh[h2*2+1]);
                        MMA_BF16(acc[mi][ni], ah[mi], blo[h2*2], blo[h2*2+1]);
                    }
                }
            }
        }
        __syncthreads();
    }

    #pragma unroll
    for (int mi = 0; mi < 2; mi++) {
        #pragma unroll
        for (int ni = 0; ni < 4; ni++) {
            int ncol = c0 + wn + ni*8 + t4*2;
            int m1 = m0 + wm + mi*16 + g;
            size_t o1 = (size_t)m1*C + ncol;
            size_t o2 = (size_t)(m1+8)*C + ncol;
            split_store2(Yh, Yl, o1, acc[mi][ni][0], acc[mi][ni][1]);
            split_store2(Yh, Yl, o2, acc[mi][ni][2], acc[mi][ni][3]);
        }
    }
}

// ---------------- gate GEMM: M-tile 64, fused epilogues --------------------
struct GateArgs {
    const bf16 *Ah[5], *Al[5];
    const bf16 *Bh[5], *Bl[5];
    int strideA, strideB, split, Fp;
    const bf16 *W1h, *W1l; const float* b1; float* Y1;
    const bf16 *W2h, *W2l; const float* b2; float* Y2;
    const float* zg; float* h;
    const float* hmul; bf16 *t0h, *t0l;   // mode0/z0: T0 = r*hmul
    bf16 *e1h, *e1l; int e1s, e1o;        // mode1 split dests
    bf16 *e2h, *e2l; int e2s, e2o;
    // mode1 fusion: 1 = encoder next-x, 2 = decoder proj
    int fuse, t;
    const float *xin, *Wp, *bp; float* out;
    bf16 *dAh, *dAl;
    int mode;
};

__global__ __launch_bounds__(128, 4)
void gate_mma(GateArgs a)
{
    const bf16* Wh = (a.mode == 0 && blockIdx.z) ? a.W2h : a.W1h;
    const bf16* Wl = (a.mode == 0 && blockIdx.z) ? a.W2l : a.W1l;
    const float* bl = (a.mode == 0 && blockIdx.z) ? a.b2 : a.b1;
    float* Yl = (a.mode == 0 && blockIdx.z) ? a.Y2 : a.Y1;

    const int m0 = blockIdx.x * 64;
    const int tid = threadIdx.x;
    const int wid = tid >> 5, lane = tid & 31;
    const int g = lane >> 2, t4 = lane & 3;
    const int CPS = a.Fp >> 4;

    __shared__ bf16 Ash[2][64][GAP];
    __shared__ bf16 Asl[2][64][GAP];
    __shared__ bf16 Bsh[2][16][GBP];
    __shared__ bf16 Bsl[2][16][GBP];

    float acc[8][4];
    #pragma unroll
    for (int ni = 0; ni < 8; ni++)
        #pragma unroll
        for (int q = 0; q < 4; q++) acc[ni][q] = 0.f;

    const int arw = tid >> 1, ja = (tid & 1) * 8;
    const int bkr = tid >> 3, bjc = (tid & 7) * 8;

    auto load_stage = [&](int buf, int kidx) {
        int s  = kidx / CPS;
        int fb = (kidx - s*CPS) * 16;
        int f0 = fb + ja;
        const bf16 *sh, *sl;
        if (f0 < a.split) { sh = a.Ah[s] + (size_t)(m0+arw)*a.strideA + f0;
                            sl = a.Al[s] + (size_t)(m0+arw)*a.strideA + f0; }
        else              { sh = a.Bh[s] + (size_t)(m0+arw)*a.strideB + (f0 - a.split);
                            sl = a.Bl[s] + (size_t)(m0+arw)*a.strideB + (f0 - a.split); }
        cp16(&Ash[buf][arw][ja], sh);
        cp16(&Asl[buf][arw][ja], sl);
        int gk = kidx*16 + bkr;
        cp16(&Bsh[buf][bkr][bjc], Wh + (size_t)gk*HID + bjc);
        cp16(&Bsl[buf][bkr][bjc], Wl + (size_t)gk*HID + bjc);
    };

    load_stage(0, 0);
    CP_COMMIT();

    const int NIT = 5 * CPS;
    for (int it = 0; it < NIT; it++) {
        int buf = it & 1;
        if (it + 1 < NIT) { load_stage(buf ^ 1, it+1); CP_COMMIT(); CP_WAIT(1); }
        else              { CP_WAIT(0); }
        __syncthreads();

        const int arow = lane & 15;
        const int acol = (lane >> 4) << 3;
        unsigned ah[4], al[4];
        ldsm4(ah, &Ash[buf][wid*16 + arow][acol]);
        ldsm4(al, &Asl[buf][wid*16 + arow][acol]);
        const int brow = lane & 15;
        #pragma unroll
        for (int np = 0; np < 4; np++) {
            const int bcol = np*16 + ((lane >> 4) << 3);
            unsigned bh[4], blo[4];
            ldsm4t(bh,  &Bsh[buf][brow][bcol]);
            ldsm4t(blo, &Bsl[buf][brow][bcol]);
            #pragma unroll
            for (int h2 = 0; h2 < 2; h2++) {
                int ni = np*2 + h2;
                MMA_BF16(acc[ni], ah, bh[h2*2],  bh[h2*2+1]);
                MMA_BF16(acc[ni], al, bh[h2*2],  bh[h2*2+1]);
                MMA_BF16(acc[ni], ah, blo[h2*2], blo[h2*2+1]);
            }
        }
        __syncthreads();
    }

    const bool write_t0 = (a.mode == 0) && (blockIdx.z == 0) && (a.t0h != nullptr);
    float partial[2] = {0.f, 0.f};
    #pragma unroll
    for (int ni = 0; ni < 8; ni++) {
        int n = ni*8 + t4*2;
        float b0 = bl[n], b1v = bl[n+1];
        #pragma unroll
        for (int half = 0; half < 2; half++) {
            int m = m0 + wid*16 + g + half*8;
            float vx = acc[ni][half*2]   + b0;
            float vy = acc[ni][half*2+1] + b1v;
            size_t off = (size_t)m*HID + n;
            if (a.mode == 0) {
                float2 o;
                o.x = 1.f / (1.f + expf(-vx));
                o.y = 1.f / (1.f + expf(-vy));
                *reinterpret_cast<float2*>(&Yl[off]) = o;
                if (write_t0) {
                    float2 hh = *reinterpret_cast<const float2*>(&a.hmul[off]);
                    split_store2(a.t0h, a.t0l, off, o.x * hh.x, o.y * hh.y);
                }
            } else {
                float2 zz = *reinterpret_cast<const float2*>(&a.zg[off]);
                float2 hh = *reinterpret_cast<float2*>(&a.h[off]);
                float2 o;
                o.x = (1.f - zz.x) * hh.x + zz.x * tanhf(vx);
                o.y = (1.f - zz.y) * hh.y + zz.y * tanhf(vy);
                *reinterpret_cast<float2*>(&a.h[off]) = o;
                if (a.e1h) split_store2(a.e1h, a.e1l, (size_t)m*a.e1s + a.e1o + n, o.x, o.y);
                if (a.e2h) split_store2(a.e2h, a.e2l, (size_t)m*a.e2s + a.e2o + n, o.x, o.y);
                if (a.fuse == 2) partial[half] += o.x * a.Wp[n] + o.y * a.Wp[n+1];
            }
        }
    }

    if (a.mode == 1 && a.fuse) {
        #pragma unroll
        for (int half = 0; half < 2; half++) {
            float p = partial[half];
            p += __shfl_xor_sync(0xffffffffu, p, 1);
            p += __shfl_xor_sync(0xffffffffu, p, 2);
            int m = m0 + wid*16 + g + half*8;
            if (t4 == 0) {
                int node = m >> 4, b = m & 15;
                if (a.fuse == 2) {
                    float s = p + a.bp[0];
                    a.out[b*(TOUT*NN) + a.t*NN + node] = s;
                    emit_split(s, a.dAh, a.dAl, (size_t)m*F0S + 64);
                } else {
                    float v = a.xin[b*(TIN*NN) + a.t*NN + node];
                    emit_split(v, a.dAh, a.dAl, (size_t)m*F0S + 64);
                }
            }
        }
    }
}

// ---------------- host driver ----------------------------------------------
extern "C" void kernel_launch(void* const* d_in, const int* in_sizes, int n_in,
                              void* d_out, int out_size)
{
    const float* x   = (const float*)d_in[0];
    const float* A   = (const float*)d_in[1];
    const float* Wr0 = (const float*)d_in[2];
    const float* br0 = (const float*)d_in[3];
    const float* Wz0 = (const float*)d_in[4];
    const float* bz0 = (const float*)d_in[5];
    const float* Wn0 = (const float*)d_in[6];
    const float* bn0 = (const float*)d_in[7];
    const float* Wr1 = (const float*)d_in[8];
    const float* br1 = (const float*)d_in[9];
    const float* Wz1 = (const float*)d_in[10];
    const float* bz1 = (const float*)d_in[11];
    const float* Wn1 = (const float*)d_in[12];
    const float* bn1 = (const float*)d_in[13];
    const float* Wp  = (const float*)d_in[14];
    const float* bp  = (const float*)d_in[15];
    float* out = (float*)d_out;

    float *G, *cs, *h0, *h1, *r, *z;
    bf16 *Gh, *Gl, *SAh, *SAl, *SBh, *SBl, *S12h, *S12l;
    bf16 *T0h, *T0l, *T12h, *T12l, *Wsh, *Wsl;
    cudaGetSymbolAddress((void**)&G,    g_G);
    cudaGetSymbolAddress((void**)&Gh,   g_Gh);
    cudaGetSymbolAddress((void**)&Gl,   g_Gl);
    cudaGetSymbolAddress((void**)&cs,   g_cs);
    cudaGetSymbolAddress((void**)&h0,   g_h0);
    cudaGetSymbolAddress((void**)&h1,   g_h1);
    cudaGetSymbolAddress((void**)&SAh,  g_SAh);
    cudaGetSymbolAddress((void**)&SAl,  g_SAl);
    cudaGetSymbolAddress((void**)&SBh,  g_SBh);
    cudaGetSymbolAddress((void**)&SBl,  g_SBl);
    cudaGetSymbolAddress((void**)&S12h, g_S12h);
    cudaGetSymbolAddress((void**)&S12l, g_S12l);
    cudaGetSymbolAddress((void**)&T0h,  g_T0h);
    cudaGetSymbolAddress((void**)&T0l,  g_T0l);
    cudaGetSymbolAddress((void**)&T12h, g_T12h);
    cudaGetSymbolAddress((void**)&T12l, g_T12l);
    cudaGetSymbolAddress((void**)&r,    g_r);
    cudaGetSymbolAddress((void**)&z,    g_z);
    cudaGetSymbolAddress((void**)&Wsh,  g_Wsh);
    cudaGetSymbolAddress((void**)&Wsl,  g_Wsl);

    rownorm_k<<<NN, 256>>>(A, G);
    colsum_k<<<2, 256>>>(A, cs);
    fill_wb_k<<<NN, 256>>>(A, cs, G);
    square_k<<<dim3(8, 8, 2), 256>>>(G, G);
    split_G_k<<<(4*NN*NN + 255)/256, 256>>>(G, Gh, Gl);
    int g0 = (KP0*HID + 255)/256, g1 = (KP1*HID + 255)/256;
    split_W0_k<<<g0, 256>>>(Wr0, Wsh + OW0R, Wsl + OW0R);
    split_W0_k<<<g0, 256>>>(Wz0, Wsh + OW0Z, Wsl + OW0Z);
    split_W0_k<<<g0, 256>>>(Wn0, Wsh + OW0N, Wsl + OW0N);
    split_W1_k<<<g1, 256>>>(Wr1, Wsh + OW1R, Wsl + OW1R);
    split_W1_k<<<g1, 256>>>(Wz1, Wsh + OW1Z, Wsl + OW1Z);
    split_W1_k<<<g1, 256>>>(Wn1, Wsh + OW1N, Wsl + OW1N);
    zero2_k<<<(NB*HID + 255)/256, 256>>>(h0, h1, NB*HID);
    zero_bb_k<<<(NN*C0S + 255)/256, 256>>>(SAh, SAl, NN*C0S);
    zero_bb_k<<<(NN*C1 + 255)/256, 256>>>(SBh, SBl, NN*C1);

    // stacked block order: 0=Wf, 1=Wb, 2=Wf2, 3=Wb2; gate slice order
    // [X, WfX, Wf2X, WbX, Wb2X] -> {in, 0, 2, 1, 3}
    auto wire_S = [&](GateArgs& ga, bf16* inh, bf16* inl, bf16* sh, bf16* sl, int C) {
        ga.Ah[0]=inh;                    ga.Al[0]=inl;
        ga.Ah[1]=sh;                     ga.Al[1]=sl;
        ga.Ah[2]=sh+(size_t)2*NN*C;      ga.Al[2]=sl+(size_t)2*NN*C;
        ga.Ah[3]=sh+(size_t)NN*C;        ga.Al[3]=sl+(size_t)NN*C;
        ga.Ah[4]=sh+(size_t)3*NN*C;      ga.Al[4]=sl+(size_t)3*NN*C;
    };

    auto cell0 = [&]() {
        hop4_mma<<<dim3(C0S/64, 16), 256>>>(Gh, Gl, SAh, SAl, S12h, S12l, C0S);
        GateArgs ga = {};
        wire_S(ga, SAh, SAl, S12h, S12l, C0S);
        for (int s=0;s<5;s++){ ga.Bh[s]=ga.Ah[s]; ga.Bl[s]=ga.Al[s]; }
        ga.strideA = F0S; ga.strideB = F0S; ga.split = F0S; ga.Fp = F0P;
        ga.W1h = Wsh+OW0R; ga.W1l = Wsl+OW0R; ga.b1 = br0; ga.Y1 = r;
        ga.W2h = Wsh+OW0Z; ga.W2l = Wsl+OW0Z; ga.b2 = bz0; ga.Y2 = z;
        ga.hmul = h0; ga.t0h = T0h; ga.t0l = T0l;
        ga.mode = 0;
        gate_mma<<<dim3(NB/64, 1, 2), 128>>>(ga);
        hop4_mma<<<dim3(CH/64, 16), 256>>>(Gh, Gl, T0h, T0l, T12h, T12l, CH);
        GateArgs gn = {};
        wire_S(gn, T0h, T0l, T12h, T12l, CH);
        gn.Bh[0]=SAh+64; gn.Bl[0]=SAl+64;
        gn.Bh[1]=S12h+64;                  gn.Bl[1]=S12l+64;
        gn.Bh[2]=S12h+(size_t)2*NN*C0S+64; gn.Bl[2]=S12l+(size_t)2*NN*C0S+64;
        gn.Bh[3]=S12h+(size_t)NN*C0S+64;   gn.Bl[3]=S12l+(size_t)NN*C0S+64;
        gn.Bh[4]=S12h+(size_t)3*NN*C0S+64; gn.Bl[4]=S12l+(size_t)3*NN*C0S+64;
        gn.strideA = HID; gn.strideB = F0S; gn.split = HID; gn.Fp = F0P;
        gn.W1h = Wsh+OW0N; gn.W1l = Wsl+OW0N; gn.b1 = bn0;
        gn.zg = z; gn.h = h0;
        gn.e1h = SAh; gn.e1l = SAl; gn.e1s = F0S; gn.e1o = 0;
        gn.e2h = SBh; gn.e2l = SBl; gn.e2s = F1;  gn.e2o = 0;
        gn.mode = 1;
        gate_mma<<<dim3(NB/64, 1, 1), 128>>>(gn);
    };

    auto cell1 = [&](int fuse, int t) {
        hop4_mma<<<dim3(C1/64, 16), 256>>>(Gh, Gl, SBh, SBl, S12h, S12l, C1);
        GateArgs ga = {};
        wire_S(ga, SBh, SBl, S12h, S12l, C1);
        for (int s=0;s<5;s++){ ga.Bh[s]=ga.Ah[s]; ga.Bl[s]=ga.Al[s]; }
        ga.strideA = F1; ga.strideB = F1; ga.split = F1; ga.Fp = F1;
        ga.W1h = Wsh+OW1R; ga.W1l = Wsl+OW1R; ga.b1 = br1; ga.Y1 = r;
        ga.W2h = Wsh+OW1Z; ga.W2l = Wsl+OW1Z; ga.b2 = bz1; ga.Y2 = z;
        ga.hmul = h1; ga.t0h = T0h; ga.t0l = T0l;
        ga.mode = 0;
        gate_mma<<<dim3(NB/64, 1, 2), 128>>>(ga);
        hop4_mma<<<dim3(CH/64, 16), 256>>>(Gh, Gl, T0h, T0l, T12h, T12l, CH);
        GateArgs gn = {};
        wire_S(gn, SBh, SBl, S12h, S12l, C1);
        gn.Bh[0]=T0h;                     gn.Bl[0]=T0l;
        gn.Bh[1]=T12h;                    gn.Bl[1]=T12l;
        gn.Bh[2]=T12h+(size_t)2*NN*CH;    gn.Bl[2]=T12l+(size_t)2*NN*CH;
        gn.Bh[3]=T12h+(size_t)NN*CH;      gn.Bl[3]=T12l+(size_t)NN*CH;
        gn.Bh[4]=T12h+(size_t)3*NN*CH;    gn.Bl[4]=T12l+(size_t)3*NN*CH;
        gn.strideA = F1; gn.strideB = HID; gn.split = HID; gn.Fp = F1;
        gn.W1h = Wsh+OW1N; gn.W1l = Wsl+OW1N; gn.b1 = bn1;
        gn.zg = z; gn.h = h1;
        gn.e1h = SBh; gn.e1l = SBl; gn.e1s = F1; gn.e1o = HID;
        gn.fuse = fuse; gn.t = t;
        gn.xin = x; gn.Wp = Wp; gn.bp = bp; gn.out = out;
        gn.dAh = SAh; gn.dAl = SAl;
        gn.mode = 1;
        gate_mma<<<dim3(NB/64, 1, 1), 128>>>(gn);
    };

    copy_xt<<<NB/256, 256>>>(x, 0, SAh, SAl);
    for (int t = 0; t < TIN; t++) {
        cell0();
        cell1(1, (t + 1 < TIN) ? t + 1 : TIN - 1);   // write next x's di
    }
    for (int t = 0; t < TOUT; t++) {
        cell0();
        cell1(2, t);                                  // proj + next di
    }
}

// round 8
// speedup vs baseline: 4.0667x; 1.0156x over previous
#include <cuda_runtime.h>
#include <cuda_bf16.h>
#include <math.h>

// ---------------------------------------------------------------------------
// DCRNN 2-layer DCGRU. B=16, N=512, HID=64, K=2, T_in=12, T_out=12.
// G4 = [Wf; Wb; Wf^2; Wb^2] precomputed; each diffusion chain is ONE stacked
// tensor-core GEMM (mma.sync bf16, two-term hi/lo split). 8 launches/step.
// NEW: all hop/gate kernels use Programmatic Dependent Launch — constant
// operands (G tiles / gate weights) are prefetched BEFORE
// cudaGridDependencySynchronize(), overlapping each kernel's ramp with its
// producer's tail.
// ---------------------------------------------------------------------------

#define NN   512
#define BB   16
#define HID  64
#define NB   (NN*BB)          // 8192
#define F0S  72               // layer0 storage: [h(64) | di | pad(7)]
#define F0P  80               // layer0 gate K per slice (rows 65..79 zero wt)
#define F1   128
#define C0S  (BB*F0S)         // 1152
#define C1   (BB*F1)          // 2048
#define CH   (BB*HID)         // 1024
#define TIN  12
#define TOUT 12

#define KC   32
#define APP  40
#define BPP  72
#define GAP  24
#define GBP  72

#define KP0  (5*F0P)          // 400
#define KP1  (5*F1)           // 640

typedef __nv_bfloat16 bf16;

// ---------------- device scratch -------------------------------------------
__device__ float g_G [4*NN*NN];
__device__ bf16  g_Gh[4*NN*NN];
__device__ bf16  g_Gl[4*NN*NN];
__device__ float g_cs[NN];
__device__ float g_h0[NB*HID];
__device__ float g_h1[NB*HID];
__device__ bf16  g_SAh[NN*C1];
__device__ bf16  g_SAl[NN*C1];
__device__ bf16  g_SBh[NN*C1];
__device__ bf16  g_SBl[NN*C1];
__device__ bf16  g_S12h[4*NN*C1];
__device__ bf16  g_S12l[4*NN*C1];
__device__ bf16  g_T0h[NN*CH];
__device__ bf16  g_T0l[NN*CH];
__device__ bf16  g_T12h[4*NN*CH];
__device__ bf16  g_T12l[4*NN*CH];
__device__ float g_r [NB*HID];
__device__ float g_z [NB*HID];
#define OW0R 0
#define OW0Z (KP0*HID)
#define OW0N (2*KP0*HID)
#define OW1R (3*KP0*HID)
#define OW1Z (3*KP0*HID + KP1*HID)
#define OW1N (3*KP0*HID + 2*KP1*HID)
#define WTOT (3*KP0*HID + 3*KP1*HID)
__device__ bf16  g_Wsh[WTOT];
__device__ bf16  g_Wsl[WTOT];

// ---------------- PTX helpers ----------------------------------------------
__device__ __forceinline__ void cp16(void* dst, const void* src) {
    unsigned d = (unsigned)__cvta_generic_to_shared(dst);
    asm volatile("cp.async.ca.shared.global [%0], [%1], 16;\n" :: "r"(d), "l"(src));
}
#define CP_COMMIT() asm volatile("cp.async.commit_group;\n")
#define CP_WAIT(n)  asm volatile("cp.async.wait_group %0;\n" :: "n"(n))

__device__ __forceinline__ void ldsm4(unsigned* r, const void* p) {
    unsigned a = (unsigned)__cvta_generic_to_shared(p);
    asm volatile("ldmatrix.sync.aligned.m8n8.x4.shared.b16 {%0,%1,%2,%3}, [%4];"
                 : "=r"(r[0]), "=r"(r[1]), "=r"(r[2]), "=r"(r[3]) : "r"(a));
}
__device__ __forceinline__ void ldsm4t(unsigned* r, const void* p) {
    unsigned a = (unsigned)__cvta_generic_to_shared(p);
    asm volatile("ldmatrix.sync.aligned.m8n8.x4.trans.shared.b16 {%0,%1,%2,%3}, [%4];"
                 : "=r"(r[0]), "=r"(r[1]), "=r"(r[2]), "=r"(r[3]) : "r"(a));
}
#define MMA_BF16(d, a, b0v, b1v)                                              \
    asm("mma.sync.aligned.m16n8k16.row.col.f32.bf16.bf16.f32 "                \
        "{%0,%1,%2,%3}, {%4,%5,%6,%7}, {%8,%9}, {%0,%1,%2,%3};"               \
        : "+f"(d[0]), "+f"(d[1]), "+f"(d[2]), "+f"(d[3])                      \
        : "r"(a[0]), "r"(a[1]), "r"(a[2]), "r"(a[3]), "r"(b0v), "r"(b1v))

__device__ __forceinline__ void split_store2(bf16* Yh, bf16* Yl, size_t off, float vx, float vy) {
    bf16 h0 = __float2bfloat16(vx);
    bf16 h1 = __float2bfloat16(vy);
    bf16 l0 = __float2bfloat16(vx - __bfloat162float(h0));
    bf16 l1 = __float2bfloat16(vy - __bfloat162float(h1));
    __nv_bfloat162 hh; hh.x = h0; hh.y = h1;
    __nv_bfloat162 ll; ll.x = l0; ll.y = l1;
    *reinterpret_cast<__nv_bfloat162*>(&Yh[off]) = hh;
    *reinterpret_cast<__nv_bfloat162*>(&Yl[off]) = ll;
}
__device__ __forceinline__ void emit_split(float v, bf16* Xh, bf16* Xl, size_t idx) {
    bf16 h = __float2bfloat16(v);
    Xh[idx] = h;
    Xl[idx] = __float2bfloat16(v - __bfloat162float(h));
}

// ---------------- setup kernels --------------------------------------------
__global__ void rownorm_k(const float* __restrict__ A, float* __restrict__ G) {
    int i = blockIdx.x;
    __shared__ float red[256];
    float s = 0.f;
    for (int j = threadIdx.x; j < NN; j += 256) s += A[i*NN + j];
    red[threadIdx.x] = s; __syncthreads();
    for (int off = 128; off; off >>= 1) {
        if (threadIdx.x < off) red[threadIdx.x] += red[threadIdx.x + off];
        __syncthreads();
    }
    float d = red[0] + 1e-6f;
    for (int j = threadIdx.x; j < NN; j += 256) G[i*NN + j] = A[i*NN + j] / d;
}
__global__ void colsum_k(const float* __restrict__ A, float* __restrict__ cs) {
    int c = blockIdx.x * blockDim.x + threadIdx.x;
    if (c < NN) {
        float s = 0.f;
        for (int r = 0; r < NN; r++) s += A[r*NN + c];
        cs[c] = s;
    }
}
__global__ void fill_wb_k(const float* __restrict__ A, const float* __restrict__ cs,
                          float* __restrict__ G) {
    int i = blockIdx.x;
    float d = cs[i] + 1e-6f;
    for (int j = threadIdx.x; j < NN; j += 256) G[(NN+i)*NN + j] = A[j*NN + i] / d;
}
__global__ void square_k(const float* __restrict__ G, float* __restrict__ Out) {
    const float* Am = G + (size_t)blockIdx.z*NN*NN;
    float* Cm = Out + (size_t)(2 + blockIdx.z)*NN*NN;
    const int m0 = blockIdx.y * 64, n0 = blockIdx.x * 64;
    const int tid = threadIdx.x;
    const int tx = tid & 15, ty = tid >> 4;
    __shared__ float As[16][64];
    __shared__ float Bs[16][64];
    float acc[4][4];
    #pragma unroll
    for (int i = 0; i < 4; i++)
        #pragma unroll
        for (int j = 0; j < 4; j++) acc[i][j] = 0.f;
    for (int k0 = 0; k0 < NN; k0 += 16) {
        {
            int m = tid >> 2, k4 = (tid & 3) * 4;
            float4 w = *reinterpret_cast<const float4*>(&Am[(size_t)(m0+m)*NN + k0 + k4]);
            As[k4+0][m] = w.x; As[k4+1][m] = w.y; As[k4+2][m] = w.z; As[k4+3][m] = w.w;
        }
        {
            int k = tid >> 4, c4 = (tid & 15) * 4;
            float4 v = *reinterpret_cast<const float4*>(&Am[(size_t)(k0+k)*NN + n0 + c4]);
            *reinterpret_cast<float4*>(&Bs[k][c4]) = v;
        }
        __syncthreads();
        #pragma unroll
        for (int k = 0; k < 16; k++) {
            float a[4], b[4];
            #pragma unroll
            for (int i = 0; i < 4; i++) a[i] = As[k][ty + 16*i];
            #pragma unroll
            for (int j = 0; j < 4; j++) b[j] = Bs[k][tx + 16*j];
            #pragma unroll
            for (int i = 0; i < 4; i++)
                #pragma unroll
                for (int j = 0; j < 4; j++) acc[i][j] += a[i] * b[j];
        }
        __syncthreads();
    }
    #pragma unroll
    for (int i = 0; i < 4; i++)
        #pragma unroll
        for (int j = 0; j < 4; j++)
            Cm[(size_t)(m0 + ty + 16*i)*NN + n0 + tx + 16*j] = acc[i][j];
}
__global__ void split_G_k(const float* __restrict__ G, bf16* __restrict__ Gh,
                          bf16* __restrict__ Gl) {
    int i = blockIdx.x * blockDim.x + threadIdx.x;
    if (i < 4*NN*NN) {
        float v = G[i];
        bf16 h = __float2bfloat16(v);
        Gh[i] = h;
        Gl[i] = __float2bfloat16(v - __bfloat162float(h));
    }
}
__global__ void split_W0_k(const float* __restrict__ W, bf16* __restrict__ Wh,
                           bf16* __restrict__ Wl) {
    int i = blockIdx.x * blockDim.x + threadIdx.x;
    if (i >= KP0*HID) return;
    int row = i >> 6, c = i & 63;
    int s = row / F0P, f = row - s*F0P;
    float v = 0.f;
    if (f < 64)       v = W[(size_t)(s*65 + f + 1)*HID + c];
    else if (f == 64) v = W[(size_t)(s*65)*HID + c];
    bf16 h = __float2bfloat16(v);
    Wh[i] = h;
    Wl[i] = __float2bfloat16(v - __bfloat162float(h));
}
__global__ void split_W1_k(const float* __restrict__ W, bf16* __restrict__ Wh,
                           bf16* __restrict__ Wl) {
    int i = blockIdx.x * blockDim.x + threadIdx.x;
    if (i >= KP1*HID) return;
    float v = W[i];
    bf16 h = __float2bfloat16(v);
    Wh[i] = h;
    Wl[i] = __float2bfloat16(v - __bfloat162float(h));
}
__global__ void zero2_k(float* a, float* b, int n) {
    int i = blockIdx.x * blockDim.x + threadIdx.x;
    if (i < n) { a[i] = 0.f; b[i] = 0.f; }
}
__global__ void zero_bb_k(bf16* a, bf16* b, int n) {
    int i = blockIdx.x * blockDim.x + threadIdx.x;
    if (i < n) { a[i] = __float2bfloat16(0.f); b[i] = __float2bfloat16(0.f); }
}
__global__ void copy_xt(const float* __restrict__ x, int t,
                        bf16* __restrict__ SAh, bf16* __restrict__ SAl)
{
    int idx = blockIdx.x * blockDim.x + threadIdx.x;
    if (idx >= NB) return;
    int b = idx >> 9, n = idx & 511;
    float v = x[b*(TIN*NN) + t*NN + n];
    int m = n*BB + b;
    emit_split(v, SAh, SAl, (size_t)m*F0S + 64);
}

// ---------------- stacked hop GEMM: Y(2048,C) = G4 @ X, PDL ----------------
__global__ __launch_bounds__(256, 2)
void hop4_mma(const bf16* __restrict__ Gh, const bf16* __restrict__ Gl,
              const bf16* __restrict__ Xh, const bf16* __restrict__ Xl,
              bf16* __restrict__ Yh, bf16* __restrict__ Yl, int C)
{
    const int m0 = blockIdx.y * 128;
    const int c0 = blockIdx.x * 64;

    __shared__ bf16 Ash[2][128][APP];
    __shared__ bf16 Asl[2][128][APP];
    __shared__ bf16 Bsh[2][KC][BPP];
    __shared__ bf16 Bsl[2][KC][BPP];

    const int tid = threadIdx.x;
    const int wid = tid >> 5, lane = tid & 31;
    const int wm = (wid >> 1) * 32;
    const int wn = (wid & 1) * 32;
    const int g = lane >> 2, t4 = lane & 3;

    const int ar = tid >> 1, aj = (tid & 1) * 16;
    const int bk = tid >> 3, bj = (tid & 7) * 8;

    float acc[2][4][4];
    #pragma unroll
    for (int mi = 0; mi < 2; mi++)
        #pragma unroll
        for (int ni = 0; ni < 4; ni++)
            #pragma unroll
            for (int q = 0; q < 4; q++) acc[mi][ni][q] = 0.f;

    auto load_A = [&](int buf, int k0) {
        const bf16* a1 = Gh + (size_t)(m0+ar)*NN + k0 + aj;
        const bf16* a2 = Gl + (size_t)(m0+ar)*NN + k0 + aj;
        cp16(&Ash[buf][ar][aj],   a1);
        cp16(&Ash[buf][ar][aj+8], a1+8);
        cp16(&Asl[buf][ar][aj],   a2);
        cp16(&Asl[buf][ar][aj+8], a2+8);
    };
    auto load_B = [&](int buf, int k0) {
        const bf16* b1 = Xh + (size_t)(k0+bk)*C + c0 + bj;
        const bf16* b2 = Xl + (size_t)(k0+bk)*C + c0 + bj;
        cp16(&Bsh[buf][bk][bj], b1);
        cp16(&Bsl[buf][bk][bj], b2);
    };

    // PDL: prefetch constant G tiles before waiting on the producer.
    load_A(0, 0);
#if __CUDA_ARCH__ >= 900
    cudaGridDependencySynchronize();
#endif
    load_B(0, 0);
    CP_COMMIT();

    const int NIT = NN / KC;
    for (int it = 0; it < NIT; it++) {
        int buf = it & 1;
        if (it + 1 < NIT) {
            load_A(buf ^ 1, (it+1)*KC);
            load_B(buf ^ 1, (it+1)*KC);
            CP_COMMIT(); CP_WAIT(1);
        } else {
            CP_WAIT(0);
        }
        __syncthreads();

        #pragma unroll
        for (int kk = 0; kk < KC; kk += 16) {
            const int arow = lane & 15;
            const int acol = kk + ((lane >> 4) << 3);
            unsigned ah[2][4], al[2][4];
            #pragma unroll
            for (int mi = 0; mi < 2; mi++) {
                ldsm4(ah[mi], &Ash[buf][wm + mi*16 + arow][acol]);
                ldsm4(al[mi], &Asl[buf][wm + mi*16 + arow][acol]);
            }
            const int brow = kk + (lane & 15);
            #pragma unroll
            for (int np = 0; np < 2; np++) {
                const int bcol = wn + np*16 + ((lane >> 4) << 3);
                unsigned bh[4], blo[4];
                ldsm4t(bh,  &Bsh[buf][brow][bcol]);
                ldsm4t(blo, &Bsl[buf][brow][bcol]);
                #pragma unroll
                for (int h2 = 0; h2 < 2; h2++) {
                    int ni = np*2 + h2;
                    #pragma unroll
                    for (int mi = 0; mi < 2; mi++) {
                        MMA_BF16(acc[mi][ni], ah[mi], bh[h2*2],  bh[h2*2+1]);
                        MMA_BF16(acc[mi][ni], al[mi], bh[h2*2],  bh[h2*2+1]);
                        MMA_BF16(acc[mi][ni], ah[mi], blo[h2*2], blo[h2*2+1]);
                    }
                }
            }
        }
        __syncthreads();
    }

    #pragma unroll
    for (int mi = 0; mi < 2; mi++) {
        #pragma unroll
        for (int ni = 0; ni < 4; ni++) {
            int ncol = c0 + wn + ni*8 + t4*2;
            int m1 = m0 + wm + mi*16 + g;
            size_t o1 = (size_t)m1*C + ncol;
            size_t o2 = (size_t)(m1+8)*C + ncol;
            split_store2(Yh, Yl, o1, acc[mi][ni][0], acc[mi][ni][1]);
            split_store2(Yh, Yl, o2, acc[mi][ni][2], acc[mi][ni][3]);
        }
    }
}

// ---------------- gate GEMM: M-tile 64, fused epilogues, PDL ---------------
struct GateArgs {
    const bf16 *Ah[5], *Al[5];
    const bf16 *Bh[5], *Bl[5];
    int strideA, strideB, split, Fp;
    const bf16 *W1h, *W1l; const float* b1; float* Y1;
    const bf16 *W2h, *W2l; const float* b2; float* Y2;
    const float* zg; float* h;
    const float* hmul; bf16 *t0h, *t0l;
    bf16 *e1h, *e1l; int e1s, e1o;
    bf16 *e2h, *e2l; int e2s, e2o;
    int fuse, t;
    const float *xin, *Wp, *bp; float* out;
    bf16 *dAh, *dAl;
    int mode;
};

__global__ __launch_bounds__(128, 4)
void gate_mma(GateArgs a)
{
    const bf16* Wh = (a.mode == 0 && blockIdx.z) ? a.W2h : a.W1h;
    const bf16* Wl = (a.mode == 0 && blockIdx.z) ? a.W2l : a.W1l;
    const float* bl = (a.mode == 0 && blockIdx.z) ? a.b2 : a.b1;
    float* Yl = (a.mode == 0 && blockIdx.z) ? a.Y2 : a.Y1;

    const int m0 = blockIdx.x * 64;
    const int tid = threadIdx.x;
    const int wid = tid >> 5, lane = tid & 31;
    const int g = lane >> 2, t4 = lane & 3;
    const int CPS = a.Fp >> 4;

    __shared__ bf16 Ash[2][64][GAP];
    __shared__ bf16 Asl[2][64][GAP];
    __shared__ bf16 Bsh[2][16][GBP];
    __shared__ bf16 Bsl[2][16][GBP];

    float acc[8][4];
    #pragma unroll
    for (int ni = 0; ni < 8; ni++)
        #pragma unroll
        for (int q = 0; q < 4; q++) acc[ni][q] = 0.f;

    const int arw = tid >> 1, ja = (tid & 1) * 8;
    const int bkr = tid >> 3, bjc = (tid & 7) * 8;

    auto load_W = [&](int buf, int kidx) {
        int gk = kidx*16 + bkr;
        cp16(&Bsh[buf][bkr][bjc], Wh + (size_t)gk*HID + bjc);
        cp16(&Bsl[buf][bkr][bjc], Wl + (size_t)gk*HID + bjc);
    };
    auto load_X = [&](int buf, int kidx) {
        int s  = kidx / CPS;
        int fb = (kidx - s*CPS) * 16;
        int f0 = fb + ja;
        const bf16 *sh, *sl;
        if (f0 < a.split) { sh = a.Ah[s] + (size_t)(m0+arw)*a.strideA + f0;
                            sl = a.Al[s] + (size_t)(m0+arw)*a.strideA + f0; }
        else              { sh = a.Bh[s] + (size_t)(m0+arw)*a.strideB + (f0 - a.split);
                            sl = a.Bl[s] + (size_t)(m0+arw)*a.strideB + (f0 - a.split); }
        cp16(&Ash[buf][arw][ja], sh);
        cp16(&Asl[buf][arw][ja], sl);
    };

    // PDL: prefetch constant weights before waiting on the producer.
    load_W(0, 0);
#if __CUDA_ARCH__ >= 900
    cudaGridDependencySynchronize();
#endif
    load_X(0, 0);
    CP_COMMIT();

    const int NIT = 5 * CPS;
    for (int it = 0; it < NIT; it++) {
        int buf = it & 1;
        if (it + 1 < NIT) {
            load_W(buf ^ 1, it+1);
            load_X(buf ^ 1, it+1);
            CP_COMMIT(); CP_WAIT(1);
        } else {
            CP_WAIT(0);
        }
        __syncthreads();

        const int arow = lane & 15;
        const int acol = (lane >> 4) << 3;
        unsigned ah[4], al[4];
        ldsm4(ah, &Ash[buf][wid*16 + arow][acol]);
        ldsm4(al, &Asl[buf][wid*16 + arow][acol]);
        const int brow = lane & 15;
        #pragma unroll
        for (int np = 0; np < 4; np++) {
            const int bcol = np*16 + ((lane >> 4) << 3);
            unsigned bh[4], blo[4];
            ldsm4t(bh,  &Bsh[buf][brow][bcol]);
            ldsm4t(blo, &Bsl[buf][brow][bcol]);
            #pragma unroll
            for (int h2 = 0; h2 < 2; h2++) {
                int ni = np*2 + h2;
                MMA_BF16(acc[ni], ah, bh[h2*2],  bh[h2*2+1]);
                MMA_BF16(acc[ni], al, bh[h2*2],  bh[h2*2+1]);
                MMA_BF16(acc[ni], ah, blo[h2*2], blo[h2*2+1]);
            }
        }
        __syncthreads();
    }

    const bool write_t0 = (a.mode == 0) && (blockIdx.z == 0) && (a.t0h != nullptr);
    float partial[2] = {0.f, 0.f};
    #pragma unroll
    for (int ni = 0; ni < 8; ni++) {
        int n = ni*8 + t4*2;
        float b0 = bl[n], b1v = bl[n+1];
        #pragma unroll
        for (int half = 0; half < 2; half++) {
            int m = m0 + wid*16 + g + half*8;
            float vx = acc[ni][half*2]   + b0;
            float vy = acc[ni][half*2+1] + b1v;
            size_t off = (size_t)m*HID + n;
            if (a.mode == 0) {
                float2 o;
                o.x = 1.f / (1.f + expf(-vx));
                o.y = 1.f / (1.f + expf(-vy));
                *reinterpret_cast<float2*>(&Yl[off]) = o;
                if (write_t0) {
                    float2 hh = *reinterpret_cast<const float2*>(&a.hmul[off]);
                    split_store2(a.t0h, a.t0l, off, o.x * hh.x, o.y * hh.y);
                }
            } else {
                float2 zz = *reinterpret_cast<const float2*>(&a.zg[off]);
                float2 hh = *reinterpret_cast<float2*>(&a.h[off]);
                float2 o;
                o.x = (1.f - zz.x) * hh.x + zz.x * tanhf(vx);
                o.y = (1.f - zz.y) * hh.y + zz.y * tanhf(vy);
                *reinterpret_cast<float2*>(&a.h[off]) = o;
                if (a.e1h) split_store2(a.e1h, a.e1l, (size_t)m*a.e1s + a.e1o + n, o.x, o.y);
                if (a.e2h) split_store2(a.e2h, a.e2l, (size_t)m*a.e2s + a.e2o + n, o.x, o.y);
                if (a.fuse == 2) partial[half] += o.x * a.Wp[n] + o.y * a.Wp[n+1];
            }
        }
    }

    if (a.mode == 1 && a.fuse) {
        #pragma unroll
        for (int half = 0; half < 2; half++) {
            float p = partial[half];
            p += __shfl_xor_sync(0xffffffffu, p, 1);
            p += __shfl_xor_sync(0xffffffffu, p, 2);
            int m = m0 + wid*16 + g + half*8;
            if (t4 == 0) {
                int node = m >> 4, b = m & 15;
                if (a.fuse == 2) {
                    float s = p + a.bp[0];
                    a.out[b*(TOUT*NN) + a.t*NN + node] = s;
                    emit_split(s, a.dAh, a.dAl, (size_t)m*F0S + 64);
                } else {
                    float v = a.xin[b*(TIN*NN) + a.t*NN + node];
                    emit_split(v, a.dAh, a.dAl, (size_t)m*F0S + 64);
                }
            }
        }
    }
}

// ---------------- host driver ----------------------------------------------
extern "C" void kernel_launch(void* const* d_in, const int* in_sizes, int n_in,
                              void* d_out, int out_size)
{
    const float* x   = (const float*)d_in[0];
    const float* A   = (const float*)d_in[1];
    const float* Wr0 = (const float*)d_in[2];
    const float* br0 = (const float*)d_in[3];
    const float* Wz0 = (const float*)d_in[4];
    const float* bz0 = (const float*)d_in[5];
    const float* Wn0 = (const float*)d_in[6];
    const float* bn0 = (const float*)d_in[7];
    const float* Wr1 = (const float*)d_in[8];
    const float* br1 = (const float*)d_in[9];
    const float* Wz1 = (const float*)d_in[10];
    const float* bz1 = (const float*)d_in[11];
    const float* Wn1 = (const float*)d_in[12];
    const float* bn1 = (const float*)d_in[13];
    const float* Wp  = (const float*)d_in[14];
    const float* bp  = (const float*)d_in[15];
    float* out = (float*)d_out;

    float *G, *cs, *h0, *h1, *r, *z;
    bf16 *Gh, *Gl, *SAh, *SAl, *SBh, *SBl, *S12h, *S12l;
    bf16 *T0h, *T0l, *T12h, *T12l, *Wsh, *Wsl;
    cudaGetSymbolAddress((void**)&G,    g_G);
    cudaGetSymbolAddress((void**)&Gh,   g_Gh);
    cudaGetSymbolAddress((void**)&Gl,   g_Gl);
    cudaGetSymbolAddress((void**)&cs,   g_cs);
    cudaGetSymbolAddress((void**)&h0,   g_h0);
    cudaGetSymbolAddress((void**)&h1,   g_h1);
    cudaGetSymbolAddress((void**)&SAh,  g_SAh);
    cudaGetSymbolAddress((void**)&SAl,  g_SAl);
    cudaGetSymbolAddress((void**)&SBh,  g_SBh);
    cudaGetSymbolAddress((void**)&SBl,  g_SBl);
    cudaGetSymbolAddress((void**)&S12h, g_S12h);
    cudaGetSymbolAddress((void**)&S12l, g_S12l);
    cudaGetSymbolAddress((void**)&T0h,  g_T0h);
    cudaGetSymbolAddress((void**)&T0l,  g_T0l);
    cudaGetSymbolAddress((void**)&T12h, g_T12h);
    cudaGetSymbolAddress((void**)&T12l, g_T12l);
    cudaGetSymbolAddress((void**)&r,    g_r);
    cudaGetSymbolAddress((void**)&z,    g_z);
    cudaGetSymbolAddress((void**)&Wsh,  g_Wsh);
    cudaGetSymbolAddress((void**)&Wsl,  g_Wsl);

    rownorm_k<<<NN, 256>>>(A, G);
    colsum_k<<<2, 256>>>(A, cs);
    fill_wb_k<<<NN, 256>>>(A, cs, G);
    square_k<<<dim3(8, 8, 2), 256>>>(G, G);
    split_G_k<<<(4*NN*NN + 255)/256, 256>>>(G, Gh, Gl);
    int g0 = (KP0*HID + 255)/256, g1 = (KP1*HID + 255)/256;
    split_W0_k<<<g0, 256>>>(Wr0, Wsh + OW0R, Wsl + OW0R);
    split_W0_k<<<g0, 256>>>(Wz0, Wsh + OW0Z, Wsl + OW0Z);
    split_W0_k<<<g0, 256>>>(Wn0, Wsh + OW0N, Wsl + OW0N);
    split_W1_k<<<g1, 256>>>(Wr1, Wsh + OW1R, Wsl + OW1R);
    split_W1_k<<<g1, 256>>>(Wz1, Wsh + OW1Z, Wsl + OW1Z);
    split_W1_k<<<g1, 256>>>(Wn1, Wsh + OW1N, Wsl + OW1N);
    zero2_k<<<(NB*HID + 255)/256, 256>>>(h0, h1, NB*HID);
    zero_bb_k<<<(NN*C0S + 255)/256, 256>>>(SAh, SAl, NN*C0S);
    zero_bb_k<<<(NN*C1 + 255)/256, 256>>>(SBh, SBl, NN*C1);

    // PDL launch helpers
    cudaLaunchAttribute pdl_attr;
    pdl_attr.id = cudaLaunchAttributeProgrammaticStreamSerialization;
    pdl_attr.val.programmaticStreamSerializationAllowed = 1;

    auto hop = [&](dim3 grid, const bf16* Xh, const bf16* Xl,
                   bf16* Yh, bf16* Yl, int C) {
        cudaLaunchConfig_t cfg = {};
        cfg.gridDim = grid; cfg.blockDim = dim3(256);
        cfg.attrs = &pdl_attr; cfg.numAttrs = 1;
        cudaLaunchKernelEx(&cfg, hop4_mma, (const bf16*)Gh, (const bf16*)Gl,
                           Xh, Xl, Yh, Yl, C);
    };
    auto gate = [&](dim3 grid, GateArgs ga) {
        cudaLaunchConfig_t cfg = {};
        cfg.gridDim = grid; cfg.blockDim = dim3(128);
        cfg.attrs = &pdl_attr; cfg.numAttrs = 1;
        cudaLaunchKernelEx(&cfg, gate_mma, ga);
    };

    // stacked block order: 0=Wf, 1=Wb, 2=Wf2, 3=Wb2; gate slice order
    // [X, WfX, Wf2X, WbX, Wb2X] -> {in, 0, 2, 1, 3}
    auto wire_S = [&](GateArgs& ga, bf16* inh, bf16* inl, bf16* sh, bf16* sl, int C) {
        ga.Ah[0]=inh;                    ga.Al[0]=inl;
        ga.Ah[1]=sh;                     ga.Al[1]=sl;
        ga.Ah[2]=sh+(size_t)2*NN*C;      ga.Al[2]=sl+(size_t)2*NN*C;
        ga.Ah[3]=sh+(size_t)NN*C;        ga.Al[3]=sl+(size_t)NN*C;
        ga.Ah[4]=sh+(size_t)3*NN*C;      ga.Al[4]=sl+(size_t)3*NN*C;
    };

    auto cell0 = [&]() {
        hop(dim3(C0S/64, 16), SAh, SAl, S12h, S12l, C0S);
        GateArgs ga = {};
        wire_S(ga, SAh, SAl, S12h, S12l, C0S);
        for (int s=0;s<5;s++){ ga.Bh[s]=ga.Ah[s]; ga.Bl[s]=ga.Al[s]; }
        ga.strideA = F0S; ga.strideB = F0S; ga.split = F0S; ga.Fp = F0P;
        ga.W1h = Wsh+OW0R; ga.W1l = Wsl+OW0R; ga.b1 = br0; ga.Y1 = r;
        ga.W2h = Wsh+OW0Z; ga.W2l = Wsl+OW0Z; ga.b2 = bz0; ga.Y2 = z;
        ga.hmul = h0; ga.t0h = T0h; ga.t0l = T0l;
        ga.mode = 0;
        gate(dim3(NB/64, 1, 2), ga);
        hop(dim3(CH/64, 16), T0h, T0l, T12h, T12l, CH);
        GateArgs gn = {};
        wire_S(gn, T0h, T0l, T12h, T12l, CH);
        gn.Bh[0]=SAh+64; gn.Bl[0]=SAl+64;
        gn.Bh[1]=S12h+64;                  gn.Bl[1]=S12l+64;
        gn.Bh[2]=S12h+(size_t)2*NN*C0S+64; gn.Bl[2]=S12l+(size_t)2*NN*C0S+64;
        gn.Bh[3]=S12h+(size_t)NN*C0S+64;   gn.Bl[3]=S12l+(size_t)NN*C0S+64;
        gn.Bh[4]=S12h+(size_t)3*NN*C0S+64; gn.Bl[4]=S12l+(size_t)3*NN*C0S+64;
        gn.strideA = HID; gn.strideB = F0S; gn.split = HID; gn.Fp = F0P;
        gn.W1h = Wsh+OW0N; gn.W1l = Wsl+OW0N; gn.b1 = bn0;
        gn.zg = z; gn.h = h0;
        gn.e1h = SAh; gn.e1l = SAl; gn.e1s = F0S; gn.e1o = 0;
        gn.e2h = SBh; gn.e2l = SBl; gn.e2s = F1;  gn.e2o = 0;
        gn.mode = 1;
        gate(dim3(NB/64, 1, 1), gn);
    };

    auto cell1 = [&](int fuse, int t) {
        hop(dim3(C1/64, 16), SBh, SBl, S12h, S12l, C1);
        GateArgs ga = {};
        wire_S(ga, SBh, SBl, S12h, S12l, C1);
        for (int s=0;s<5;s++){ ga.Bh[s]=ga.Ah[s]; ga.Bl[s]=ga.Al[s]; }
        ga.strideA = F1; ga.strideB = F1; ga.split = F1; ga.Fp = F1;
        ga.W1h = Wsh+OW1R; ga.W1l = Wsl+OW1R; ga.b1 = br1; ga.Y1 = r;
        ga.W2h = Wsh+OW1Z; ga.W2l = Wsl+OW1Z; ga.b2 = bz1; ga.Y2 = z;
        ga.hmul = h1; ga.t0h = T0h; ga.t0l = T0l;
        ga.mode = 0;
        gate(dim3(NB/64, 1, 2), ga);
        hop(dim3(CH/64, 16), T0h, T0l, T12h, T12l, CH);
        GateArgs gn = {};
        wire_S(gn, SBh, SBl, S12h, S12l, C1);
        gn.Bh[0]=T0h;                     gn.Bl[0]=T0l;
        gn.Bh[1]=T12h;                    gn.Bl[1]=T12l;
        gn.Bh[2]=T12h+(size_t)2*NN*CH;    gn.Bl[2]=T12l+(size_t)2*NN*CH;
        gn.Bh[3]=T12h+(size_t)NN*CH;      gn.Bl[3]=T12l+(size_t)NN*CH;
        gn.Bh[4]=T12h+(size_t)3*NN*CH;    gn.Bl[4]=T12l+(size_t)3*NN*CH;
        gn.strideA = F1; gn.strideB = HID; gn.split = HID; gn.Fp = F1;
        gn.W1h = Wsh+OW1N; gn.W1l = Wsl+OW1N; gn.b1 = bn1;
        gn.zg = z; gn.h = h1;
        gn.e1h = SBh; gn.e1l = SBl; gn.e1s = F1; gn.e1o = HID;
        gn.fuse = fuse; gn.t = t;
        gn.xin = x; gn.Wp = Wp; gn.bp = bp; gn.out = out;
        gn.dAh = SAh; gn.dAl = SAl;
        gn.mode = 1;
        gate(dim3(NB/64, 1, 1), gn);
    };

    copy_xt<<<NB/256, 256>>>(x, 0, SAh, SAl);
    for (int t = 0; t < TIN; t++) {
        cell0();
        cell1(1, (t + 1 < TIN) ? t + 1 : TIN - 1);   // write next x's di
    }
    for (int t = 0; t < TOUT; t++) {
        cell0();
        cell1(2, t);                                  // proj + next di
    }
}